// round 8
// baseline (speedup 1.0000x reference)
#include <cuda_runtime.h>
#include <cuda_bf16.h>
#include <math.h>
#include <stdint.h>

// ===========================================================================
// MotionCompensationBlock — mma.sync (HMMA bf16x3 hi/lo) implicit-GEMM
// Round 8: ldmatrix fragment loads + 4-stage cp.async pipeline in the GEMM
// ===========================================================================

__device__ __forceinline__ uint32_t smem_u32(const void* p) {
    uint32_t a;
    asm("{ .reg .u64 t; cvta.to.shared.u64 t, %1; cvt.u32.u64 %0, t; }" : "=r"(a) : "l"(p));
    return a;
}

#define CP16(dst, src) \
    asm volatile("cp.async.cg.shared.global [%0], [%1], 16;" :: "r"(dst), "l"(src) : "memory")
#define CP_COMMIT() asm volatile("cp.async.commit_group;" ::: "memory")
#define CP_WAIT(n)  asm volatile("cp.async.wait_group %0;" :: "n"(n) : "memory")

#define LDSM4(r, addr) \
    asm volatile("ldmatrix.sync.aligned.m8n8.x4.shared.b16 {%0,%1,%2,%3}, [%4];" \
                 : "=r"((r)[0]), "=r"((r)[1]), "=r"((r)[2]), "=r"((r)[3]) : "r"(addr))

__device__ __forceinline__ void mma16816(float* c, const uint32_t* a,
                                         uint32_t b0, uint32_t b1) {
    asm volatile(
        "mma.sync.aligned.m16n8k16.row.col.f32.bf16.bf16.f32 "
        "{%0,%1,%2,%3}, {%4,%5,%6,%7}, {%8,%9}, {%0,%1,%2,%3};"
        : "+f"(c[0]), "+f"(c[1]), "+f"(c[2]), "+f"(c[3])
        : "r"(a[0]), "r"(a[1]), "r"(a[2]), "r"(a[3]), "r"(b0), "r"(b1));
}

__device__ __forceinline__ uint32_t hilo_pack_hi(float v0, float v1,
                                                 uint32_t& lo) {
    __nv_bfloat16 h0 = __float2bfloat16(v0), h1 = __float2bfloat16(v1);
    __nv_bfloat16 l0 = __float2bfloat16(v0 - __bfloat162float(h0));
    __nv_bfloat16 l1 = __float2bfloat16(v1 - __bfloat162float(h1));
    __nv_bfloat162 hp = __nv_bfloat162(h0, h1), lp = __nv_bfloat162(l0, l1);
    lo = *(uint32_t*)&lp;
    return *(uint32_t*)&hp;
}

// ------------------------------ scratch -----------------------------------
__device__ __nv_bfloat16 g_Bhi[83886080];
__device__ __nv_bfloat16 g_Blo[83886080];
__device__ __nv_bfloat16 g_Ahi[1245184];
__device__ __nv_bfloat16 g_Alo[1245184];
__device__ float g_offeat[4u * 64 * 128 * 128];
__device__ float g_om[4u * 216 * 128 * 128];
__device__ float g_fuse[4u * 128 * 128 * 128];
__device__ float g_up[4u * 128 * 128 * 128];

// ---------------------------------------------------------------------------
// im2col v2: coalesced both sides via smem transpose (unchanged, R7 winner)
// ---------------------------------------------------------------------------
__global__ void __launch_bounds__(256)
im2col_v2(const float* __restrict__ s1, int c1, long bs1,
          const float* __restrict__ s2, int c2, long bs2,
          int H, int W, int Cp, int Kh,
          uint32_t* __restrict__ Bh, uint32_t* __restrict__ Bl)
{
    __shared__ uint32_t sh[32][65];
    __shared__ uint32_t sl[32][65];
    __shared__ int st_t[32], st_c[32];
    __shared__ int sp_b[64], sp_y[64], sp_x[64];

    const int tid = threadIdx.x;
    const int kk0 = blockIdx.x * 32;
    const long n0 = (long)blockIdx.y * 64;
    const int HW = H * W;

    if (tid < 32) {
        int k0 = (kk0 + tid) * 2;
        int t = k0 / Cp;
        st_t[tid] = t;
        st_c[tid] = k0 - t * Cp;
    } else if (tid < 96) {
        int i = tid - 32;
        long n = n0 + i;
        int b = (int)(n / HW);
        int p = (int)(n - (long)b * HW);
        sp_b[i] = b;
        sp_y[i] = p / W;
        sp_x[i] = p % W;
    }
    __syncthreads();

    const int Cin = c1 + c2;
#pragma unroll
    for (int e = tid; e < 2048; e += 256) {
        const int p = e & 63, kk = e >> 6;
        const int t = st_t[kk], c = st_c[kk];
        float v0 = 0.f, v1 = 0.f;
        if (t < 9) {
            const int yy = sp_y[p] + t / 3 - 1;
            const int xx = sp_x[p] + t % 3 - 1;
            if (yy >= 0 && yy < H && xx >= 0 && xx < W) {
                const long sp = (long)yy * W + xx;
                const int b = sp_b[p];
                if (c < c1)          v0 = s1[(long)b * bs1 + (long)c * HW + sp];
                else if (c < Cin)    v0 = s2[(long)b * bs2 + (long)(c - c1) * HW + sp];
                const int cc = c + 1;
                if (cc < c1)         v1 = s1[(long)b * bs1 + (long)cc * HW + sp];
                else if (cc < Cin)   v1 = s2[(long)b * bs2 + (long)(cc - c1) * HW + sp];
            }
        }
        uint32_t lo;
        uint32_t hi = hilo_pack_hi(v0, v1, lo);
        sh[kk][p] = hi;
        sl[kk][p] = lo;
    }
    __syncthreads();

#pragma unroll
    for (int e = tid; e < 2048; e += 256) {
        const int kk = e & 31, p = e >> 5;
        const long o = (n0 + p) * Kh + kk0 + kk;
        Bh[o] = sh[kk][p];
        Bl[o] = sl[kk][p];
    }
}

// ---------------------------------------------------------------------------
// Weight convert (unchanged)
// ---------------------------------------------------------------------------
__global__ void wconv(const float* __restrict__ w, int M, int Cin, int Cp, int Kp,
                      uint32_t* __restrict__ Ah, uint32_t* __restrict__ Al, int total)
{
    int idx = blockIdx.x * blockDim.x + threadIdx.x;
    if (idx >= total) return;
    const int Kh = Kp >> 1;
    const int kk = idx % Kh;
    const int m  = idx / Kh;
    const int k0 = kk * 2;
    const int t = k0 / Cp, c = k0 - t * Cp;
    float v0 = 0.f, v1 = 0.f;
    if (m < M && t < 9) {
        if (c < Cin)     v0 = w[((long)m * Cin + c) * 9 + t];
        if (c + 1 < Cin) v1 = w[((long)m * Cin + c + 1) * 9 + t];
    }
    uint32_t lo;
    uint32_t hi = hilo_pack_hi(v0, v1, lo);
    Ah[idx] = hi;
    Al[idx] = lo;
}

// ---------------------------------------------------------------------------
// mma.sync GEMM v2: ldmatrix fragments, 4-stage cp.async pipeline.
// D[128 M-tile, 128 N-tile], K-chunks of 32 bf16.
// ---------------------------------------------------------------------------
#define LROW 40
#define PLANE (128 * LROW)                 // bf16 per plane
#define PLANE_B (PLANE * 2)                // bytes
#define STAGE_B (4 * PLANE_B)              // Ah,Al,Bh,Bl = 40960 B
#define NSTAGE 4
#define GEMM_SMEM (NSTAGE * STAGE_B)       // 160 KB

__global__ void __launch_bounds__(256)
gemm_mma(const __nv_bfloat16* __restrict__ Ahi, const __nv_bfloat16* __restrict__ Alo,
         const __nv_bfloat16* __restrict__ Bhi, const __nv_bfloat16* __restrict__ Blo,
         const float* __restrict__ bias, float* __restrict__ out,
         int Kp, int nchunks, int Cout, int ocStride, int HW)
{
    extern __shared__ __nv_bfloat16 sm[];

    const int tid = threadIdx.x, wid = tid >> 5, lane = tid & 31;
    const int g = lane >> 2, t = lane & 3;
    const int wm = wid >> 2, wn = wid & 3;

    const int p0 = blockIdx.x * 128;
    const int m0 = blockIdx.y * 128;

    float acc[4][4][4];
#pragma unroll
    for (int i = 0; i < 4; i++)
#pragma unroll
        for (int j = 0; j < 4; j++)
#pragma unroll
            for (int k = 0; k < 4; k++) acc[i][j][k] = 0.f;

    const uint32_t smb = smem_u32(sm);

    // cp.async staging geometry (512 x 16B tasks per plane, 2 per thread)
    const int r0 = tid >> 2, s0 = tid & 3;
    const int r1 = (tid + 256) >> 2, s1 = (tid + 256) & 3;

    // ldmatrix per-lane byte offsets within a plane
    uint32_t aoff[4], boff[2];
    {
        const int arow = (lane & 7) + ((lane >> 3) & 1) * 8;
        const int acol = (lane >> 4) * 8;
#pragma unroll
        for (int mt = 0; mt < 4; mt++)
            aoff[mt] = (uint32_t)(((wm * 64 + mt * 16 + arow) * LROW + acol) * 2);
        const int brow = (lane & 7) + (lane >> 4) * 8;
        const int bcol = ((lane >> 3) & 1) * 8;
#pragma unroll
        for (int np = 0; np < 2; np++)
            boff[np] = (uint32_t)(((wn * 32 + np * 16 + brow) * LROW + bcol) * 2);
    }

    auto stage = [&](int ci, int buf) {
        const long kc = (long)ci * 32;
        const uint32_t bufb = smb + (uint32_t)buf * STAGE_B;
        CP16(bufb + r0 * 80 + s0 * 16, Ahi + (long)(m0 + r0) * Kp + kc + s0 * 8);
        CP16(bufb + r1 * 80 + s1 * 16, Ahi + (long)(m0 + r1) * Kp + kc + s1 * 8);
        CP16(bufb + PLANE_B + r0 * 80 + s0 * 16, Alo + (long)(m0 + r0) * Kp + kc + s0 * 8);
        CP16(bufb + PLANE_B + r1 * 80 + s1 * 16, Alo + (long)(m0 + r1) * Kp + kc + s1 * 8);
        CP16(bufb + 2 * PLANE_B + r0 * 80 + s0 * 16, Bhi + (long)(p0 + r0) * Kp + kc + s0 * 8);
        CP16(bufb + 2 * PLANE_B + r1 * 80 + s1 * 16, Bhi + (long)(p0 + r1) * Kp + kc + s1 * 8);
        CP16(bufb + 3 * PLANE_B + r0 * 80 + s0 * 16, Blo + (long)(p0 + r0) * Kp + kc + s0 * 8);
        CP16(bufb + 3 * PLANE_B + r1 * 80 + s1 * 16, Blo + (long)(p0 + r1) * Kp + kc + s1 * 8);
    };

    // prologue: always commit exactly 3 groups
#pragma unroll
    for (int s = 0; s < 3; s++) {
        if (s < nchunks) stage(s, s);
        CP_COMMIT();
    }

    for (int ci = 0; ci < nchunks; ci++) {
        CP_WAIT(2);
        __syncthreads();
        if (ci + 3 < nchunks) stage(ci + 3, (ci + 3) & (NSTAGE - 1));
        CP_COMMIT();

        const uint32_t stg = smb + (uint32_t)(ci & (NSTAGE - 1)) * STAGE_B;

#pragma unroll
        for (int s = 0; s < 2; s++) {
            const uint32_t cofs = (uint32_t)(s * 32);   // 16 bf16 cols = 32 B
            uint32_t afh[4][4], afl[4][4], bfh[2][4], bfl[2][4];
#pragma unroll
            for (int mt = 0; mt < 4; mt++) {
                LDSM4(afh[mt], stg + aoff[mt] + cofs);
                LDSM4(afl[mt], stg + PLANE_B + aoff[mt] + cofs);
            }
#pragma unroll
            for (int np = 0; np < 2; np++) {
                LDSM4(bfh[np], stg + 2 * PLANE_B + boff[np] + cofs);
                LDSM4(bfl[np], stg + 3 * PLANE_B + boff[np] + cofs);
            }
#pragma unroll
            for (int mt = 0; mt < 4; mt++)
#pragma unroll
                for (int nt = 0; nt < 4; nt++) {
                    const uint32_t* bh = &bfh[nt >> 1][(nt & 1) * 2];
                    const uint32_t* bl = &bfl[nt >> 1][(nt & 1) * 2];
                    mma16816(acc[mt][nt], afh[mt], bh[0], bh[1]);
                    mma16816(acc[mt][nt], afh[mt], bl[0], bl[1]);
                    mma16816(acc[mt][nt], afl[mt], bh[0], bh[1]);
                }
        }
    }

    // ---- epilogue ----
    const int bIdx = p0 / HW, prow0 = p0 % HW;
#pragma unroll
    for (int mt = 0; mt < 4; mt++) {
        const int oca = m0 + wm * 64 + mt * 16 + g;
        const int ocb = oca + 8;
        const float ba = (oca < Cout) ? bias[oca] : 0.f;
        const float bb = (ocb < Cout) ? bias[ocb] : 0.f;
#pragma unroll
        for (int nt = 0; nt < 4; nt++) {
            const int pc = prow0 + wn * 32 + nt * 8 + 2 * t;
            if (oca < Cout) {
                float2 v = make_float2(acc[mt][nt][0] + ba, acc[mt][nt][1] + ba);
                *(float2*)&out[((long)bIdx * ocStride + oca) * HW + pc] = v;
            }
            if (ocb < Cout) {
                float2 v = make_float2(acc[mt][nt][2] + bb, acc[mt][nt][3] + bb);
                *(float2*)&out[((long)bIdx * ocStride + ocb) * HW + pc] = v;
            }
        }
    }
}

// ---------------------------------------------------------------------------
// DCN bilinear sampler (unchanged, R7 winner)
// ---------------------------------------------------------------------------
__global__ void dcn_sample_bf(const float* __restrict__ x, long xbs,
                              const float* __restrict__ om,
                              uint4* __restrict__ Bh4, uint4* __restrict__ Bl4,
                              int C, int H, int W, int total)
{
    int idx = blockIdx.x * blockDim.x + threadIdx.x;
    if (idx >= total) return;
    const int HW = H * W;
    const int p = idx % HW;
    const int k = (idx / HW) % 9;
    const int g = (idx / (HW * 9)) % 8;
    const int b = idx / (HW * 72);
    const int y = p / W, xq = p % W;

    const long omb = (long)b * 216 * HW + (long)(g * 9 + k) * HW + p;
    float dy = om[omb];
    float dx = om[omb + 72L * HW];
    float mk = om[omb + 144L * HW];
    mk = 1.f / (1.f + expf(-mk));

    float pyf = (float)y + (float)(k / 3 - 1) + dy;
    float pxf = (float)xq + (float)(k % 3 - 1) + dx;
    float y0f = floorf(pyf), x0f = floorf(pxf);
    int y0 = (int)y0f, x0i = (int)x0f;
    float ty = pyf - y0f, tx = pxf - x0f;
    int y1 = y0 + 1, x1i = x0i + 1;

    bool vy0 = (y0 >= 0) && (y0 < H), vy1 = (y1 >= 0) && (y1 < H);
    bool vx0 = (x0i >= 0) && (x0i < W), vx1 = (x1i >= 0) && (x1i < W);
    float w00 = (vy0 && vx0) ? (1.f - ty) * (1.f - tx) : 0.f;
    float w01 = (vy0 && vx1) ? (1.f - ty) * tx : 0.f;
    float w10 = (vy1 && vx0) ? ty * (1.f - tx) : 0.f;
    float w11 = (vy1 && vx1) ? ty * tx : 0.f;
    w00 *= mk; w01 *= mk; w10 *= mk; w11 *= mk;

    int cy0 = min(max(y0, 0), H - 1), cy1 = min(max(y1, 0), H - 1);
    int cx0 = min(max(x0i, 0), W - 1), cx1 = min(max(x1i, 0), W - 1);
    int i00 = cy0 * W + cx0, i01 = cy0 * W + cx1;
    int i10 = cy1 * W + cx0, i11 = cy1 * W + cx1;

    const int Cg = C >> 3;
    const int K = C * 9;
    const float* xb = x + (long)b * xbs + (long)g * Cg * HW;
    const long rowbase = ((long)b * HW + p) * K + (long)k * C + (long)g * Cg;
    const long o4 = rowbase >> 3;

    for (int cb = 0; cb < Cg; cb += 8) {
        uint32_t hv[4], lv[4];
#pragma unroll
        for (int j = 0; j < 4; j++) {
            const float* xc0 = xb + (long)(cb + 2 * j) * HW;
            const float* xc1 = xc0 + HW;
            float v0 = w00 * xc0[i00] + w01 * xc0[i01] + w10 * xc0[i10] + w11 * xc0[i11];
            float v1 = w00 * xc1[i00] + w01 * xc1[i01] + w10 * xc1[i10] + w11 * xc1[i11];
            hv[j] = hilo_pack_hi(v0, v1, lv[j]);
        }
        const long o = o4 + (cb >> 3);
        Bh4[o] = make_uint4(hv[0], hv[1], hv[2], hv[3]);
        Bl4[o] = make_uint4(lv[0], lv[1], lv[2], lv[3]);
    }
}

// ---------------------------------------------------------------------------
// Bilinear 2x upsample (unchanged)
// ---------------------------------------------------------------------------
__global__ void up2_kernel(const float* __restrict__ in, float* __restrict__ out,
                           int H, int W, int total)
{
    int idx = blockIdx.x * blockDim.x + threadIdx.x;
    if (idx >= total) return;
    const int W2 = 2 * W, H2 = 2 * H;
    const int ox = idx % W2;
    const int oy = (idx / W2) % H2;
    const int bc = idx / (W2 * H2);

    float sy = fmaxf(oy * 0.5f - 0.25f, 0.f);
    float sx = fmaxf(ox * 0.5f - 0.25f, 0.f);
    int y0 = (int)floorf(sy); float ty = sy - (float)y0; int y1 = min(y0 + 1, H - 1);
    int x0 = (int)floorf(sx); float tx = sx - (float)x0; int x1 = min(x0 + 1, W - 1);

    const float* p = in + (long)bc * H * W;
    float a = p[y0 * W + x0] * (1.f - ty) + p[y1 * W + x0] * ty;
    float c = p[y0 * W + x1] * (1.f - ty) + p[y1 * W + x1] * ty;
    out[idx] = a * (1.f - tx) + c * tx;
}

// ---------------------------------------------------------------------------
extern "C" void kernel_launch(void* const* d_in, const int* in_sizes, int n_in,
                              void* d_out, int out_size)
{
    const float *x0 = nullptr, *x1 = nullptr, *x2 = nullptr;
    const float *flow0 = nullptr, *flow1 = nullptr, *flow2 = nullptr;
    for (int i = 0; i < 6; i++) {
        const float* p = (const float*)d_in[i];
        switch (in_sizes[i]) {
            case 4 * 2 * 64 * 128 * 128: x0 = p; break;
            case 4 * 2 * 128 * 64 * 64:  x1 = p; break;
            case 4 * 2 * 256 * 32 * 32:  x2 = p; break;
            case 4 * 2 * 128 * 128:      flow0 = p; break;
            case 4 * 2 * 64 * 64:        flow1 = p; break;
            case 4 * 2 * 32 * 32:        flow2 = p; break;
        }
    }
    const float* off_w0 = (const float*)d_in[6];  const float* off_b0 = (const float*)d_in[7];
    const float* co_w0  = (const float*)d_in[8];  const float* co_b0  = (const float*)d_in[9];
    const float* dcn_w0 = (const float*)d_in[10]; const float* dcn_b0 = (const float*)d_in[11];
    const float* off_w1 = (const float*)d_in[12]; const float* off_b1 = (const float*)d_in[13];
    const float* co_w1  = (const float*)d_in[14]; const float* co_b1  = (const float*)d_in[15];
    const float* dcn_w1 = (const float*)d_in[16]; const float* dcn_b1 = (const float*)d_in[17];
    const float* off_w2 = (const float*)d_in[18]; const float* off_b2 = (const float*)d_in[19];
    const float* co_w2  = (const float*)d_in[20]; const float* co_b2  = (const float*)d_in[21];
    const float* dcn_w2 = (const float*)d_in[22]; const float* dcn_b2 = (const float*)d_in[23];
    const float* ch_w0  = (const float*)d_in[24]; const float* ch_b0  = (const float*)d_in[25];
    const float* ft_w0  = (const float*)d_in[26]; const float* ft_b0  = (const float*)d_in[27];
    const float* ch_w1  = (const float*)d_in[28]; const float* ch_b1  = (const float*)d_in[29];
    const float* ft_w1  = (const float*)d_in[30]; const float* ft_b1  = (const float*)d_in[31];

    __nv_bfloat16 *Bhi, *Blo, *Ahi, *Alo;
    float *offeat, *om, *fuse, *up;
    cudaGetSymbolAddress((void**)&Bhi, g_Bhi);
    cudaGetSymbolAddress((void**)&Blo, g_Blo);
    cudaGetSymbolAddress((void**)&Ahi, g_Ahi);
    cudaGetSymbolAddress((void**)&Alo, g_Alo);
    cudaGetSymbolAddress((void**)&offeat, g_offeat);
    cudaGetSymbolAddress((void**)&om, g_om);
    cudaGetSymbolAddress((void**)&fuse, g_fuse);
    cudaGetSymbolAddress((void**)&up, g_up);

    cudaFuncSetAttribute(gemm_mma, cudaFuncAttributeMaxDynamicSharedMemorySize, GEMM_SMEM);

    float* out0 = (float*)d_out;
    float* out1 = out0 + 4L * 64 * 128 * 128;
    float* out2 = out1 + 4L * 128 * 64 * 64;

    const int B = 4;

    auto IM2COL = [&](const float* s1, int c1, long bs1, const float* s2, int c2, long bs2,
                      int H, int W, int Cp, int Kp) {
        const int Kh = Kp >> 1;
        dim3 grid(Kh / 32, (B * H * W) / 64);
        im2col_v2<<<grid, 256>>>(s1, c1, bs1, s2, c2, bs2, H, W, Cp, Kh,
                                 (uint32_t*)Bhi, (uint32_t*)Blo);
    };
    auto WCONV = [&](const float* w, int M, int Cin, int Cp, int Kp, int Mp) {
        int total = Mp * (Kp >> 1);
        wconv<<<(total + 255) / 256, 256>>>(w, M, Cin, Cp, Kp,
                                            (uint32_t*)Ahi, (uint32_t*)Alo, total);
    };
    auto GEMM = [&](const float* bias, float* out, int Kp, int Cout, int ocStride,
                    int HW, int Mtiles) {
        dim3 grid((B * HW) / 128, Mtiles);
        gemm_mma<<<grid, 256, GEMM_SMEM>>>(Ahi, Alo, Bhi, Blo, bias, out,
                                           Kp, Kp / 32, Cout, ocStride, HW);
    };

    // ================= level 2: C=256, 32x32 =================
    {
        const int H = 32, W = 32, HW = H * W;
        IM2COL(x2, 512, 512L * HW, flow2, 2, 2L * HW, H, W, 520, 4736);
        WCONV(off_w2, 256, 514, 520, 4736, 256);
        GEMM(off_b2, offeat, 4736, 256, 256, HW, 2);

        IM2COL(offeat, 256, 256L * HW, nullptr, 0, 0, H, W, 256, 2304);
        WCONV(co_w2, 216, 256, 256, 2304, 256);
        GEMM(co_b2, om, 2304, 216, 216, HW, 2);

        int st = B * 72 * HW;
        dcn_sample_bf<<<(st + 255) / 256, 256>>>(x2 + 256L * HW, 512L * HW, om,
                                                 (uint4*)Bhi, (uint4*)Blo,
                                                 256, H, W, st);
        WCONV(dcn_w2, 256, 256, 256, 2304, 256);
        GEMM(dcn_b2, out2, 2304, 256, 256, HW, 2);

        int ut = B * 256 * 4 * HW;
        up2_kernel<<<(ut + 255) / 256, 256>>>(out2, up, H, W, ut);
    }

    // ================= level 1: C=128, 64x64 =================
    {
        const int H = 64, W = 64, HW = H * W;
        IM2COL(x1, 256, 256L * HW, flow1, 2, 2L * HW, H, W, 264, 2432);
        WCONV(off_w1, 128, 258, 264, 2432, 128);
        GEMM(off_b1, offeat, 2432, 128, 128, HW, 1);

        IM2COL(offeat, 128, 128L * HW, nullptr, 0, 0, H, W, 128, 1152);
        WCONV(co_w1, 216, 128, 128, 1152, 256);
        GEMM(co_b1, om, 1152, 216, 216, HW, 2);

        int st = B * 72 * HW;
        dcn_sample_bf<<<(st + 255) / 256, 256>>>(x1 + 128L * HW, 256L * HW, om,
                                                 (uint4*)Bhi, (uint4*)Blo,
                                                 128, H, W, st);
        WCONV(dcn_w1, 128, 128, 128, 1152, 128);
        GEMM(dcn_b1, fuse, 1152, 128, 256, HW, 1);

        IM2COL(up, 256, 256L * HW, nullptr, 0, 0, H, W, 256, 2304);
        WCONV(ch_w1, 128, 256, 256, 2304, 128);
        GEMM(ch_b1, fuse + 128L * HW, 2304, 128, 256, HW, 1);

        IM2COL(fuse, 256, 256L * HW, nullptr, 0, 0, H, W, 256, 2304);
        WCONV(ft_w1, 128, 256, 256, 2304, 128);
        GEMM(ft_b1, out1, 2304, 128, 128, HW, 1);

        int ut = B * 128 * 4 * HW;
        up2_kernel<<<(ut + 255) / 256, 256>>>(out1, up, H, W, ut);
    }

    // ================= level 0: C=64, 128x128 =================
    {
        const int H = 128, W = 128, HW = H * W;
        IM2COL(x0, 128, 128L * HW, flow0, 2, 2L * HW, H, W, 136, 1280);
        WCONV(off_w0, 64, 130, 136, 1280, 128);
        GEMM(off_b0, offeat, 1280, 64, 64, HW, 1);

        IM2COL(offeat, 64, 64L * HW, nullptr, 0, 0, H, W, 64, 576);
        WCONV(co_w0, 216, 64, 64, 576, 256);
        GEMM(co_b0, om, 576, 216, 216, HW, 2);

        int st = B * 72 * HW;
        dcn_sample_bf<<<(st + 255) / 256, 256>>>(x0 + 64L * HW, 128L * HW, om,
                                                 (uint4*)Bhi, (uint4*)Blo,
                                                 64, H, W, st);
        WCONV(dcn_w0, 64, 64, 64, 576, 128);
        GEMM(dcn_b0, fuse, 576, 64, 128, HW, 1);

        IM2COL(up, 128, 128L * HW, nullptr, 0, 0, H, W, 128, 1152);
        WCONV(ch_w0, 64, 128, 128, 1152, 128);
        GEMM(ch_b0, fuse + 64L * HW, 1152, 64, 128, HW, 1);

        IM2COL(fuse, 128, 128L * HW, nullptr, 0, 0, H, W, 128, 1152);
        WCONV(ft_w0, 64, 128, 128, 1152, 128);
        GEMM(ft_b0, out0, 1152, 64, 64, HW, 1);
    }
}

// round 9
// speedup vs baseline: 1.1497x; 1.1497x over previous
#include <cuda_runtime.h>
#include <cuda_bf16.h>
#include <math.h>
#include <stdint.h>

// ===========================================================================
// MotionCompensationBlock — HMMA bf16x3 implicit-GEMM, multi-stream overlap
// Round 9: 3-way stream fork (per-level chains) + GEMM 2 blocks/SM
// ===========================================================================

__device__ __forceinline__ uint32_t smem_u32(const void* p) {
    uint32_t a;
    asm("{ .reg .u64 t; cvta.to.shared.u64 t, %1; cvt.u32.u64 %0, t; }" : "=r"(a) : "l"(p));
    return a;
}

#define CP16(dst, src) \
    asm volatile("cp.async.cg.shared.global [%0], [%1], 16;" :: "r"(dst), "l"(src) : "memory")
#define CP_COMMIT() asm volatile("cp.async.commit_group;" ::: "memory")
#define CP_WAIT(n)  asm volatile("cp.async.wait_group %0;" :: "n"(n) : "memory")

#define LDSM4(r, addr) \
    asm volatile("ldmatrix.sync.aligned.m8n8.x4.shared.b16 {%0,%1,%2,%3}, [%4];" \
                 : "=r"((r)[0]), "=r"((r)[1]), "=r"((r)[2]), "=r"((r)[3]) : "r"(addr))

__device__ __forceinline__ void mma16816(float* c, const uint32_t* a,
                                         uint32_t b0, uint32_t b1) {
    asm volatile(
        "mma.sync.aligned.m16n8k16.row.col.f32.bf16.bf16.f32 "
        "{%0,%1,%2,%3}, {%4,%5,%6,%7}, {%8,%9}, {%0,%1,%2,%3};"
        : "+f"(c[0]), "+f"(c[1]), "+f"(c[2]), "+f"(c[3])
        : "r"(a[0]), "r"(a[1]), "r"(a[2]), "r"(a[3]), "r"(b0), "r"(b1));
}

__device__ __forceinline__ uint32_t hilo_pack_hi(float v0, float v1,
                                                 uint32_t& lo) {
    __nv_bfloat16 h0 = __float2bfloat16(v0), h1 = __float2bfloat16(v1);
    __nv_bfloat16 l0 = __float2bfloat16(v0 - __bfloat162float(h0));
    __nv_bfloat16 l1 = __float2bfloat16(v1 - __bfloat162float(h1));
    __nv_bfloat162 hp = __nv_bfloat162(h0, h1), lp = __nv_bfloat162(l0, l1);
    lo = *(uint32_t*)&lp;
    return *(uint32_t*)&hp;
}

// ------------------------------ scratch (per-chain) -----------------------
__device__ __nv_bfloat16 g_B2h[19398656], g_B2l[19398656];   // L2 chain
__device__ __nv_bfloat16 g_B1h[39845888], g_B1l[39845888];   // L1 chain
__device__ __nv_bfloat16 g_B0h[83886080], g_B0l[83886080];   // L0 chain
__device__ __nv_bfloat16 g_Bfh[75497472], g_Bfl[75497472];   // fusion convs
#define ASLOT 1245184
__device__ __nv_bfloat16 g_Ah[13 * ASLOT], g_Al[13 * ASLOT];
__device__ float g_offeat0[4194304], g_offeat1[2097152], g_offeat2[1048576];
__device__ float g_om0[14155776], g_om1[3538944], g_om2[884736];
__device__ float g_fuse0[8388608], g_fuse1[4194304];
__device__ float g_upA[4194304], g_upB[8388608];

// ------------------------------ streams (created pre-main) ----------------
struct MCStreams {
    cudaStream_t s1, s2;
    cudaEvent_t eF, eL0, eL1;
    MCStreams() {
        cudaStreamCreateWithFlags(&s1, cudaStreamNonBlocking);
        cudaStreamCreateWithFlags(&s2, cudaStreamNonBlocking);
        cudaEventCreateWithFlags(&eF,  cudaEventDisableTiming);
        cudaEventCreateWithFlags(&eL0, cudaEventDisableTiming);
        cudaEventCreateWithFlags(&eL1, cudaEventDisableTiming);
    }
};
static MCStreams g_s;

// ---------------------------------------------------------------------------
// im2col: coalesced both sides via smem transpose (R7 winner, unchanged)
// ---------------------------------------------------------------------------
__global__ void __launch_bounds__(256)
im2col_v2(const float* __restrict__ s1, int c1, long bs1,
          const float* __restrict__ s2, int c2, long bs2,
          int H, int W, int Cp, int Kh,
          uint32_t* __restrict__ Bh, uint32_t* __restrict__ Bl)
{
    __shared__ uint32_t sh[32][65];
    __shared__ uint32_t sl[32][65];
    __shared__ int st_t[32], st_c[32];
    __shared__ int sp_b[64], sp_y[64], sp_x[64];

    const int tid = threadIdx.x;
    const int kk0 = blockIdx.x * 32;
    const long n0 = (long)blockIdx.y * 64;
    const int HW = H * W;

    if (tid < 32) {
        int k0 = (kk0 + tid) * 2;
        int t = k0 / Cp;
        st_t[tid] = t;
        st_c[tid] = k0 - t * Cp;
    } else if (tid < 96) {
        int i = tid - 32;
        long n = n0 + i;
        int b = (int)(n / HW);
        int p = (int)(n - (long)b * HW);
        sp_b[i] = b;
        sp_y[i] = p / W;
        sp_x[i] = p % W;
    }
    __syncthreads();

    const int Cin = c1 + c2;
#pragma unroll
    for (int e = tid; e < 2048; e += 256) {
        const int p = e & 63, kk = e >> 6;
        const int t = st_t[kk], c = st_c[kk];
        float v0 = 0.f, v1 = 0.f;
        if (t < 9) {
            const int yy = sp_y[p] + t / 3 - 1;
            const int xx = sp_x[p] + t % 3 - 1;
            if (yy >= 0 && yy < H && xx >= 0 && xx < W) {
                const long sp = (long)yy * W + xx;
                const int b = sp_b[p];
                if (c < c1)          v0 = s1[(long)b * bs1 + (long)c * HW + sp];
                else if (c < Cin)    v0 = s2[(long)b * bs2 + (long)(c - c1) * HW + sp];
                const int cc = c + 1;
                if (cc < c1)         v1 = s1[(long)b * bs1 + (long)cc * HW + sp];
                else if (cc < Cin)   v1 = s2[(long)b * bs2 + (long)(cc - c1) * HW + sp];
            }
        }
        uint32_t lo;
        uint32_t hi = hilo_pack_hi(v0, v1, lo);
        sh[kk][p] = hi;
        sl[kk][p] = lo;
    }
    __syncthreads();

#pragma unroll
    for (int e = tid; e < 2048; e += 256) {
        const int kk = e & 31, p = e >> 5;
        const long o = (n0 + p) * Kh + kk0 + kk;
        Bh[o] = sh[kk][p];
        Bl[o] = sl[kk][p];
    }
}

// ---------------------------------------------------------------------------
// Weight convert (unchanged)
// ---------------------------------------------------------------------------
__global__ void wconv(const float* __restrict__ w, int M, int Cin, int Cp, int Kp,
                      uint32_t* __restrict__ Ah, uint32_t* __restrict__ Al, int total)
{
    int idx = blockIdx.x * blockDim.x + threadIdx.x;
    if (idx >= total) return;
    const int Kh = Kp >> 1;
    const int kk = idx % Kh;
    const int m  = idx / Kh;
    const int k0 = kk * 2;
    const int t = k0 / Cp, c = k0 - t * Cp;
    float v0 = 0.f, v1 = 0.f;
    if (m < M && t < 9) {
        if (c < Cin)     v0 = w[((long)m * Cin + c) * 9 + t];
        if (c + 1 < Cin) v1 = w[((long)m * Cin + c + 1) * 9 + t];
    }
    uint32_t lo;
    uint32_t hi = hilo_pack_hi(v0, v1, lo);
    Ah[idx] = hi;
    Al[idx] = lo;
}

// ---------------------------------------------------------------------------
// mma.sync GEMM: ldmatrix fragments, 2-stage cp.async, 80KB smem, 2 blk/SM
// ---------------------------------------------------------------------------
#define LROW 40
#define PLANE (128 * LROW)
#define PLANE_B (PLANE * 2)
#define STAGE_B (4 * PLANE_B)              // 40960 B
#define NSTAGE 2
#define GEMM_SMEM (NSTAGE * STAGE_B)       // 80 KB

__global__ void __launch_bounds__(256, 2)
gemm_mma(const __nv_bfloat16* __restrict__ Ahi, const __nv_bfloat16* __restrict__ Alo,
         const __nv_bfloat16* __restrict__ Bhi, const __nv_bfloat16* __restrict__ Blo,
         const float* __restrict__ bias, float* __restrict__ out,
         int Kp, int nchunks, int Cout, int ocStride, int HW)
{
    extern __shared__ __nv_bfloat16 sm[];

    const int tid = threadIdx.x, wid = tid >> 5, lane = tid & 31;
    const int g = lane >> 2, t = lane & 3;
    const int wm = wid >> 2, wn = wid & 3;

    const int p0 = blockIdx.x * 128;
    const int m0 = blockIdx.y * 128;

    float acc[4][4][4];
#pragma unroll
    for (int i = 0; i < 4; i++)
#pragma unroll
        for (int j = 0; j < 4; j++)
#pragma unroll
            for (int k = 0; k < 4; k++) acc[i][j][k] = 0.f;

    const uint32_t smb = smem_u32(sm);

    const int r0 = tid >> 2, s0 = tid & 3;
    const int r1 = (tid + 256) >> 2, s1 = (tid + 256) & 3;

    uint32_t aoff[4], boff[2];
    {
        const int arow = (lane & 7) + ((lane >> 3) & 1) * 8;
        const int acol = (lane >> 4) * 8;
#pragma unroll
        for (int mt = 0; mt < 4; mt++)
            aoff[mt] = (uint32_t)(((wm * 64 + mt * 16 + arow) * LROW + acol) * 2);
        const int brow = (lane & 7) + (lane >> 4) * 8;
        const int bcol = ((lane >> 3) & 1) * 8;
#pragma unroll
        for (int np = 0; np < 2; np++)
            boff[np] = (uint32_t)(((wn * 32 + np * 16 + brow) * LROW + bcol) * 2);
    }

    auto stage = [&](int ci, int buf) {
        const long kc = (long)ci * 32;
        const uint32_t bufb = smb + (uint32_t)buf * STAGE_B;
        CP16(bufb + r0 * 80 + s0 * 16, Ahi + (long)(m0 + r0) * Kp + kc + s0 * 8);
        CP16(bufb + r1 * 80 + s1 * 16, Ahi + (long)(m0 + r1) * Kp + kc + s1 * 8);
        CP16(bufb + PLANE_B + r0 * 80 + s0 * 16, Alo + (long)(m0 + r0) * Kp + kc + s0 * 8);
        CP16(bufb + PLANE_B + r1 * 80 + s1 * 16, Alo + (long)(m0 + r1) * Kp + kc + s1 * 8);
        CP16(bufb + 2 * PLANE_B + r0 * 80 + s0 * 16, Bhi + (long)(p0 + r0) * Kp + kc + s0 * 8);
        CP16(bufb + 2 * PLANE_B + r1 * 80 + s1 * 16, Bhi + (long)(p0 + r1) * Kp + kc + s1 * 8);
        CP16(bufb + 3 * PLANE_B + r0 * 80 + s0 * 16, Blo + (long)(p0 + r0) * Kp + kc + s0 * 8);
        CP16(bufb + 3 * PLANE_B + r1 * 80 + s1 * 16, Blo + (long)(p0 + r1) * Kp + kc + s1 * 8);
    };

    stage(0, 0);
    CP_COMMIT();

    for (int ci = 0; ci < nchunks; ci++) {
        if (ci + 1 < nchunks) stage(ci + 1, (ci + 1) & 1);
        CP_COMMIT();
        CP_WAIT(1);
        __syncthreads();

        const uint32_t stg = smb + (uint32_t)(ci & 1) * STAGE_B;

#pragma unroll
        for (int s = 0; s < 2; s++) {
            const uint32_t cofs = (uint32_t)(s * 32);
            uint32_t afh[4][4], afl[4][4], bfh[2][4], bfl[2][4];
#pragma unroll
            for (int mt = 0; mt < 4; mt++) {
                LDSM4(afh[mt], stg + aoff[mt] + cofs);
                LDSM4(afl[mt], stg + PLANE_B + aoff[mt] + cofs);
            }
#pragma unroll
            for (int np = 0; np < 2; np++) {
                LDSM4(bfh[np], stg + 2 * PLANE_B + boff[np] + cofs);
                LDSM4(bfl[np], stg + 3 * PLANE_B + boff[np] + cofs);
            }
#pragma unroll
            for (int mt = 0; mt < 4; mt++)
#pragma unroll
                for (int nt = 0; nt < 4; nt++) {
                    const uint32_t* bh = &bfh[nt >> 1][(nt & 1) * 2];
                    const uint32_t* bl = &bfl[nt >> 1][(nt & 1) * 2];
                    mma16816(acc[mt][nt], afh[mt], bh[0], bh[1]);
                    mma16816(acc[mt][nt], afh[mt], bl[0], bl[1]);
                    mma16816(acc[mt][nt], afl[mt], bh[0], bh[1]);
                }
        }
        __syncthreads();
    }

    // ---- epilogue ----
    const int bIdx = p0 / HW, prow0 = p0 % HW;
#pragma unroll
    for (int mt = 0; mt < 4; mt++) {
        const int oca = m0 + wm * 64 + mt * 16 + g;
        const int ocb = oca + 8;
        const float ba = (oca < Cout) ? bias[oca] : 0.f;
        const float bb = (ocb < Cout) ? bias[ocb] : 0.f;
#pragma unroll
        for (int nt = 0; nt < 4; nt++) {
            const int pc = prow0 + wn * 32 + nt * 8 + 2 * t;
            if (oca < Cout) {
                float2 v = make_float2(acc[mt][nt][0] + ba, acc[mt][nt][1] + ba);
                *(float2*)&out[((long)bIdx * ocStride + oca) * HW + pc] = v;
            }
            if (ocb < Cout) {
                float2 v = make_float2(acc[mt][nt][2] + bb, acc[mt][nt][3] + bb);
                *(float2*)&out[((long)bIdx * ocStride + ocb) * HW + pc] = v;
            }
        }
    }
}

// ---------------------------------------------------------------------------
// DCN bilinear sampler (unchanged)
// ---------------------------------------------------------------------------
__global__ void dcn_sample_bf(const float* __restrict__ x, long xbs,
                              const float* __restrict__ om,
                              uint4* __restrict__ Bh4, uint4* __restrict__ Bl4,
                              int C, int H, int W, int total)
{
    int idx = blockIdx.x * blockDim.x + threadIdx.x;
    if (idx >= total) return;
    const int HW = H * W;
    const int p = idx % HW;
    const int k = (idx / HW) % 9;
    const int g = (idx / (HW * 9)) % 8;
    const int b = idx / (HW * 72);
    const int y = p / W, xq = p % W;

    const long omb = (long)b * 216 * HW + (long)(g * 9 + k) * HW + p;
    float dy = om[omb];
    float dx = om[omb + 72L * HW];
    float mk = om[omb + 144L * HW];
    mk = 1.f / (1.f + expf(-mk));

    float pyf = (float)y + (float)(k / 3 - 1) + dy;
    float pxf = (float)xq + (float)(k % 3 - 1) + dx;
    float y0f = floorf(pyf), x0f = floorf(pxf);
    int y0 = (int)y0f, x0i = (int)x0f;
    float ty = pyf - y0f, tx = pxf - x0f;
    int y1 = y0 + 1, x1i = x0i + 1;

    bool vy0 = (y0 >= 0) && (y0 < H), vy1 = (y1 >= 0) && (y1 < H);
    bool vx0 = (x0i >= 0) && (x0i < W), vx1 = (x1i >= 0) && (x1i < W);
    float w00 = (vy0 && vx0) ? (1.f - ty) * (1.f - tx) : 0.f;
    float w01 = (vy0 && vx1) ? (1.f - ty) * tx : 0.f;
    float w10 = (vy1 && vx0) ? ty * (1.f - tx) : 0.f;
    float w11 = (vy1 && vx1) ? ty * tx : 0.f;
    w00 *= mk; w01 *= mk; w10 *= mk; w11 *= mk;

    int cy0 = min(max(y0, 0), H - 1), cy1 = min(max(y1, 0), H - 1);
    int cx0 = min(max(x0i, 0), W - 1), cx1 = min(max(x1i, 0), W - 1);
    int i00 = cy0 * W + cx0, i01 = cy0 * W + cx1;
    int i10 = cy1 * W + cx0, i11 = cy1 * W + cx1;

    const int Cg = C >> 3;
    const int K = C * 9;
    const float* xb = x + (long)b * xbs + (long)g * Cg * HW;
    const long rowbase = ((long)b * HW + p) * K + (long)k * C + (long)g * Cg;
    const long o4 = rowbase >> 3;

    for (int cb = 0; cb < Cg; cb += 8) {
        uint32_t hv[4], lv[4];
#pragma unroll
        for (int j = 0; j < 4; j++) {
            const float* xc0 = xb + (long)(cb + 2 * j) * HW;
            const float* xc1 = xc0 + HW;
            float v0 = w00 * xc0[i00] + w01 * xc0[i01] + w10 * xc0[i10] + w11 * xc0[i11];
            float v1 = w00 * xc1[i00] + w01 * xc1[i01] + w10 * xc1[i10] + w11 * xc1[i11];
            hv[j] = hilo_pack_hi(v0, v1, lv[j]);
        }
        const long o = o4 + (cb >> 3);
        Bh4[o] = make_uint4(hv[0], hv[1], hv[2], hv[3]);
        Bl4[o] = make_uint4(lv[0], lv[1], lv[2], lv[3]);
    }
}

// ---------------------------------------------------------------------------
// Bilinear 2x upsample (unchanged)
// ---------------------------------------------------------------------------
__global__ void up2_kernel(const float* __restrict__ in, float* __restrict__ out,
                           int H, int W, int total)
{
    int idx = blockIdx.x * blockDim.x + threadIdx.x;
    if (idx >= total) return;
    const int W2 = 2 * W, H2 = 2 * H;
    const int ox = idx % W2;
    const int oy = (idx / W2) % H2;
    const int bc = idx / (W2 * H2);

    float sy = fmaxf(oy * 0.5f - 0.25f, 0.f);
    float sx = fmaxf(ox * 0.5f - 0.25f, 0.f);
    int y0 = (int)floorf(sy); float ty = sy - (float)y0; int y1 = min(y0 + 1, H - 1);
    int x0 = (int)floorf(sx); float tx = sx - (float)x0; int x1 = min(x0 + 1, W - 1);

    const float* p = in + (long)bc * H * W;
    float a = p[y0 * W + x0] * (1.f - ty) + p[y1 * W + x0] * ty;
    float c = p[y0 * W + x1] * (1.f - ty) + p[y1 * W + x1] * ty;
    out[idx] = a * (1.f - tx) + c * tx;
}

// ---------------------------------------------------------------------------
extern "C" void kernel_launch(void* const* d_in, const int* in_sizes, int n_in,
                              void* d_out, int out_size)
{
    const float *x0 = nullptr, *x1 = nullptr, *x2 = nullptr;
    const float *flow0 = nullptr, *flow1 = nullptr, *flow2 = nullptr;
    for (int i = 0; i < 6; i++) {
        const float* p = (const float*)d_in[i];
        switch (in_sizes[i]) {
            case 4 * 2 * 64 * 128 * 128: x0 = p; break;
            case 4 * 2 * 128 * 64 * 64:  x1 = p; break;
            case 4 * 2 * 256 * 32 * 32:  x2 = p; break;
            case 4 * 2 * 128 * 128:      flow0 = p; break;
            case 4 * 2 * 64 * 64:        flow1 = p; break;
            case 4 * 2 * 32 * 32:        flow2 = p; break;
        }
    }
    const float* off_w0 = (const float*)d_in[6];  const float* off_b0 = (const float*)d_in[7];
    const float* co_w0  = (const float*)d_in[8];  const float* co_b0  = (const float*)d_in[9];
    const float* dcn_w0 = (const float*)d_in[10]; const float* dcn_b0 = (const float*)d_in[11];
    const float* off_w1 = (const float*)d_in[12]; const float* off_b1 = (const float*)d_in[13];
    const float* co_w1  = (const float*)d_in[14]; const float* co_b1  = (const float*)d_in[15];
    const float* dcn_w1 = (const float*)d_in[16]; const float* dcn_b1 = (const float*)d_in[17];
    const float* off_w2 = (const float*)d_in[18]; const float* off_b2 = (const float*)d_in[19];
    const float* co_w2  = (const float*)d_in[20]; const float* co_b2  = (const float*)d_in[21];
    const float* dcn_w2 = (const float*)d_in[22]; const float* dcn_b2 = (const float*)d_in[23];
    const float* ch_w0  = (const float*)d_in[24]; const float* ch_b0  = (const float*)d_in[25];
    const float* ft_w0  = (const float*)d_in[26]; const float* ft_b0  = (const float*)d_in[27];
    const float* ch_w1  = (const float*)d_in[28]; const float* ch_b1  = (const float*)d_in[29];
    const float* ft_w1  = (const float*)d_in[30]; const float* ft_b1  = (const float*)d_in[31];

    __nv_bfloat16 *B2h, *B2l, *B1h, *B1l, *B0h, *B0l, *Bfh, *Bfl, *Ah, *Al;
    float *offeat0, *offeat1, *offeat2, *om0, *om1, *om2, *fuse0, *fuse1, *upA, *upB;
    cudaGetSymbolAddress((void**)&B2h, g_B2h);  cudaGetSymbolAddress((void**)&B2l, g_B2l);
    cudaGetSymbolAddress((void**)&B1h, g_B1h);  cudaGetSymbolAddress((void**)&B1l, g_B1l);
    cudaGetSymbolAddress((void**)&B0h, g_B0h);  cudaGetSymbolAddress((void**)&B0l, g_B0l);
    cudaGetSymbolAddress((void**)&Bfh, g_Bfh);  cudaGetSymbolAddress((void**)&Bfl, g_Bfl);
    cudaGetSymbolAddress((void**)&Ah,  g_Ah);   cudaGetSymbolAddress((void**)&Al,  g_Al);
    cudaGetSymbolAddress((void**)&offeat0, g_offeat0);
    cudaGetSymbolAddress((void**)&offeat1, g_offeat1);
    cudaGetSymbolAddress((void**)&offeat2, g_offeat2);
    cudaGetSymbolAddress((void**)&om0, g_om0);
    cudaGetSymbolAddress((void**)&om1, g_om1);
    cudaGetSymbolAddress((void**)&om2, g_om2);
    cudaGetSymbolAddress((void**)&fuse0, g_fuse0);
    cudaGetSymbolAddress((void**)&fuse1, g_fuse1);
    cudaGetSymbolAddress((void**)&upA, g_upA);
    cudaGetSymbolAddress((void**)&upB, g_upB);

    cudaFuncSetAttribute(gemm_mma, cudaFuncAttributeMaxDynamicSharedMemorySize, GEMM_SMEM);

    float* out0 = (float*)d_out;
    float* out1 = out0 + 4L * 64 * 128 * 128;
    float* out2 = out1 + 4L * 128 * 64 * 64;

    const int B = 4;
    cudaStream_t S0 = 0, S1 = g_s.s1, S2 = g_s.s2;

    auto WCONV = [&](int slot, const float* w, int M, int Cin, int Cp, int Kp, int Mp) {
        int total = Mp * (Kp >> 1);
        wconv<<<(total + 255) / 256, 256, 0, S0>>>(
            w, M, Cin, Cp, Kp,
            (uint32_t*)(Ah + (long)slot * ASLOT), (uint32_t*)(Al + (long)slot * ASLOT), total);
    };
    auto IM2COL = [&](cudaStream_t st, __nv_bfloat16* Bh, __nv_bfloat16* Bl,
                      const float* s1, int c1, long bs1, const float* s2, int c2, long bs2,
                      int H, int W, int Cp, int Kp) {
        const int Kh = Kp >> 1;
        dim3 grid(Kh / 32, (B * H * W) / 64);
        im2col_v2<<<grid, 256, 0, st>>>(s1, c1, bs1, s2, c2, bs2, H, W, Cp, Kh,
                                        (uint32_t*)Bh, (uint32_t*)Bl);
    };
    auto GEMM = [&](cudaStream_t st, int slot, __nv_bfloat16* Bh, __nv_bfloat16* Bl,
                    const float* bias, float* out, int Kp, int Cout, int ocStride,
                    int HW, int Mtiles) {
        dim3 grid((B * HW) / 128, Mtiles);
        gemm_mma<<<grid, 256, GEMM_SMEM, st>>>(
            Ah + (long)slot * ASLOT, Al + (long)slot * ASLOT, Bh, Bl, bias, out,
            Kp, Kp / 32, Cout, ocStride, HW);
    };
    auto DCN = [&](cudaStream_t st, const float* x, long xbs, const float* om,
                   __nv_bfloat16* Bh, __nv_bfloat16* Bl, int C, int H, int W) {
        int st_total = B * 72 * H * W;
        dcn_sample_bf<<<(st_total + 255) / 256, 256, 0, st>>>(
            x, xbs, om, (uint4*)Bh, (uint4*)Bl, C, H, W, st_total);
    };
    auto UP2 = [&](cudaStream_t st, const float* in, float* out, int H, int W, int C) {
        int total = B * C * 4 * H * W;
        up2_kernel<<<(total + 255) / 256, 256, 0, st>>>(in, out, H, W, total);
    };

    // ---- all weight conversions up-front (origin stream) ----
    WCONV(0,  off_w2, 256, 514, 520, 4736, 256);
    WCONV(1,  co_w2,  216, 256, 256, 2304, 256);
    WCONV(2,  dcn_w2, 256, 256, 256, 2304, 256);
    WCONV(3,  off_w1, 128, 258, 264, 2432, 128);
    WCONV(4,  co_w1,  216, 128, 128, 1152, 256);
    WCONV(5,  dcn_w1, 128, 128, 128, 1152, 128);
    WCONV(6,  off_w0, 64,  130, 136, 1280, 128);
    WCONV(7,  co_w0,  216, 64,  64,  576,  256);
    WCONV(8,  dcn_w0, 64,  64,  64,  576,  128);
    WCONV(9,  ch_w1,  128, 256, 256, 2304, 128);
    WCONV(10, ft_w1,  128, 256, 256, 2304, 128);
    WCONV(11, ch_w0,  64,  128, 128, 1152, 128);
    WCONV(12, ft_w0,  64,  128, 128, 1152, 128);

    // ---- fork ----
    cudaEventRecord(g_s.eF, S0);
    cudaStreamWaitEvent(S1, g_s.eF, 0);
    cudaStreamWaitEvent(S2, g_s.eF, 0);

    // ---- s1: level 0 off/co/dcn chain (HW=16384) ----
    {
        const int H = 128, W = 128, HW = H * W;
        IM2COL(S1, B0h, B0l, x0, 128, 128L * HW, flow0, 2, 2L * HW, H, W, 136, 1280);
        GEMM(S1, 6, B0h, B0l, off_b0, offeat0, 1280, 64, 64, HW, 1);
        IM2COL(S1, B0h, B0l, offeat0, 64, 64L * HW, nullptr, 0, 0, H, W, 64, 576);
        GEMM(S1, 7, B0h, B0l, co_b0, om0, 576, 216, 216, HW, 2);
        DCN(S1, x0 + 64L * HW, 128L * HW, om0, B0h, B0l, 64, H, W);
        GEMM(S1, 8, B0h, B0l, dcn_b0, fuse0, 576, 64, 128, HW, 1);  // fuse0 ch [0,64)
        cudaEventRecord(g_s.eL0, S1);
    }

    // ---- s2: level 1 off/co/dcn chain (HW=4096) ----
    {
        const int H = 64, W = 64, HW = H * W;
        IM2COL(S2, B1h, B1l, x1, 256, 256L * HW, flow1, 2, 2L * HW, H, W, 264, 2432);
        GEMM(S2, 3, B1h, B1l, off_b1, offeat1, 2432, 128, 128, HW, 1);
        IM2COL(S2, B1h, B1l, offeat1, 128, 128L * HW, nullptr, 0, 0, H, W, 128, 1152);
        GEMM(S2, 4, B1h, B1l, co_b1, om1, 1152, 216, 216, HW, 2);
        DCN(S2, x1 + 128L * HW, 256L * HW, om1, B1h, B1l, 128, H, W);
        GEMM(S2, 5, B1h, B1l, dcn_b1, fuse1, 1152, 128, 256, HW, 1); // fuse1 ch [0,128)
        cudaEventRecord(g_s.eL1, S2);
    }

    // ---- origin: level 2 chain (HW=1024) + fusion cascade ----
    {
        const int H = 32, W = 32, HW = H * W;
        IM2COL(S0, B2h, B2l, x2, 512, 512L * HW, flow2, 2, 2L * HW, H, W, 520, 4736);
        GEMM(S0, 0, B2h, B2l, off_b2, offeat2, 4736, 256, 256, HW, 2);
        IM2COL(S0, B2h, B2l, offeat2, 256, 256L * HW, nullptr, 0, 0, H, W, 256, 2304);
        GEMM(S0, 1, B2h, B2l, co_b2, om2, 2304, 216, 216, HW, 2);
        DCN(S0, x2 + 256L * HW, 512L * HW, om2, B2h, B2l, 256, H, W);
        GEMM(S0, 2, B2h, B2l, dcn_b2, out2, 2304, 256, 256, HW, 2);
        UP2(S0, out2, upA, H, W, 256);
    }
    {   // level 1 fusion
        const int H = 64, W = 64, HW = H * W;
        IM2COL(S0, Bfh, Bfl, upA, 256, 256L * HW, nullptr, 0, 0, H, W, 256, 2304);
        GEMM(S0, 9, Bfh, Bfl, ch_b1, fuse1 + 128L * HW, 2304, 128, 256, HW, 1); // ch [128,256)
        cudaStreamWaitEvent(S0, g_s.eL1, 0);
        IM2COL(S0, Bfh, Bfl, fuse1, 256, 256L * HW, nullptr, 0, 0, H, W, 256, 2304);
        GEMM(S0, 10, Bfh, Bfl, ft_b1, out1, 2304, 128, 128, HW, 1);
        UP2(S0, out1, upB, H, W, 128);
    }
    {   // level 0 fusion
        const int H = 128, W = 128, HW = H * W;
        IM2COL(S0, Bfh, Bfl, upB, 128, 128L * HW, nullptr, 0, 0, H, W, 128, 1152);
        GEMM(S0, 11, Bfh, Bfl, ch_b0, fuse0 + 64L * HW, 1152, 64, 128, HW, 1);  // ch [64,128)
        cudaStreamWaitEvent(S0, g_s.eL0, 0);
        IM2COL(S0, Bfh, Bfl, fuse0, 128, 128L * HW, nullptr, 0, 0, H, W, 128, 1152);
        GEMM(S0, 12, Bfh, Bfl, ft_b0, out0, 1152, 64, 64, HW, 1);
    }
}

// round 10
// speedup vs baseline: 1.3071x; 1.1370x over previous
#include <cuda_runtime.h>
#include <cuda_bf16.h>
#include <math.h>
#include <stdint.h>

// ===========================================================================
// MotionCompensationBlock — HMMA bf16x3 implicit-GEMM, multi-stream overlap
// Round 10: fused wconv_all + M64xN256 GEMM for Cout=64 (level 0)
// ===========================================================================

__device__ __forceinline__ uint32_t smem_u32(const void* p) {
    uint32_t a;
    asm("{ .reg .u64 t; cvta.to.shared.u64 t, %1; cvt.u32.u64 %0, t; }" : "=r"(a) : "l"(p));
    return a;
}

#define CP16(dst, src) \
    asm volatile("cp.async.cg.shared.global [%0], [%1], 16;" :: "r"(dst), "l"(src) : "memory")
#define CP_COMMIT() asm volatile("cp.async.commit_group;" ::: "memory")
#define CP_WAIT(n)  asm volatile("cp.async.wait_group %0;" :: "n"(n) : "memory")

#define LDSM4(r, addr) \
    asm volatile("ldmatrix.sync.aligned.m8n8.x4.shared.b16 {%0,%1,%2,%3}, [%4];" \
                 : "=r"((r)[0]), "=r"((r)[1]), "=r"((r)[2]), "=r"((r)[3]) : "r"(addr))

__device__ __forceinline__ void mma16816(float* c, const uint32_t* a,
                                         uint32_t b0, uint32_t b1) {
    asm volatile(
        "mma.sync.aligned.m16n8k16.row.col.f32.bf16.bf16.f32 "
        "{%0,%1,%2,%3}, {%4,%5,%6,%7}, {%8,%9}, {%0,%1,%2,%3};"
        : "+f"(c[0]), "+f"(c[1]), "+f"(c[2]), "+f"(c[3])
        : "r"(a[0]), "r"(a[1]), "r"(a[2]), "r"(a[3]), "r"(b0), "r"(b1));
}

__device__ __forceinline__ uint32_t hilo_pack_hi(float v0, float v1,
                                                 uint32_t& lo) {
    __nv_bfloat16 h0 = __float2bfloat16(v0), h1 = __float2bfloat16(v1);
    __nv_bfloat16 l0 = __float2bfloat16(v0 - __bfloat162float(h0));
    __nv_bfloat16 l1 = __float2bfloat16(v1 - __bfloat162float(h1));
    __nv_bfloat162 hp = __nv_bfloat162(h0, h1), lp = __nv_bfloat162(l0, l1);
    lo = *(uint32_t*)&lp;
    return *(uint32_t*)&hp;
}

// ------------------------------ scratch (per-chain) -----------------------
__device__ __nv_bfloat16 g_B2h[19398656], g_B2l[19398656];   // L2 chain
__device__ __nv_bfloat16 g_B1h[39845888], g_B1l[39845888];   // L1 chain
__device__ __nv_bfloat16 g_B0h[83886080], g_B0l[83886080];   // L0 chain
__device__ __nv_bfloat16 g_Bfh[75497472], g_Bfl[75497472];   // fusion convs
#define ASLOT 1245184
__device__ __nv_bfloat16 g_Ah[13 * ASLOT], g_Al[13 * ASLOT];
__device__ float g_offeat0[4194304], g_offeat1[2097152], g_offeat2[1048576];
__device__ float g_om0[14155776], g_om1[3538944], g_om2[884736];
__device__ float g_fuse0[8388608], g_fuse1[4194304];
__device__ float g_upA[4194304], g_upB[8388608];

// ------------------------------ streams (created pre-main) ----------------
struct MCStreams {
    cudaStream_t s1, s2;
    cudaEvent_t eF, eL0, eL1;
    MCStreams() {
        cudaStreamCreateWithFlags(&s1, cudaStreamNonBlocking);
        cudaStreamCreateWithFlags(&s2, cudaStreamNonBlocking);
        cudaEventCreateWithFlags(&eF,  cudaEventDisableTiming);
        cudaEventCreateWithFlags(&eL0, cudaEventDisableTiming);
        cudaEventCreateWithFlags(&eL1, cudaEventDisableTiming);
    }
};
static MCStreams g_s;

// ---------------------------------------------------------------------------
// im2col: coalesced both sides via smem transpose (unchanged)
// ---------------------------------------------------------------------------
__global__ void __launch_bounds__(256)
im2col_v2(const float* __restrict__ s1, int c1, long bs1,
          const float* __restrict__ s2, int c2, long bs2,
          int H, int W, int Cp, int Kh,
          uint32_t* __restrict__ Bh, uint32_t* __restrict__ Bl)
{
    __shared__ uint32_t sh[32][65];
    __shared__ uint32_t sl[32][65];
    __shared__ int st_t[32], st_c[32];
    __shared__ int sp_b[64], sp_y[64], sp_x[64];

    const int tid = threadIdx.x;
    const int kk0 = blockIdx.x * 32;
    const long n0 = (long)blockIdx.y * 64;
    const int HW = H * W;

    if (tid < 32) {
        int k0 = (kk0 + tid) * 2;
        int t = k0 / Cp;
        st_t[tid] = t;
        st_c[tid] = k0 - t * Cp;
    } else if (tid < 96) {
        int i = tid - 32;
        long n = n0 + i;
        int b = (int)(n / HW);
        int p = (int)(n - (long)b * HW);
        sp_b[i] = b;
        sp_y[i] = p / W;
        sp_x[i] = p % W;
    }
    __syncthreads();

    const int Cin = c1 + c2;
#pragma unroll
    for (int e = tid; e < 2048; e += 256) {
        const int p = e & 63, kk = e >> 6;
        const int t = st_t[kk], c = st_c[kk];
        float v0 = 0.f, v1 = 0.f;
        if (t < 9) {
            const int yy = sp_y[p] + t / 3 - 1;
            const int xx = sp_x[p] + t % 3 - 1;
            if (yy >= 0 && yy < H && xx >= 0 && xx < W) {
                const long sp = (long)yy * W + xx;
                const int b = sp_b[p];
                if (c < c1)          v0 = s1[(long)b * bs1 + (long)c * HW + sp];
                else if (c < Cin)    v0 = s2[(long)b * bs2 + (long)(c - c1) * HW + sp];
                const int cc = c + 1;
                if (cc < c1)         v1 = s1[(long)b * bs1 + (long)cc * HW + sp];
                else if (cc < Cin)   v1 = s2[(long)b * bs2 + (long)(cc - c1) * HW + sp];
            }
        }
        uint32_t lo;
        uint32_t hi = hilo_pack_hi(v0, v1, lo);
        sh[kk][p] = hi;
        sl[kk][p] = lo;
    }
    __syncthreads();

#pragma unroll
    for (int e = tid; e < 2048; e += 256) {
        const int kk = e & 31, p = e >> 5;
        const long o = (n0 + p) * Kh + kk0 + kk;
        Bh[o] = sh[kk][p];
        Bl[o] = sl[kk][p];
    }
}

// ---------------------------------------------------------------------------
// Fused weight convert: all 13 convs in one launch (blockIdx.y = job)
// ---------------------------------------------------------------------------
struct WJob {
    const float* w;
    uint32_t* Ah;
    uint32_t* Al;
    int M, Cin, Cp, Kp, total;
};
struct WJobs { WJob j[13]; };

__global__ void __launch_bounds__(256)
wconv_all(WJobs jobs)
{
    const WJob jb = jobs.j[blockIdx.y];
    int idx = blockIdx.x * 256 + threadIdx.x;
    if (idx >= jb.total) return;
    const int Kh = jb.Kp >> 1;
    const int kk = idx % Kh;
    const int m  = idx / Kh;
    const int k0 = kk * 2;
    const int t = k0 / jb.Cp, c = k0 - t * jb.Cp;
    float v0 = 0.f, v1 = 0.f;
    if (m < jb.M && t < 9) {
        if (c < jb.Cin)     v0 = jb.w[((long)m * jb.Cin + c) * 9 + t];
        if (c + 1 < jb.Cin) v1 = jb.w[((long)m * jb.Cin + c + 1) * 9 + t];
    }
    uint32_t lo;
    uint32_t hi = hilo_pack_hi(v0, v1, lo);
    jb.Ah[idx] = hi;
    jb.Al[idx] = lo;
}

// ---------------------------------------------------------------------------
// mma.sync GEMM, M-tile 128 x N-tile 128 (unchanged R9 winner)
// ---------------------------------------------------------------------------
#define LROW 40
#define PLANE (128 * LROW)
#define PLANE_B (PLANE * 2)
#define STAGE_B (4 * PLANE_B)
#define GEMM_SMEM (2 * STAGE_B)            // 80 KB

__global__ void __launch_bounds__(256, 2)
gemm_mma(const __nv_bfloat16* __restrict__ Ahi, const __nv_bfloat16* __restrict__ Alo,
         const __nv_bfloat16* __restrict__ Bhi, const __nv_bfloat16* __restrict__ Blo,
         const float* __restrict__ bias, float* __restrict__ out,
         int Kp, int nchunks, int Cout, int ocStride, int HW)
{
    extern __shared__ __nv_bfloat16 sm[];

    const int tid = threadIdx.x, wid = tid >> 5, lane = tid & 31;
    const int g = lane >> 2, t = lane & 3;
    const int wm = wid >> 2, wn = wid & 3;

    const int p0 = blockIdx.x * 128;
    const int m0 = blockIdx.y * 128;

    float acc[4][4][4];
#pragma unroll
    for (int i = 0; i < 4; i++)
#pragma unroll
        for (int j = 0; j < 4; j++)
#pragma unroll
            for (int k = 0; k < 4; k++) acc[i][j][k] = 0.f;

    const uint32_t smb = smem_u32(sm);

    const int r0 = tid >> 2, s0 = tid & 3;
    const int r1 = (tid + 256) >> 2, s1 = (tid + 256) & 3;

    uint32_t aoff[4], boff[2];
    {
        const int arow = (lane & 7) + ((lane >> 3) & 1) * 8;
        const int acol = (lane >> 4) * 8;
#pragma unroll
        for (int mt = 0; mt < 4; mt++)
            aoff[mt] = (uint32_t)(((wm * 64 + mt * 16 + arow) * LROW + acol) * 2);
        const int brow = (lane & 7) + (lane >> 4) * 8;
        const int bcol = ((lane >> 3) & 1) * 8;
#pragma unroll
        for (int np = 0; np < 2; np++)
            boff[np] = (uint32_t)(((wn * 32 + np * 16 + brow) * LROW + bcol) * 2);
    }

    auto stage = [&](int ci, int buf) {
        const long kc = (long)ci * 32;
        const uint32_t bufb = smb + (uint32_t)buf * STAGE_B;
        CP16(bufb + r0 * 80 + s0 * 16, Ahi + (long)(m0 + r0) * Kp + kc + s0 * 8);
        CP16(bufb + r1 * 80 + s1 * 16, Ahi + (long)(m0 + r1) * Kp + kc + s1 * 8);
        CP16(bufb + PLANE_B + r0 * 80 + s0 * 16, Alo + (long)(m0 + r0) * Kp + kc + s0 * 8);
        CP16(bufb + PLANE_B + r1 * 80 + s1 * 16, Alo + (long)(m0 + r1) * Kp + kc + s1 * 8);
        CP16(bufb + 2 * PLANE_B + r0 * 80 + s0 * 16, Bhi + (long)(p0 + r0) * Kp + kc + s0 * 8);
        CP16(bufb + 2 * PLANE_B + r1 * 80 + s1 * 16, Bhi + (long)(p0 + r1) * Kp + kc + s1 * 8);
        CP16(bufb + 3 * PLANE_B + r0 * 80 + s0 * 16, Blo + (long)(p0 + r0) * Kp + kc + s0 * 8);
        CP16(bufb + 3 * PLANE_B + r1 * 80 + s1 * 16, Blo + (long)(p0 + r1) * Kp + kc + s1 * 8);
    };

    stage(0, 0);
    CP_COMMIT();

    for (int ci = 0; ci < nchunks; ci++) {
        if (ci + 1 < nchunks) stage(ci + 1, (ci + 1) & 1);
        CP_COMMIT();
        CP_WAIT(1);
        __syncthreads();

        const uint32_t stg = smb + (uint32_t)(ci & 1) * STAGE_B;

#pragma unroll
        for (int s = 0; s < 2; s++) {
            const uint32_t cofs = (uint32_t)(s * 32);
            uint32_t afh[4][4], afl[4][4], bfh[2][4], bfl[2][4];
#pragma unroll
            for (int mt = 0; mt < 4; mt++) {
                LDSM4(afh[mt], stg + aoff[mt] + cofs);
                LDSM4(afl[mt], stg + PLANE_B + aoff[mt] + cofs);
            }
#pragma unroll
            for (int np = 0; np < 2; np++) {
                LDSM4(bfh[np], stg + 2 * PLANE_B + boff[np] + cofs);
                LDSM4(bfl[np], stg + 3 * PLANE_B + boff[np] + cofs);
            }
#pragma unroll
            for (int mt = 0; mt < 4; mt++)
#pragma unroll
                for (int nt = 0; nt < 4; nt++) {
                    const uint32_t* bh = &bfh[nt >> 1][(nt & 1) * 2];
                    const uint32_t* bl = &bfl[nt >> 1][(nt & 1) * 2];
                    mma16816(acc[mt][nt], afh[mt], bh[0], bh[1]);
                    mma16816(acc[mt][nt], afh[mt], bl[0], bl[1]);
                    mma16816(acc[mt][nt], afl[mt], bh[0], bh[1]);
                }
        }
        __syncthreads();
    }

    const int bIdx = p0 / HW, prow0 = p0 % HW;
#pragma unroll
    for (int mt = 0; mt < 4; mt++) {
        const int oca = m0 + wm * 64 + mt * 16 + g;
        const int ocb = oca + 8;
        const float ba = (oca < Cout) ? bias[oca] : 0.f;
        const float bb = (ocb < Cout) ? bias[ocb] : 0.f;
#pragma unroll
        for (int nt = 0; nt < 4; nt++) {
            const int pc = prow0 + wn * 32 + nt * 8 + 2 * t;
            if (oca < Cout) {
                float2 v = make_float2(acc[mt][nt][0] + ba, acc[mt][nt][1] + ba);
                *(float2*)&out[((long)bIdx * ocStride + oca) * HW + pc] = v;
            }
            if (ocb < Cout) {
                float2 v = make_float2(acc[mt][nt][2] + bb, acc[mt][nt][3] + bb);
                *(float2*)&out[((long)bIdx * ocStride + ocb) * HW + pc] = v;
            }
        }
    }
}

// ---------------------------------------------------------------------------
// mma.sync GEMM, M-tile 64 x N-tile 256 (for Cout <= 64): no M padding waste.
// A planes: 64 rows; B planes: 256 rows. All 8 warps share the 64 M-rows.
// ---------------------------------------------------------------------------
#define APL64_B (64 * LROW * 2)            // 5120 B per A plane
#define BPL64_B (256 * LROW * 2)           // 20480 B per B plane
#define STAGE64_B (2 * APL64_B + 2 * BPL64_B)  // 51200 B
#define GEMM64_SMEM (2 * STAGE64_B)        // 102400 B

__global__ void __launch_bounds__(256, 2)
gemm_mma64(const __nv_bfloat16* __restrict__ Ahi, const __nv_bfloat16* __restrict__ Alo,
           const __nv_bfloat16* __restrict__ Bhi, const __nv_bfloat16* __restrict__ Blo,
           const float* __restrict__ bias, float* __restrict__ out,
           int Kp, int nchunks, int Cout, int ocStride, int HW)
{
    extern __shared__ __nv_bfloat16 sm[];

    const int tid = threadIdx.x, wid = tid >> 5, lane = tid & 31;
    const int g = lane >> 2, t = lane & 3;
    const int wn = wid;                      // 8 warps across N

    const int p0 = blockIdx.x * 256;

    float acc[4][4][4];
#pragma unroll
    for (int i = 0; i < 4; i++)
#pragma unroll
        for (int j = 0; j < 4; j++)
#pragma unroll
            for (int k = 0; k < 4; k++) acc[i][j][k] = 0.f;

    const uint32_t smb = smem_u32(sm);

    // staging: A 256 tasks (1/thread), B 1024 tasks (4/thread)
    const int rA = tid >> 2, sA = tid & 3;

    uint32_t aoff[4], boff[2];
    {
        const int arow = (lane & 7) + ((lane >> 3) & 1) * 8;
        const int acol = (lane >> 4) * 8;
#pragma unroll
        for (int mt = 0; mt < 4; mt++)
            aoff[mt] = (uint32_t)(((mt * 16 + arow) * LROW + acol) * 2);
        const int brow = (lane & 7) + (lane >> 4) * 8;
        const int bcol = ((lane >> 3) & 1) * 8;
#pragma unroll
        for (int np = 0; np < 2; np++)
            boff[np] = (uint32_t)(((wn * 32 + np * 16 + brow) * LROW + bcol) * 2);
    }

    auto stage = [&](int ci, int buf) {
        const long kc = (long)ci * 32;
        const uint32_t bufb = smb + (uint32_t)buf * STAGE64_B;
        // A hi/lo (64 rows)
        CP16(bufb + rA * 80 + sA * 16, Ahi + (long)rA * Kp + kc + sA * 8);
        CP16(bufb + APL64_B + rA * 80 + sA * 16, Alo + (long)rA * Kp + kc + sA * 8);
        // B hi/lo (256 rows)
        const uint32_t bB = bufb + 2 * APL64_B;
#pragma unroll
        for (int j = 0; j < 4; j++) {
            const int task = tid + 256 * j;
            const int r = task >> 2, s = task & 3;
            CP16(bB + r * 80 + s * 16, Bhi + (long)(p0 + r) * Kp + kc + s * 8);
            CP16(bB + BPL64_B + r * 80 + s * 16, Blo + (long)(p0 + r) * Kp + kc + s * 8);
        }
    };

    stage(0, 0);
    CP_COMMIT();

    for (int ci = 0; ci < nchunks; ci++) {
        if (ci + 1 < nchunks) stage(ci + 1, (ci + 1) & 1);
        CP_COMMIT();
        CP_WAIT(1);
        __syncthreads();

        const uint32_t stg = smb + (uint32_t)(ci & 1) * STAGE64_B;
        const uint32_t stgB = stg + 2 * APL64_B;

#pragma unroll
        for (int s = 0; s < 2; s++) {
            const uint32_t cofs = (uint32_t)(s * 32);
            uint32_t afh[4][4], afl[4][4], bfh[2][4], bfl[2][4];
#pragma unroll
            for (int mt = 0; mt < 4; mt++) {
                LDSM4(afh[mt], stg + aoff[mt] + cofs);
                LDSM4(afl[mt], stg + APL64_B + aoff[mt] + cofs);
            }
#pragma unroll
            for (int np = 0; np < 2; np++) {
                LDSM4(bfh[np], stgB + boff[np] + cofs);
                LDSM4(bfl[np], stgB + BPL64_B + boff[np] + cofs);
            }
#pragma unroll
            for (int mt = 0; mt < 4; mt++)
#pragma unroll
                for (int nt = 0; nt < 4; nt++) {
                    const uint32_t* bh = &bfh[nt >> 1][(nt & 1) * 2];
                    const uint32_t* bl = &bfl[nt >> 1][(nt & 1) * 2];
                    mma16816(acc[mt][nt], afh[mt], bh[0], bh[1]);
                    mma16816(acc[mt][nt], afh[mt], bl[0], bl[1]);
                    mma16816(acc[mt][nt], afl[mt], bh[0], bh[1]);
                }
        }
        __syncthreads();
    }

    const int bIdx = p0 / HW, prow0 = p0 % HW;
#pragma unroll
    for (int mt = 0; mt < 4; mt++) {
        const int oca = mt * 16 + g;
        const int ocb = oca + 8;
        const float ba = (oca < Cout) ? bias[oca] : 0.f;
        const float bb = (ocb < Cout) ? bias[ocb] : 0.f;
#pragma unroll
        for (int nt = 0; nt < 4; nt++) {
            const int pc = prow0 + wn * 32 + nt * 8 + 2 * t;
            if (oca < Cout) {
                float2 v = make_float2(acc[mt][nt][0] + ba, acc[mt][nt][1] + ba);
                *(float2*)&out[((long)bIdx * ocStride + oca) * HW + pc] = v;
            }
            if (ocb < Cout) {
                float2 v = make_float2(acc[mt][nt][2] + bb, acc[mt][nt][3] + bb);
                *(float2*)&out[((long)bIdx * ocStride + ocb) * HW + pc] = v;
            }
        }
    }
}

// ---------------------------------------------------------------------------
// DCN bilinear sampler (unchanged)
// ---------------------------------------------------------------------------
__global__ void dcn_sample_bf(const float* __restrict__ x, long xbs,
                              const float* __restrict__ om,
                              uint4* __restrict__ Bh4, uint4* __restrict__ Bl4,
                              int C, int H, int W, int total)
{
    int idx = blockIdx.x * blockDim.x + threadIdx.x;
    if (idx >= total) return;
    const int HW = H * W;
    const int p = idx % HW;
    const int k = (idx / HW) % 9;
    const int g = (idx / (HW * 9)) % 8;
    const int b = idx / (HW * 72);
    const int y = p / W, xq = p % W;

    const long omb = (long)b * 216 * HW + (long)(g * 9 + k) * HW + p;
    float dy = om[omb];
    float dx = om[omb + 72L * HW];
    float mk = om[omb + 144L * HW];
    mk = 1.f / (1.f + expf(-mk));

    float pyf = (float)y + (float)(k / 3 - 1) + dy;
    float pxf = (float)xq + (float)(k % 3 - 1) + dx;
    float y0f = floorf(pyf), x0f = floorf(pxf);
    int y0 = (int)y0f, x0i = (int)x0f;
    float ty = pyf - y0f, tx = pxf - x0f;
    int y1 = y0 + 1, x1i = x0i + 1;

    bool vy0 = (y0 >= 0) && (y0 < H), vy1 = (y1 >= 0) && (y1 < H);
    bool vx0 = (x0i >= 0) && (x0i < W), vx1 = (x1i >= 0) && (x1i < W);
    float w00 = (vy0 && vx0) ? (1.f - ty) * (1.f - tx) : 0.f;
    float w01 = (vy0 && vx1) ? (1.f - ty) * tx : 0.f;
    float w10 = (vy1 && vx0) ? ty * (1.f - tx) : 0.f;
    float w11 = (vy1 && vx1) ? ty * tx : 0.f;
    w00 *= mk; w01 *= mk; w10 *= mk; w11 *= mk;

    int cy0 = min(max(y0, 0), H - 1), cy1 = min(max(y1, 0), H - 1);
    int cx0 = min(max(x0i, 0), W - 1), cx1 = min(max(x1i, 0), W - 1);
    int i00 = cy0 * W + cx0, i01 = cy0 * W + cx1;
    int i10 = cy1 * W + cx0, i11 = cy1 * W + cx1;

    const int Cg = C >> 3;
    const int K = C * 9;
    const float* xb = x + (long)b * xbs + (long)g * Cg * HW;
    const long rowbase = ((long)b * HW + p) * K + (long)k * C + (long)g * Cg;
    const long o4 = rowbase >> 3;

    for (int cb = 0; cb < Cg; cb += 8) {
        uint32_t hv[4], lv[4];
#pragma unroll
        for (int j = 0; j < 4; j++) {
            const float* xc0 = xb + (long)(cb + 2 * j) * HW;
            const float* xc1 = xc0 + HW;
            float v0 = w00 * xc0[i00] + w01 * xc0[i01] + w10 * xc0[i10] + w11 * xc0[i11];
            float v1 = w00 * xc1[i00] + w01 * xc1[i01] + w10 * xc1[i10] + w11 * xc1[i11];
            hv[j] = hilo_pack_hi(v0, v1, lv[j]);
        }
        const long o = o4 + (cb >> 3);
        Bh4[o] = make_uint4(hv[0], hv[1], hv[2], hv[3]);
        Bl4[o] = make_uint4(lv[0], lv[1], lv[2], lv[3]);
    }
}

// ---------------------------------------------------------------------------
// Bilinear 2x upsample (unchanged)
// ---------------------------------------------------------------------------
__global__ void up2_kernel(const float* __restrict__ in, float* __restrict__ out,
                           int H, int W, int total)
{
    int idx = blockIdx.x * blockDim.x + threadIdx.x;
    if (idx >= total) return;
    const int W2 = 2 * W, H2 = 2 * H;
    const int ox = idx % W2;
    const int oy = (idx / W2) % H2;
    const int bc = idx / (W2 * H2);

    float sy = fmaxf(oy * 0.5f - 0.25f, 0.f);
    float sx = fmaxf(ox * 0.5f - 0.25f, 0.f);
    int y0 = (int)floorf(sy); float ty = sy - (float)y0; int y1 = min(y0 + 1, H - 1);
    int x0 = (int)floorf(sx); float tx = sx - (float)x0; int x1 = min(x0 + 1, W - 1);

    const float* p = in + (long)bc * H * W;
    float a = p[y0 * W + x0] * (1.f - ty) + p[y1 * W + x0] * ty;
    float c = p[y0 * W + x1] * (1.f - ty) + p[y1 * W + x1] * ty;
    out[idx] = a * (1.f - tx) + c * tx;
}

// ---------------------------------------------------------------------------
extern "C" void kernel_launch(void* const* d_in, const int* in_sizes, int n_in,
                              void* d_out, int out_size)
{
    const float *x0 = nullptr, *x1 = nullptr, *x2 = nullptr;
    const float *flow0 = nullptr, *flow1 = nullptr, *flow2 = nullptr;
    for (int i = 0; i < 6; i++) {
        const float* p = (const float*)d_in[i];
        switch (in_sizes[i]) {
            case 4 * 2 * 64 * 128 * 128: x0 = p; break;
            case 4 * 2 * 128 * 64 * 64:  x1 = p; break;
            case 4 * 2 * 256 * 32 * 32:  x2 = p; break;
            case 4 * 2 * 128 * 128:      flow0 = p; break;
            case 4 * 2 * 64 * 64:        flow1 = p; break;
            case 4 * 2 * 32 * 32:        flow2 = p; break;
        }
    }
    const float* off_w0 = (const float*)d_in[6];  const float* off_b0 = (const float*)d_in[7];
    const float* co_w0  = (const float*)d_in[8];  const float* co_b0  = (const float*)d_in[9];
    const float* dcn_w0 = (const float*)d_in[10]; const float* dcn_b0 = (const float*)d_in[11];
    const float* off_w1 = (const float*)d_in[12]; const float* off_b1 = (const float*)d_in[13];
    const float* co_w1  = (const float*)d_in[14]; const float* co_b1  = (const float*)d_in[15];
    const float* dcn_w1 = (const float*)d_in[16]; const float* dcn_b1 = (const float*)d_in[17];
    const float* off_w2 = (const float*)d_in[18]; const float* off_b2 = (const float*)d_in[19];
    const float* co_w2  = (const float*)d_in[20]; const float* co_b2  = (const float*)d_in[21];
    const float* dcn_w2 = (const float*)d_in[22]; const float* dcn_b2 = (const float*)d_in[23];
    const float* ch_w0  = (const float*)d_in[24]; const float* ch_b0  = (const float*)d_in[25];
    const float* ft_w0  = (const float*)d_in[26]; const float* ft_b0  = (const float*)d_in[27];
    const float* ch_w1  = (const float*)d_in[28]; const float* ch_b1  = (const float*)d_in[29];
    const float* ft_w1  = (const float*)d_in[30]; const float* ft_b1  = (const float*)d_in[31];

    __nv_bfloat16 *B2h, *B2l, *B1h, *B1l, *B0h, *B0l, *Bfh, *Bfl, *Ah, *Al;
    float *offeat0, *offeat1, *offeat2, *om0, *om1, *om2, *fuse0, *fuse1, *upA, *upB;
    cudaGetSymbolAddress((void**)&B2h, g_B2h);  cudaGetSymbolAddress((void**)&B2l, g_B2l);
    cudaGetSymbolAddress((void**)&B1h, g_B1h);  cudaGetSymbolAddress((void**)&B1l, g_B1l);
    cudaGetSymbolAddress((void**)&B0h, g_B0h);  cudaGetSymbolAddress((void**)&B0l, g_B0l);
    cudaGetSymbolAddress((void**)&Bfh, g_Bfh);  cudaGetSymbolAddress((void**)&Bfl, g_Bfl);
    cudaGetSymbolAddress((void**)&Ah,  g_Ah);   cudaGetSymbolAddress((void**)&Al,  g_Al);
    cudaGetSymbolAddress((void**)&offeat0, g_offeat0);
    cudaGetSymbolAddress((void**)&offeat1, g_offeat1);
    cudaGetSymbolAddress((void**)&offeat2, g_offeat2);
    cudaGetSymbolAddress((void**)&om0, g_om0);
    cudaGetSymbolAddress((void**)&om1, g_om1);
    cudaGetSymbolAddress((void**)&om2, g_om2);
    cudaGetSymbolAddress((void**)&fuse0, g_fuse0);
    cudaGetSymbolAddress((void**)&fuse1, g_fuse1);
    cudaGetSymbolAddress((void**)&upA, g_upA);
    cudaGetSymbolAddress((void**)&upB, g_upB);

    cudaFuncSetAttribute(gemm_mma, cudaFuncAttributeMaxDynamicSharedMemorySize, GEMM_SMEM);
    cudaFuncSetAttribute(gemm_mma64, cudaFuncAttributeMaxDynamicSharedMemorySize, GEMM64_SMEM);

    float* out0 = (float*)d_out;
    float* out1 = out0 + 4L * 64 * 128 * 128;
    float* out2 = out1 + 4L * 128 * 64 * 64;

    const int B = 4;
    cudaStream_t S0 = 0, S1 = g_s.s1, S2 = g_s.s2;

    auto IM2COL = [&](cudaStream_t st, __nv_bfloat16* Bh, __nv_bfloat16* Bl,
                      const float* s1, int c1, long bs1, const float* s2, int c2, long bs2,
                      int H, int W, int Cp, int Kp) {
        const int Kh = Kp >> 1;
        dim3 grid(Kh / 32, (B * H * W) / 64);
        im2col_v2<<<grid, 256, 0, st>>>(s1, c1, bs1, s2, c2, bs2, H, W, Cp, Kh,
                                        (uint32_t*)Bh, (uint32_t*)Bl);
    };
    auto GEMM = [&](cudaStream_t st, int slot, __nv_bfloat16* Bh, __nv_bfloat16* Bl,
                    const float* bias, float* out, int Kp, int Cout, int ocStride,
                    int HW, int Mtiles) {
        dim3 grid((B * HW) / 128, Mtiles);
        gemm_mma<<<grid, 256, GEMM_SMEM, st>>>(
            Ah + (long)slot * ASLOT, Al + (long)slot * ASLOT, Bh, Bl, bias, out,
            Kp, Kp / 32, Cout, ocStride, HW);
    };
    auto GEMM64 = [&](cudaStream_t st, int slot, __nv_bfloat16* Bh, __nv_bfloat16* Bl,
                      const float* bias, float* out, int Kp, int Cout, int ocStride,
                      int HW) {
        dim3 grid((B * HW) / 256);
        gemm_mma64<<<grid, 256, GEMM64_SMEM, st>>>(
            Ah + (long)slot * ASLOT, Al + (long)slot * ASLOT, Bh, Bl, bias, out,
            Kp, Kp / 32, Cout, ocStride, HW);
    };
    auto DCN = [&](cudaStream_t st, const float* x, long xbs, const float* om,
                   __nv_bfloat16* Bh, __nv_bfloat16* Bl, int C, int H, int W) {
        int st_total = B * 72 * H * W;
        dcn_sample_bf<<<(st_total + 255) / 256, 256, 0, st>>>(
            x, xbs, om, (uint4*)Bh, (uint4*)Bl, C, H, W, st_total);
    };
    auto UP2 = [&](cudaStream_t st, const float* in, float* out, int H, int W, int C) {
        int total = B * C * 4 * H * W;
        up2_kernel<<<(total + 255) / 256, 256, 0, st>>>(in, out, H, W, total);
    };

    // ---- all weight conversions in ONE launch ----
    {
        WJobs jobs;
        auto J = [&](int i, const float* w, int M, int Cin, int Cp, int Kp, int Mp) {
            jobs.j[i] = WJob{w, (uint32_t*)(Ah + (long)i * ASLOT),
                             (uint32_t*)(Al + (long)i * ASLOT),
                             M, Cin, Cp, Kp, Mp * (Kp >> 1)};
        };
        J(0,  off_w2, 256, 514, 520, 4736, 256);
        J(1,  co_w2,  216, 256, 256, 2304, 256);
        J(2,  dcn_w2, 256, 256, 256, 2304, 256);
        J(3,  off_w1, 128, 258, 264, 2432, 128);
        J(4,  co_w1,  216, 128, 128, 1152, 256);
        J(5,  dcn_w1, 128, 128, 128, 1152, 128);
        J(6,  off_w0, 64,  130, 136, 1280, 64);
        J(7,  co_w0,  216, 64,  64,  576,  256);
        J(8,  dcn_w0, 64,  64,  64,  576,  64);
        J(9,  ch_w1,  128, 256, 256, 2304, 128);
        J(10, ft_w1,  128, 256, 256, 2304, 128);
        J(11, ch_w0,  64,  128, 128, 1152, 64);
        J(12, ft_w0,  64,  128, 128, 1152, 64);
        int maxBlocks = (256 * (4736 >> 1) + 255) / 256;
        wconv_all<<<dim3(maxBlocks, 13), 256, 0, S0>>>(jobs);
    }

    // ---- fork ----
    cudaEventRecord(g_s.eF, S0);
    cudaStreamWaitEvent(S1, g_s.eF, 0);
    cudaStreamWaitEvent(S2, g_s.eF, 0);

    // ---- s1: level 0 off/co/dcn chain (HW=16384, Cout=64 -> GEMM64) ----
    {
        const int H = 128, W = 128, HW = H * W;
        IM2COL(S1, B0h, B0l, x0, 128, 128L * HW, flow0, 2, 2L * HW, H, W, 136, 1280);
        GEMM64(S1, 6, B0h, B0l, off_b0, offeat0, 1280, 64, 64, HW);
        IM2COL(S1, B0h, B0l, offeat0, 64, 64L * HW, nullptr, 0, 0, H, W, 64, 576);
        GEMM(S1, 7, B0h, B0l, co_b0, om0, 576, 216, 216, HW, 2);
        DCN(S1, x0 + 64L * HW, 128L * HW, om0, B0h, B0l, 64, H, W);
        GEMM64(S1, 8, B0h, B0l, dcn_b0, fuse0, 576, 64, 128, HW);   // fuse0 ch [0,64)
        cudaEventRecord(g_s.eL0, S1);
    }

    // ---- s2: level 1 off/co/dcn chain (HW=4096) ----
    {
        const int H = 64, W = 64, HW = H * W;
        IM2COL(S2, B1h, B1l, x1, 256, 256L * HW, flow1, 2, 2L * HW, H, W, 264, 2432);
        GEMM(S2, 3, B1h, B1l, off_b1, offeat1, 2432, 128, 128, HW, 1);
        IM2COL(S2, B1h, B1l, offeat1, 128, 128L * HW, nullptr, 0, 0, H, W, 128, 1152);
        GEMM(S2, 4, B1h, B1l, co_b1, om1, 1152, 216, 216, HW, 2);
        DCN(S2, x1 + 128L * HW, 256L * HW, om1, B1h, B1l, 128, H, W);
        GEMM(S2, 5, B1h, B1l, dcn_b1, fuse1, 1152, 128, 256, HW, 1); // fuse1 ch [0,128)
        cudaEventRecord(g_s.eL1, S2);
    }

    // ---- origin: level 2 chain (HW=1024) + fusion cascade ----
    {
        const int H = 32, W = 32, HW = H * W;
        IM2COL(S0, B2h, B2l, x2, 512, 512L * HW, flow2, 2, 2L * HW, H, W, 520, 4736);
        GEMM(S0, 0, B2h, B2l, off_b2, offeat2, 4736, 256, 256, HW, 2);
        IM2COL(S0, B2h, B2l, offeat2, 256, 256L * HW, nullptr, 0, 0, H, W, 256, 2304);
        GEMM(S0, 1, B2h, B2l, co_b2, om2, 2304, 216, 216, HW, 2);
        DCN(S0, x2 + 256L * HW, 512L * HW, om2, B2h, B2l, 256, H, W);
        GEMM(S0, 2, B2h, B2l, dcn_b2, out2, 2304, 256, 256, HW, 2);
        UP2(S0, out2, upA, H, W, 256);
    }
    {   // level 1 fusion
        const int H = 64, W = 64, HW = H * W;
        IM2COL(S0, Bfh, Bfl, upA, 256, 256L * HW, nullptr, 0, 0, H, W, 256, 2304);
        GEMM(S0, 9, Bfh, Bfl, ch_b1, fuse1 + 128L * HW, 2304, 128, 256, HW, 1); // ch [128,256)
        cudaStreamWaitEvent(S0, g_s.eL1, 0);
        IM2COL(S0, Bfh, Bfl, fuse1, 256, 256L * HW, nullptr, 0, 0, H, W, 256, 2304);
        GEMM(S0, 10, Bfh, Bfl, ft_b1, out1, 2304, 128, 128, HW, 1);
        UP2(S0, out1, upB, H, W, 128);
    }
    {   // level 0 fusion
        const int H = 128, W = 128, HW = H * W;
        IM2COL(S0, Bfh, Bfl, upB, 128, 128L * HW, nullptr, 0, 0, H, W, 128, 1152);
        GEMM64(S0, 11, Bfh, Bfl, ch_b0, fuse0 + 64L * HW, 1152, 64, 128, HW);  // ch [64,128)
        cudaStreamWaitEvent(S0, g_s.eL0, 0);
        IM2COL(S0, Bfh, Bfl, fuse0, 128, 128L * HW, nullptr, 0, 0, H, W, 128, 1152);
        GEMM64(S0, 12, Bfh, Bfl, ft_b0, out0, 1152, 64, 64, HW);
    }
}

// round 11
// speedup vs baseline: 1.7771x; 1.3595x over previous
#include <cuda_runtime.h>
#include <cuda_bf16.h>
#include <math.h>
#include <stdint.h>

// ===========================================================================
// MotionCompensationBlock — HMMA bf16x3, implicit-tap GEMM (no im2col)
// Round 11: compact Xt[n][c] + tap-offset cp.async staging in the GEMM
// ===========================================================================

__device__ __forceinline__ uint32_t smem_u32(const void* p) {
    uint32_t a;
    asm("{ .reg .u64 t; cvta.to.shared.u64 t, %1; cvt.u32.u64 %0, t; }" : "=r"(a) : "l"(p));
    return a;
}

#define CP16(dst, src) \
    asm volatile("cp.async.cg.shared.global [%0], [%1], 16;" :: "r"(dst), "l"(src) : "memory")
#define CP_COMMIT() asm volatile("cp.async.commit_group;" ::: "memory")
#define CP_WAIT(n)  asm volatile("cp.async.wait_group %0;" :: "n"(n) : "memory")
#define ZSTS16(addr) \
    asm volatile("st.shared.v4.b32 [%0], {%1,%1,%1,%1};" :: "r"(addr), "r"(0u) : "memory")

#define LDSM4(r, addr) \
    asm volatile("ldmatrix.sync.aligned.m8n8.x4.shared.b16 {%0,%1,%2,%3}, [%4];" \
                 : "=r"((r)[0]), "=r"((r)[1]), "=r"((r)[2]), "=r"((r)[3]) : "r"(addr))

__device__ __forceinline__ void mma16816(float* c, const uint32_t* a,
                                         uint32_t b0, uint32_t b1) {
    asm volatile(
        "mma.sync.aligned.m16n8k16.row.col.f32.bf16.bf16.f32 "
        "{%0,%1,%2,%3}, {%4,%5,%6,%7}, {%8,%9}, {%0,%1,%2,%3};"
        : "+f"(c[0]), "+f"(c[1]), "+f"(c[2]), "+f"(c[3])
        : "r"(a[0]), "r"(a[1]), "r"(a[2]), "r"(a[3]), "r"(b0), "r"(b1));
}

__device__ __forceinline__ uint32_t hilo_pack_hi(float v0, float v1,
                                                 uint32_t& lo) {
    __nv_bfloat16 h0 = __float2bfloat16(v0), h1 = __float2bfloat16(v1);
    __nv_bfloat16 l0 = __float2bfloat16(v0 - __bfloat162float(h0));
    __nv_bfloat16 l1 = __float2bfloat16(v1 - __bfloat162float(h1));
    __nv_bfloat162 hp = __nv_bfloat162(h0, h1), lp = __nv_bfloat162(l0, l1);
    lo = *(uint32_t*)&lp;
    return *(uint32_t*)&hp;
}

// ------------------------------ pools --------------------------------------
#define POOL_U32 (68u << 20)
__device__ uint32_t g_XH[POOL_U32];
__device__ uint32_t g_XL[POOL_U32];
// offsets (u32 units)
#define O_XT0A  (0L)
#define O_XT0B  (6L  << 20)
#define O_SAMP0 (9L  << 20)
#define O_XT1A  (28L << 20)
#define O_XT1B  (31L << 20)
#define O_SAMP1 (33L << 20)
#define O_XT2A  (43L << 20)
#define O_XT2B  (45L << 20)
#define O_SAMP2 (46L << 20)
#define O_XTU1  (51L << 20)
#define O_XTF1  (54L << 20)
#define O_XTU0  (57L << 20)
#define O_XTF0  (62L << 20)

#define ASLOT 1253376
__device__ __nv_bfloat16 g_Ah[13L * ASLOT], g_Al[13L * ASLOT];
__device__ float g_offeat0[4194304], g_offeat1[2097152], g_offeat2[1048576];
__device__ float g_om0[14155776], g_om1[3538944], g_om2[884736];
__device__ float g_fuse0[8388608], g_fuse1[4194304];

// ------------------------------ streams ------------------------------------
struct MCStreams {
    cudaStream_t s1, s2;
    cudaEvent_t eF, eL0, eL1;
    MCStreams() {
        cudaStreamCreateWithFlags(&s1, cudaStreamNonBlocking);
        cudaStreamCreateWithFlags(&s2, cudaStreamNonBlocking);
        cudaEventCreateWithFlags(&eF,  cudaEventDisableTiming);
        cudaEventCreateWithFlags(&eL0, cudaEventDisableTiming);
        cudaEventCreateWithFlags(&eL1, cudaEventDisableTiming);
    }
};
static MCStreams g_s;

// ---------------------------------------------------------------------------
// xpose: NCHW fp32 (dual-source concat) -> Xt[n][c] bf16 hi/lo pairs.
// Tile 32 c-pairs x 64 pixels, smem transpose for coalescing both sides.
// ---------------------------------------------------------------------------
__global__ void __launch_bounds__(256)
xpose(const float* __restrict__ s1, int c1, long bs1,
      const float* __restrict__ s2, int c2, long bs2,
      int H, int W, int Cph,
      uint32_t* __restrict__ Xh, uint32_t* __restrict__ Xl)
{
    __shared__ uint32_t sh[32][65], sl[32][65];
    __shared__ int sp_b[64], sp_p[64];

    const int tid = threadIdx.x;
    const int cc0 = blockIdx.x * 32;
    const long n0 = (long)blockIdx.y * 64;
    const int HW = H * W;

    if (tid < 64) {
        long n = n0 + tid;
        int b = (int)(n / HW);
        sp_b[tid] = b;
        sp_p[tid] = (int)(n - (long)b * HW);
    }
    __syncthreads();

    const int Cin = c1 + c2;
#pragma unroll
    for (int e = tid; e < 2048; e += 256) {
        const int p = e & 63, cc = e >> 6;
        const int c = (cc0 + cc) * 2;
        float v0 = 0.f, v1 = 0.f;
        const int b = sp_b[p];
        const int sp = sp_p[p];
        if (c < c1)          v0 = s1[(long)b * bs1 + (long)c * HW + sp];
        else if (c < Cin)    v0 = s2[(long)b * bs2 + (long)(c - c1) * HW + sp];
        const int cn = c + 1;
        if (cn < c1)         v1 = s1[(long)b * bs1 + (long)cn * HW + sp];
        else if (cn < Cin)   v1 = s2[(long)b * bs2 + (long)(cn - c1) * HW + sp];
        uint32_t lo;
        uint32_t hi = hilo_pack_hi(v0, v1, lo);
        sh[cc][p] = hi;
        sl[cc][p] = lo;
    }
    __syncthreads();

#pragma unroll
    for (int e = tid; e < 2048; e += 256) {
        const int kk = e & 31, p = e >> 5;
        if (cc0 + kk < Cph) {
            const long o = (n0 + p) * Cph + cc0 + kk;
            Xh[o] = sh[kk][p];
            Xl[o] = sl[kk][p];
        }
    }
}

// ---------------------------------------------------------------------------
// up2_xt: fused bilinear 2x upsample (torch align_corners=False) + transpose
// to Xt[n][c] bf16 hi/lo. Source: fp32 [b][C][Hs][Ws].
// ---------------------------------------------------------------------------
__global__ void __launch_bounds__(256)
up2_xt(const float* __restrict__ src, int C, int Hs, int Ws, int Cph,
       uint32_t* __restrict__ Xh, uint32_t* __restrict__ Xl)
{
    __shared__ uint32_t sh[32][65], sl[32][65];
    __shared__ int sb[64], si0[64], si1[64], si2[64], si3[64];
    __shared__ float swy[64], swx[64];

    const int tid = threadIdx.x;
    const int cc0 = blockIdx.x * 32;
    const long n0 = (long)blockIdx.y * 64;
    const int W2 = 2 * Ws, H2 = 2 * Hs;
    const int HW2 = H2 * W2;
    const int HWs = Hs * Ws;

    if (tid < 64) {
        long n = n0 + tid;
        int b = (int)(n / HW2);
        int p2 = (int)(n - (long)b * HW2);
        int oy = p2 / W2, ox = p2 % W2;
        float sy = fmaxf(oy * 0.5f - 0.25f, 0.f);
        float sx = fmaxf(ox * 0.5f - 0.25f, 0.f);
        int y0 = (int)floorf(sy); float ty = sy - (float)y0;
        int y1 = min(y0 + 1, Hs - 1);
        int x0 = (int)floorf(sx); float tx = sx - (float)x0;
        int x1 = min(x0 + 1, Ws - 1);
        sb[tid] = b;
        si0[tid] = y0 * Ws + x0; si1[tid] = y0 * Ws + x1;
        si2[tid] = y1 * Ws + x0; si3[tid] = y1 * Ws + x1;
        swy[tid] = ty; swx[tid] = tx;
    }
    __syncthreads();

#pragma unroll
    for (int e = tid; e < 2048; e += 256) {
        const int p = e & 63, cc = e >> 6;
        const int c = (cc0 + cc) * 2;
        const float ty = swy[p], tx = swx[p];
        const int i0 = si0[p], i1 = si1[p], i2 = si2[p], i3 = si3[p];
        const float* pc = src + ((long)sb[p] * C + c) * HWs;
        float a0 = pc[i0] * (1.f - ty) + pc[i2] * ty;
        float a1 = pc[i1] * (1.f - ty) + pc[i3] * ty;
        float v0 = a0 * (1.f - tx) + a1 * tx;
        const float* pd = pc + HWs;
        float b0 = pd[i0] * (1.f - ty) + pd[i2] * ty;
        float b1 = pd[i1] * (1.f - ty) + pd[i3] * ty;
        float v1 = b0 * (1.f - tx) + b1 * tx;
        uint32_t lo;
        uint32_t hi = hilo_pack_hi(v0, v1, lo);
        sh[cc][p] = hi;
        sl[cc][p] = lo;
    }
    __syncthreads();

#pragma unroll
    for (int e = tid; e < 2048; e += 256) {
        const int kk = e & 31, p = e >> 5;
        const long o = (n0 + p) * Cph + cc0 + kk;
        Xh[o] = sh[kk][p];
        Xl[o] = sl[kk][p];
    }
}

// ---------------------------------------------------------------------------
// Fused weight convert: all 13 convs in one launch (blockIdx.y = job)
// ---------------------------------------------------------------------------
struct WJob {
    const float* w;
    uint32_t* Ah;
    uint32_t* Al;
    int M, Cin, Cp, Kp, total;
};
struct WJobs { WJob j[13]; };

__global__ void __launch_bounds__(256)
wconv_all(WJobs jobs)
{
    const WJob jb = jobs.j[blockIdx.y];
    int idx = blockIdx.x * 256 + threadIdx.x;
    if (idx >= jb.total) return;
    const int Kh = jb.Kp >> 1;
    const int kk = idx % Kh;
    const int m  = idx / Kh;
    const int k0 = kk * 2;
    const int t = k0 / jb.Cp, c = k0 - t * jb.Cp;
    float v0 = 0.f, v1 = 0.f;
    if (m < jb.M && t < 9) {
        if (c < jb.Cin)     v0 = jb.w[((long)m * jb.Cin + c) * 9 + t];
        if (c + 1 < jb.Cin) v1 = jb.w[((long)m * jb.Cin + c + 1) * 9 + t];
    }
    uint32_t lo;
    uint32_t hi = hilo_pack_hi(v0, v1, lo);
    jb.Ah[idx] = hi;
    jb.Al[idx] = lo;
}

// ===========================================================================
// GEMM common geometry
// ===========================================================================
#define LROW 40
#define PLANE (128 * LROW)
#define PLANE_B (PLANE * 2)
#define STAGE_B (4 * PLANE_B)
#define GEMM_SMEM (2 * STAGE_B)            // 80 KB (M128xN128)

#define APL64_B (64 * LROW * 2)
#define BPL64_B (256 * LROW * 2)
#define STAGE64_B (2 * APL64_B + 2 * BPL64_B)
#define GEMM64_SMEM (2 * STAGE64_B)        // 100 KB (M64xN256)

// MMA inner body shared by all GEMMs (s in {0,1} covers k16 halves)
#define MMA_BODY(stgA, plA, stgB, plB)                                         \
    _Pragma("unroll")                                                          \
    for (int s = 0; s < 2; s++) {                                              \
        const uint32_t cofs = (uint32_t)(s * 32);                              \
        uint32_t afh[4][4], afl[4][4], bfh[2][4], bfl[2][4];                   \
        _Pragma("unroll")                                                      \
        for (int mt = 0; mt < 4; mt++) {                                       \
            LDSM4(afh[mt], (stgA) + aoff[mt] + cofs);                          \
            LDSM4(afl[mt], (stgA) + (plA) + aoff[mt] + cofs);                  \
        }                                                                      \
        _Pragma("unroll")                                                      \
        for (int np = 0; np < 2; np++) {                                       \
            LDSM4(bfh[np], (stgB) + boff[np] + cofs);                          \
            LDSM4(bfl[np], (stgB) + (plB) + boff[np] + cofs);                  \
        }                                                                      \
        _Pragma("unroll")                                                      \
        for (int mt = 0; mt < 4; mt++)                                         \
            _Pragma("unroll")                                                  \
            for (int nt = 0; nt < 4; nt++) {                                   \
                const uint32_t* bh = &bfh[nt >> 1][(nt & 1) * 2];              \
                const uint32_t* bl = &bfl[nt >> 1][(nt & 1) * 2];              \
                mma16816(acc[mt][nt], afh[mt], bh[0], bh[1]);                  \
                mma16816(acc[mt][nt], afh[mt], bl[0], bl[1]);                  \
                mma16816(acc[mt][nt], afl[mt], bh[0], bh[1]);                  \
            }                                                                  \
    }

// ---------------------------------------------------------------------------
// gemm_tap: M128 x N128, implicit-tap B staging from compact Xt[n][Cp].
// K = 9*Cp; each 32-k chunk lies in one tap (Cp % 32 == 0).
// ---------------------------------------------------------------------------
__global__ void __launch_bounds__(256, 2)
gemm_tap(const __nv_bfloat16* __restrict__ Ahi, const __nv_bfloat16* __restrict__ Alo,
         const uint32_t* __restrict__ Xh, const uint32_t* __restrict__ Xl,
         const float* __restrict__ bias, float* __restrict__ out,
         int Kp, int Cp, int nchunks, int Cout, int ocStride, int H, int W)
{
    extern __shared__ __nv_bfloat16 sm[];

    const int tid = threadIdx.x, wid = tid >> 5, lane = tid & 31;
    const int g = lane >> 2, t = lane & 3;
    const int wm = wid >> 2, wn = wid & 3;
    const int HW = H * W;

    const int p0 = blockIdx.x * 128;
    const int m0 = blockIdx.y * 128;

    float acc[4][4][4];
#pragma unroll
    for (int i = 0; i < 4; i++)
#pragma unroll
        for (int j = 0; j < 4; j++)
#pragma unroll
            for (int k = 0; k < 4; k++) acc[i][j][k] = 0.f;

    const uint32_t smb = smem_u32(sm);
    const int r0 = tid >> 2, s0 = tid & 3;
    const int r1 = r0 + 64, s1 = s0;

    // per-row pixel coords (for tap validity)
    int b0r, y0r, x0r, b1r, y1r, x1r;
    {
        int n = p0 + r0; b0r = n / HW; int p = n - b0r * HW; y0r = p / W; x0r = p - y0r * W;
        n = p0 + r1; b1r = n / HW; p = n - b1r * HW; y1r = p / W; x1r = p - y1r * W;
    }

    uint32_t aoff[4], boff[2];
    {
        const int arow = (lane & 7) + ((lane >> 3) & 1) * 8;
        const int acol = (lane >> 4) * 8;
#pragma unroll
        for (int mt = 0; mt < 4; mt++)
            aoff[mt] = (uint32_t)(((wm * 64 + mt * 16 + arow) * LROW + acol) * 2);
        const int brow = (lane & 7) + (lane >> 4) * 8;
        const int bcol = ((lane >> 3) & 1) * 8;
#pragma unroll
        for (int np = 0; np < 2; np++)
            boff[np] = (uint32_t)(((wn * 32 + np * 16 + brow) * LROW + bcol) * 2);
    }

    const char* XhB = (const char*)Xh;
    const char* XlB = (const char*)Xl;
    const long rowB = (long)Cp * 2;   // bytes per Xt row

    auto stage = [&](int tp, int kin, int buf) {
        const long kc = (long)tp * Cp + kin;
        const uint32_t bufb = smb + (uint32_t)buf * STAGE_B;
        // A hi/lo
        CP16(bufb + r0 * 80 + s0 * 16, Ahi + (long)(m0 + r0) * Kp + kc + s0 * 8);
        CP16(bufb + r1 * 80 + s1 * 16, Ahi + (long)(m0 + r1) * Kp + kc + s1 * 8);
        CP16(bufb + PLANE_B + r0 * 80 + s0 * 16, Alo + (long)(m0 + r0) * Kp + kc + s0 * 8);
        CP16(bufb + PLANE_B + r1 * 80 + s1 * 16, Alo + (long)(m0 + r1) * Kp + kc + s1 * 8);
        // B hi/lo from Xt with tap offset + zero fill
        const int q = tp / 3;
        const int dy = q - 1, dx = tp - 3 * q - 1;
        const long cb = (long)kin * 2;
        {
            const int yy = y0r + dy, xx = x0r + dx;
            const uint32_t dH = bufb + 2 * PLANE_B + r0 * 80 + s0 * 16;
            const uint32_t dL = dH + PLANE_B;
            if ((unsigned)yy < (unsigned)H && (unsigned)xx < (unsigned)W) {
                const long src = ((long)b0r * HW + yy * W + xx) * rowB + cb + s0 * 16;
                CP16(dH, XhB + src);
                CP16(dL, XlB + src);
            } else { ZSTS16(dH); ZSTS16(dL); }
        }
        {
            const int yy = y1r + dy, xx = x1r + dx;
            const uint32_t dH = bufb + 2 * PLANE_B + r1 * 80 + s1 * 16;
            const uint32_t dL = dH + PLANE_B;
            if ((unsigned)yy < (unsigned)H && (unsigned)xx < (unsigned)W) {
                const long src = ((long)b1r * HW + yy * W + xx) * rowB + cb + s1 * 16;
                CP16(dH, XhB + src);
                CP16(dL, XlB + src);
            } else { ZSTS16(dH); ZSTS16(dL); }
        }
    };

    int tP = 0, kinP = 0;
    stage(tP, kinP, 0);
    CP_COMMIT();
    kinP += 32; if (kinP == Cp) { kinP = 0; tP++; }

    for (int ci = 0; ci < nchunks; ci++) {
        if (ci + 1 < nchunks) {
            stage(tP, kinP, (ci + 1) & 1);
            kinP += 32; if (kinP == Cp) { kinP = 0; tP++; }
        }
        CP_COMMIT();
        CP_WAIT(1);
        __syncthreads();

        const uint32_t stg = smb + (uint32_t)(ci & 1) * STAGE_B;
        MMA_BODY(stg, PLANE_B, stg + 2 * PLANE_B, PLANE_B)
        __syncthreads();
    }

    const int bIdx = p0 / HW, prow0 = p0 % HW;
#pragma unroll
    for (int mt = 0; mt < 4; mt++) {
        const int oca = m0 + wm * 64 + mt * 16 + g;
        const int ocb = oca + 8;
        const float ba = (oca < Cout) ? bias[oca] : 0.f;
        const float bb = (ocb < Cout) ? bias[ocb] : 0.f;
#pragma unroll
        for (int nt = 0; nt < 4; nt++) {
            const int pc = prow0 + wn * 32 + nt * 8 + 2 * t;
            if (oca < Cout) {
                float2 v = make_float2(acc[mt][nt][0] + ba, acc[mt][nt][1] + ba);
                *(float2*)&out[((long)bIdx * ocStride + oca) * HW + pc] = v;
            }
            if (ocb < Cout) {
                float2 v = make_float2(acc[mt][nt][2] + bb, acc[mt][nt][3] + bb);
                *(float2*)&out[((long)bIdx * ocStride + ocb) * HW + pc] = v;
            }
        }
    }
}

// ---------------------------------------------------------------------------
// gemm_tap64: M64 x N256, implicit-tap B staging (for Cout <= 64)
// ---------------------------------------------------------------------------
__global__ void __launch_bounds__(256, 2)
gemm_tap64(const __nv_bfloat16* __restrict__ Ahi, const __nv_bfloat16* __restrict__ Alo,
           const uint32_t* __restrict__ Xh, const uint32_t* __restrict__ Xl,
           const float* __restrict__ bias, float* __restrict__ out,
           int Kp, int Cp, int nchunks, int Cout, int ocStride, int H, int W)
{
    extern __shared__ __nv_bfloat16 sm[];

    const int tid = threadIdx.x, wid = tid >> 5, lane = tid & 31;
    const int g = lane >> 2, t = lane & 3;
    const int wn = wid;
    const int HW = H * W;

    const int p0 = blockIdx.x * 256;

    float acc[4][4][4];
#pragma unroll
    for (int i = 0; i < 4; i++)
#pragma unroll
        for (int j = 0; j < 4; j++)
#pragma unroll
            for (int k = 0; k < 4; k++) acc[i][j][k] = 0.f;

    const uint32_t smb = smem_u32(sm);
    const int rA = tid >> 2, sA = tid & 3;

    int b4[4], y4[4], x4[4];
#pragma unroll
    for (int j = 0; j < 4; j++) {
        int n = p0 + rA + 64 * j;
        b4[j] = n / HW;
        int p = n - b4[j] * HW;
        y4[j] = p / W;
        x4[j] = p - y4[j] * W;
    }

    uint32_t aoff[4], boff[2];
    {
        const int arow = (lane & 7) + ((lane >> 3) & 1) * 8;
        const int acol = (lane >> 4) * 8;
#pragma unroll
        for (int mt = 0; mt < 4; mt++)
            aoff[mt] = (uint32_t)(((mt * 16 + arow) * LROW + acol) * 2);
        const int brow = (lane & 7) + (lane >> 4) * 8;
        const int bcol = ((lane >> 3) & 1) * 8;
#pragma unroll
        for (int np = 0; np < 2; np++)
            boff[np] = (uint32_t)(((wn * 32 + np * 16 + brow) * LROW + bcol) * 2);
    }

    const char* XhB = (const char*)Xh;
    const char* XlB = (const char*)Xl;
    const long rowB = (long)Cp * 2;

    auto stage = [&](int tp, int kin, int buf) {
        const long kc = (long)tp * Cp + kin;
        const uint32_t bufb = smb + (uint32_t)buf * STAGE64_B;
        CP16(bufb + rA * 80 + sA * 16, Ahi + (long)rA * Kp + kc + sA * 8);
        CP16(bufb + APL64_B + rA * 80 + sA * 16, Alo + (long)rA * Kp + kc + sA * 8);
        const int q = tp / 3;
        const int dy = q - 1, dx = tp - 3 * q - 1;
        const long cb = (long)kin * 2;
        const uint32_t bB = bufb + 2 * APL64_B;
#pragma unroll
        for (int j = 0; j < 4; j++) {
            const int r = rA + 64 * j;
            const int yy = y4[j] + dy, xx = x4[j] + dx;
            const uint32_t dH = bB + r * 80 + sA * 16;
            const uint32_t dL = dH + BPL64_B;
            if ((unsigned)yy < (unsigned)H && (unsigned)xx < (unsigned)W) {
                const long src = ((long)b4[j] * HW + yy * W + xx) * rowB + cb + sA * 16;
                CP16(dH, XhB + src);
                CP16(dL, XlB + src);
            } else { ZSTS16(dH); ZSTS16(dL); }
        }
    };

    int tP = 0, kinP = 0;
    stage(tP, kinP, 0);
    CP_COMMIT();
    kinP += 32; if (kinP == Cp) { kinP = 0; tP++; }

    for (int ci = 0; ci < nchunks; ci++) {
        if (ci + 1 < nchunks) {
            stage(tP, kinP, (ci + 1) & 1);
            kinP += 32; if (kinP == Cp) { kinP = 0; tP++; }
        }
        CP_COMMIT();
        CP_WAIT(1);
        __syncthreads();

        const uint32_t stg = smb + (uint32_t)(ci & 1) * STAGE64_B;
        MMA_BODY(stg, APL64_B, stg + 2 * APL64_B, BPL64_B)
        __syncthreads();
    }

    const int bIdx = p0 / HW, prow0 = p0 % HW;
#pragma unroll
    for (int mt = 0; mt < 4; mt++) {
        const int oca = mt * 16 + g;
        const int ocb = oca + 8;
        const float ba = (oca < Cout) ? bias[oca] : 0.f;
        const float bb = (ocb < Cout) ? bias[ocb] : 0.f;
#pragma unroll
        for (int nt = 0; nt < 4; nt++) {
            const int pc = prow0 + wn * 32 + nt * 8 + 2 * t;
            if (oca < Cout) {
                float2 v = make_float2(acc[mt][nt][0] + ba, acc[mt][nt][1] + ba);
                *(float2*)&out[((long)bIdx * ocStride + oca) * HW + pc] = v;
            }
            if (ocb < Cout) {
                float2 v = make_float2(acc[mt][nt][2] + bb, acc[mt][nt][3] + bb);
                *(float2*)&out[((long)bIdx * ocStride + ocb) * HW + pc] = v;
            }
        }
    }
}

// ---------------------------------------------------------------------------
// gemm_mma / gemm_mma64: direct-B variants for the DCN GEMMs (B = samp[n][K])
// ---------------------------------------------------------------------------
__global__ void __launch_bounds__(256, 2)
gemm_mma(const __nv_bfloat16* __restrict__ Ahi, const __nv_bfloat16* __restrict__ Alo,
         const __nv_bfloat16* __restrict__ Bhi, const __nv_bfloat16* __restrict__ Blo,
         const float* __restrict__ bias, float* __restrict__ out,
         int Kp, int nchunks, int Cout, int ocStride, int HW)
{
    extern __shared__ __nv_bfloat16 sm[];

    const int tid = threadIdx.x, wid = tid >> 5, lane = tid & 31;
    const int g = lane >> 2, t = lane & 3;
    const int wm = wid >> 2, wn = wid & 3;

    const int p0 = blockIdx.x * 128;
    const int m0 = blockIdx.y * 128;

    float acc[4][4][4];
#pragma unroll
    for (int i = 0; i < 4; i++)
#pragma unroll
        for (int j = 0; j < 4; j++)
#pragma unroll
            for (int k = 0; k < 4; k++) acc[i][j][k] = 0.f;

    const uint32_t smb = smem_u32(sm);
    const int r0 = tid >> 2, s0 = tid & 3;
    const int r1 = r0 + 64, s1 = s0;

    uint32_t aoff[4], boff[2];
    {
        const int arow = (lane & 7) + ((lane >> 3) & 1) * 8;
        const int acol = (lane >> 4) * 8;
#pragma unroll
        for (int mt = 0; mt < 4; mt++)
            aoff[mt] = (uint32_t)(((wm * 64 + mt * 16 + arow) * LROW + acol) * 2);
        const int brow = (lane & 7) + (lane >> 4) * 8;
        const int bcol = ((lane >> 3) & 1) * 8;
#pragma unroll
        for (int np = 0; np < 2; np++)
            boff[np] = (uint32_t)(((wn * 32 + np * 16 + brow) * LROW + bcol) * 2);
    }

    auto stage = [&](int ci, int buf) {
        const long kc = (long)ci * 32;
        const uint32_t bufb = smb + (uint32_t)buf * STAGE_B;
        CP16(bufb + r0 * 80 + s0 * 16, Ahi + (long)(m0 + r0) * Kp + kc + s0 * 8);
        CP16(bufb + r1 * 80 + s1 * 16, Ahi + (long)(m0 + r1) * Kp + kc + s1 * 8);
        CP16(bufb + PLANE_B + r0 * 80 + s0 * 16, Alo + (long)(m0 + r0) * Kp + kc + s0 * 8);
        CP16(bufb + PLANE_B + r1 * 80 + s1 * 16, Alo + (long)(m0 + r1) * Kp + kc + s1 * 8);
        CP16(bufb + 2 * PLANE_B + r0 * 80 + s0 * 16, Bhi + (long)(p0 + r0) * Kp + kc + s0 * 8);
        CP16(bufb + 2 * PLANE_B + r1 * 80 + s1 * 16, Bhi + (long)(p0 + r1) * Kp + kc + s1 * 8);
        CP16(bufb + 3 * PLANE_B + r0 * 80 + s0 * 16, Blo + (long)(p0 + r0) * Kp + kc + s0 * 8);
        CP16(bufb + 3 * PLANE_B + r1 * 80 + s1 * 16, Blo + (long)(p0 + r1) * Kp + kc + s1 * 8);
    };

    stage(0, 0);
    CP_COMMIT();

    for (int ci = 0; ci < nchunks; ci++) {
        if (ci + 1 < nchunks) stage(ci + 1, (ci + 1) & 1);
        CP_COMMIT();
        CP_WAIT(1);
        __syncthreads();

        const uint32_t stg = smb + (uint32_t)(ci & 1) * STAGE_B;
        MMA_BODY(stg, PLANE_B, stg + 2 * PLANE_B, PLANE_B)
        __syncthreads();
    }

    const int bIdx = p0 / HW, prow0 = p0 % HW;
#pragma unroll
    for (int mt = 0; mt < 4; mt++) {
        const int oca = m0 + wm * 64 + mt * 16 + g;
        const int ocb = oca + 8;
        const float ba = (oca < Cout) ? bias[oca] : 0.f;
        const float bb = (ocb < Cout) ? bias[ocb] : 0.f;
#pragma unroll
        for (int nt = 0; nt < 4; nt++) {
            const int pc = prow0 + wn * 32 + nt * 8 + 2 * t;
            if (oca < Cout) {
                float2 v = make_float2(acc[mt][nt][0] + ba, acc[mt][nt][1] + ba);
                *(float2*)&out[((long)bIdx * ocStride + oca) * HW + pc] = v;
            }
            if (ocb < Cout) {
                float2 v = make_float2(acc[mt][nt][2] + bb, acc[mt][nt][3] + bb);
                *(float2*)&out[((long)bIdx * ocStride + ocb) * HW + pc] = v;
            }
        }
    }
}

__global__ void __launch_bounds__(256, 2)
gemm_mma64(const __nv_bfloat16* __restrict__ Ahi, const __nv_bfloat16* __restrict__ Alo,
           const __nv_bfloat16* __restrict__ Bhi, const __nv_bfloat16* __restrict__ Blo,
           const float* __restrict__ bias, float* __restrict__ out,
           int Kp, int nchunks, int Cout, int ocStride, int HW)
{
    extern __shared__ __nv_bfloat16 sm[];

    const int tid = threadIdx.x, wid = tid >> 5, lane = tid & 31;
    const int g = lane >> 2, t = lane & 3;
    const int wn = wid;

    const int p0 = blockIdx.x * 256;

    float acc[4][4][4];
#pragma unroll
    for (int i = 0; i < 4; i++)
#pragma unroll
        for (int j = 0; j < 4; j++)
#pragma unroll
            for (int k = 0; k < 4; k++) acc[i][j][k] = 0.f;

    const uint32_t smb = smem_u32(sm);
    const int rA = tid >> 2, sA = tid & 3;

    uint32_t aoff[4], boff[2];
    {
        const int arow = (lane & 7) + ((lane >> 3) & 1) * 8;
        const int acol = (lane >> 4) * 8;
#pragma unroll
        for (int mt = 0; mt < 4; mt++)
            aoff[mt] = (uint32_t)(((mt * 16 + arow) * LROW + acol) * 2);
        const int brow = (lane & 7) + (lane >> 4) * 8;
        const int bcol = ((lane >> 3) & 1) * 8;
#pragma unroll
        for (int np = 0; np < 2; np++)
            boff[np] = (uint32_t)(((wn * 32 + np * 16 + brow) * LROW + bcol) * 2);
    }

    auto stage = [&](int ci, int buf) {
        const long kc = (long)ci * 32;
        const uint32_t bufb = smb + (uint32_t)buf * STAGE64_B;
        CP16(bufb + rA * 80 + sA * 16, Ahi + (long)rA * Kp + kc + sA * 8);
        CP16(bufb + APL64_B + rA * 80 + sA * 16, Alo + (long)rA * Kp + kc + sA * 8);
        const uint32_t bB = bufb + 2 * APL64_B;
#pragma unroll
        for (int j = 0; j < 4; j++) {
            const int task = tid + 256 * j;
            const int r = task >> 2, s = task & 3;
            CP16(bB + r * 80 + s * 16, Bhi + (long)(p0 + r) * Kp + kc + s * 8);
            CP16(bB + BPL64_B + r * 80 + s * 16, Blo + (long)(p0 + r) * Kp + kc + s * 8);
        }
    };

    stage(0, 0);
    CP_COMMIT();

    for (int ci = 0; ci < nchunks; ci++) {
        if (ci + 1 < nchunks) stage(ci + 1, (ci + 1) & 1);
        CP_COMMIT();
        CP_WAIT(1);
        __syncthreads();

        const uint32_t stg = smb + (uint32_t)(ci & 1) * STAGE64_B;
        MMA_BODY(stg, APL64_B, stg + 2 * APL64_B, BPL64_B)
        __syncthreads();
    }

    const int bIdx = p0 / HW, prow0 = p0 % HW;
#pragma unroll
    for (int mt = 0; mt < 4; mt++) {
        const int oca = mt * 16 + g;
        const int ocb = oca + 8;
        const float ba = (oca < Cout) ? bias[oca] : 0.f;
        const float bb = (ocb < Cout) ? bias[ocb] : 0.f;
#pragma unroll
        for (int nt = 0; nt < 4; nt++) {
            const int pc = prow0 + wn * 32 + nt * 8 + 2 * t;
            if (oca < Cout) {
                float2 v = make_float2(acc[mt][nt][0] + ba, acc[mt][nt][1] + ba);
                *(float2*)&out[((long)bIdx * ocStride + oca) * HW + pc] = v;
            }
            if (ocb < Cout) {
                float2 v = make_float2(acc[mt][nt][2] + bb, acc[mt][nt][3] + bb);
                *(float2*)&out[((long)bIdx * ocStride + ocb) * HW + pc] = v;
            }
        }
    }
}

// ---------------------------------------------------------------------------
// DCN bilinear sampler -> samp[n][k = tap*C + g*Cg + c] bf16 hi/lo pairs
// ---------------------------------------------------------------------------
__global__ void dcn_sample_bf(const float* __restrict__ x, long xbs,
                              const float* __restrict__ om,
                              uint4* __restrict__ Bh4, uint4* __restrict__ Bl4,
                              int C, int H, int W, int total)
{
    int idx = blockIdx.x * blockDim.x + threadIdx.x;
    if (idx >= total) return;
    const int HW = H * W;
    const int p = idx % HW;
    const int k = (idx / HW) % 9;
    const int g = (idx / (HW * 9)) % 8;
    const int b = idx / (HW * 72);
    const int y = p / W, xq = p % W;

    const long omb = (long)b * 216 * HW + (long)(g * 9 + k) * HW + p;
    float dy = om[omb];
    float dx = om[omb + 72L * HW];
    float mk = om[omb + 144L * HW];
    mk = 1.f / (1.f + expf(-mk));

    float pyf = (float)y + (float)(k / 3 - 1) + dy;
    float pxf = (float)xq + (float)(k % 3 - 1) + dx;
    float y0f = floorf(pyf), x0f = floorf(pxf);
    int y0 = (int)y0f, x0i = (int)x0f;
    float ty = pyf - y0f, tx = pxf - x0f;
    int y1 = y0 + 1, x1i = x0i + 1;

    bool vy0 = (y0 >= 0) && (y0 < H), vy1 = (y1 >= 0) && (y1 < H);
    bool vx0 = (x0i >= 0) && (x0i < W), vx1 = (x1i >= 0) && (x1i < W);
    float w00 = (vy0 && vx0) ? (1.f - ty) * (1.f - tx) : 0.f;
    float w01 = (vy0 && vx1) ? (1.f - ty) * tx : 0.f;
    float w10 = (vy1 && vx0) ? ty * (1.f - tx) : 0.f;
    float w11 = (vy1 && vx1) ? ty * tx : 0.f;
    w00 *= mk; w01 *= mk; w10 *= mk; w11 *= mk;

    int cy0 = min(max(y0, 0), H - 1), cy1 = min(max(y1, 0), H - 1);
    int cx0 = min(max(x0i, 0), W - 1), cx1 = min(max(x1i, 0), W - 1);
    int i00 = cy0 * W + cx0, i01 = cy0 * W + cx1;
    int i10 = cy1 * W + cx0, i11 = cy1 * W + cx1;

    const int Cg = C >> 3;
    const int K = C * 9;
    const float* xb = x + (long)b * xbs + (long)g * Cg * HW;
    const long rowbase = ((long)b * HW + p) * K + (long)k * C + (long)g * Cg;
    const long o4 = rowbase >> 3;

    for (int cb = 0; cb < Cg; cb += 8) {
        uint32_t hv[4], lv[4];
#pragma unroll
        for (int j = 0; j < 4; j++) {
            const float* xc0 = xb + (long)(cb + 2 * j) * HW;
            const float* xc1 = xc0 + HW;
            float v0 = w00 * xc0[i00] + w01 * xc0[i01] + w10 * xc0[i10] + w11 * xc0[i11];
            float v1 = w00 * xc1[i00] + w01 * xc1[i01] + w10 * xc1[i10] + w11 * xc1[i11];
            hv[j] = hilo_pack_hi(v0, v1, lv[j]);
        }
        const long o = o4 + (cb >> 3);
        Bh4[o] = make_uint4(hv[0], hv[1], hv[2], hv[3]);
        Bl4[o] = make_uint4(lv[0], lv[1], lv[2], lv[3]);
    }
}

// ---------------------------------------------------------------------------
extern "C" void kernel_launch(void* const* d_in, const int* in_sizes, int n_in,
                              void* d_out, int out_size)
{
    const float *x0 = nullptr, *x1 = nullptr, *x2 = nullptr;
    const float *flow0 = nullptr, *flow1 = nullptr, *flow2 = nullptr;
    for (int i = 0; i < 6; i++) {
        const float* p = (const float*)d_in[i];
        switch (in_sizes[i]) {
            case 4 * 2 * 64 * 128 * 128: x0 = p; break;
            case 4 * 2 * 128 * 64 * 64:  x1 = p; break;
            case 4 * 2 * 256 * 32 * 32:  x2 = p; break;
            case 4 * 2 * 128 * 128:      flow0 = p; break;
            case 4 * 2 * 64 * 64:        flow1 = p; break;
            case 4 * 2 * 32 * 32:        flow2 = p; break;
        }
    }
    const float* off_w0 = (const float*)d_in[6];  const float* off_b0 = (const float*)d_in[7];
    const float* co_w0  = (const float*)d_in[8];  const float* co_b0  = (const float*)d_in[9];
    const float* dcn_w0 = (const float*)d_in[10]; const float* dcn_b0 = (const float*)d_in[11];
    const float* off_w1 = (const float*)d_in[12]; const float* off_b1 = (const float*)d_in[13];
    const float* co_w1  = (const float*)d_in[14]; const float* co_b1  = (const float*)d_in[15];
    const float* dcn_w1 = (const float*)d_in[16]; const float* dcn_b1 = (const float*)d_in[17];
    const float* off_w2 = (const float*)d_in[18]; const float* off_b2 = (const float*)d_in[19];
    const float* co_w2  = (const float*)d_in[20]; const float* co_b2  = (const float*)d_in[21];
    const float* dcn_w2 = (const float*)d_in[22]; const float* dcn_b2 = (const float*)d_in[23];
    const float* ch_w0  = (const float*)d_in[24]; const float* ch_b0  = (const float*)d_in[25];
    const float* ft_w0  = (const float*)d_in[26]; const float* ft_b0  = (const float*)d_in[27];
    const float* ch_w1  = (const float*)d_in[28]; const float* ch_b1  = (const float*)d_in[29];
    const float* ft_w1  = (const float*)d_in[30]; const float* ft_b1  = (const float*)d_in[31];

    uint32_t *XH, *XL;
    __nv_bfloat16 *Ah, *Al;
    float *offeat0, *offeat1, *offeat2, *om0, *om1, *om2, *fuse0, *fuse1;
    cudaGetSymbolAddress((void**)&XH, g_XH);
    cudaGetSymbolAddress((void**)&XL, g_XL);
    cudaGetSymbolAddress((void**)&Ah, g_Ah);
    cudaGetSymbolAddress((void**)&Al, g_Al);
    cudaGetSymbolAddress((void**)&offeat0, g_offeat0);
    cudaGetSymbolAddress((void**)&offeat1, g_offeat1);
    cudaGetSymbolAddress((void**)&offeat2, g_offeat2);
    cudaGetSymbolAddress((void**)&om0, g_om0);
    cudaGetSymbolAddress((void**)&om1, g_om1);
    cudaGetSymbolAddress((void**)&om2, g_om2);
    cudaGetSymbolAddress((void**)&fuse0, g_fuse0);
    cudaGetSymbolAddress((void**)&fuse1, g_fuse1);

    cudaFuncSetAttribute(gemm_tap,   cudaFuncAttributeMaxDynamicSharedMemorySize, GEMM_SMEM);
    cudaFuncSetAttribute(gemm_tap64, cudaFuncAttributeMaxDynamicSharedMemorySize, GEMM64_SMEM);
    cudaFuncSetAttribute(gemm_mma,   cudaFuncAttributeMaxDynamicSharedMemorySize, GEMM_SMEM);
    cudaFuncSetAttribute(gemm_mma64, cudaFuncAttributeMaxDynamicSharedMemorySize, GEMM64_SMEM);

    float* out0 = (float*)d_out;
    float* out1 = out0 + 4L * 64 * 128 * 128;
    float* out2 = out1 + 4L * 128 * 64 * 64;

    const int B = 4;
    cudaStream_t S0 = 0, S1 = g_s.s1, S2 = g_s.s2;

    auto XPOSE = [&](cudaStream_t st, long off, const float* s1, int c1, long bs1,
                     const float* s2, int c2, long bs2, int H, int W, int Cph) {
        dim3 grid((Cph + 31) / 32, (B * H * W) / 64);
        xpose<<<grid, 256, 0, st>>>(s1, c1, bs1, s2, c2, bs2, H, W, Cph,
                                    XH + off, XL + off);
    };
    auto UP2XT = [&](cudaStream_t st, long off, const float* src, int C,
                     int Hs, int Ws) {
        int Cph = C / 2;
        dim3 grid(Cph / 32, (B * 4 * Hs * Ws) / 64);
        up2_xt<<<grid, 256, 0, st>>>(src, C, Hs, Ws, Cph, XH + off, XL + off);
    };
    auto GTAP = [&](cudaStream_t st, int slot, long off, const float* bias, float* out,
                    int Kp, int Cp, int Cout, int ocStride, int H, int W, int Mtiles) {
        dim3 grid((B * H * W) / 128, Mtiles);
        gemm_tap<<<grid, 256, GEMM_SMEM, st>>>(
            Ah + (long)slot * ASLOT, Al + (long)slot * ASLOT, XH + off, XL + off,
            bias, out, Kp, Cp, Kp / 32, Cout, ocStride, H, W);
    };
    auto GTAP64 = [&](cudaStream_t st, int slot, long off, const float* bias, float* out,
                      int Kp, int Cp, int Cout, int ocStride, int H, int W) {
        dim3 grid((B * H * W) / 256);
        gemm_tap64<<<grid, 256, GEMM64_SMEM, st>>>(
            Ah + (long)slot * ASLOT, Al + (long)slot * ASLOT, XH + off, XL + off,
            bias, out, Kp, Cp, Kp / 32, Cout, ocStride, H, W);
    };
    auto GOLD = [&](cudaStream_t st, int slot, long off, const float* bias, float* out,
                    int Kp, int Cout, int ocStride, int HW, int Mtiles) {
        dim3 grid((B * HW) / 128, Mtiles);
        gemm_mma<<<grid, 256, GEMM_SMEM, st>>>(
            Ah + (long)slot * ASLOT, Al + (long)slot * ASLOT,
            (const __nv_bfloat16*)(XH + off), (const __nv_bfloat16*)(XL + off),
            bias, out, Kp, Kp / 32, Cout, ocStride, HW);
    };
    auto GOLD64 = [&](cudaStream_t st, int slot, long off, const float* bias, float* out,
                      int Kp, int Cout, int ocStride, int HW) {
        dim3 grid((B * HW) / 256);
        gemm_mma64<<<grid, 256, GEMM64_SMEM, st>>>(
            Ah + (long)slot * ASLOT, Al + (long)slot * ASLOT,
            (const __nv_bfloat16*)(XH + off), (const __nv_bfloat16*)(XL + off),
            bias, out, Kp, Kp / 32, Cout, ocStride, HW);
    };
    auto DCN = [&](cudaStream_t st, long off, const float* x, long xbs, const float* om,
                   int C, int H, int W) {
        int total = B * 72 * H * W;
        dcn_sample_bf<<<(total + 255) / 256, 256, 0, st>>>(
            x, xbs, om, (uint4*)(XH + off), (uint4*)(XL + off), C, H, W, total);
    };

    // ---- all weight conversions in ONE launch ----
    {
        WJobs jobs;
        auto J = [&](int i, const float* w, int M, int Cin, int Cp, int Kp, int Mp) {
            jobs.j[i] = WJob{w, (uint32_t*)(Ah + (long)i * ASLOT),
                             (uint32_t*)(Al + (long)i * ASLOT),
                             M, Cin, Cp, Kp, Mp * (Kp >> 1)};
        };
        J(0,  off_w2, 256, 514, 544, 4896, 256);
        J(1,  co_w2,  216, 256, 256, 2304, 256);
        J(2,  dcn_w2, 256, 256, 256, 2304, 256);
        J(3,  off_w1, 128, 258, 288, 2592, 128);
        J(4,  co_w1,  216, 128, 128, 1152, 256);
        J(5,  dcn_w1, 128, 128, 128, 1152, 128);
        J(6,  off_w0, 64,  130, 160, 1440, 64);
        J(7,  co_w0,  216, 64,  64,  576,  256);
        J(8,  dcn_w0, 64,  64,  64,  576,  64);
        J(9,  ch_w1,  128, 256, 256, 2304, 128);
        J(10, ft_w1,  128, 256, 256, 2304, 128);
        J(11, ch_w0,  64,  128, 128, 1152, 64);
        J(12, ft_w0,  64,  128, 128, 1152, 64);
        int maxBlocks = (256 * (4896 >> 1) + 255) / 256;
        wconv_all<<<dim3(maxBlocks, 13), 256, 0, S0>>>(jobs);
    }

    // ---- fork ----
    cudaEventRecord(g_s.eF, S0);
    cudaStreamWaitEvent(S1, g_s.eF, 0);
    cudaStreamWaitEvent(S2, g_s.eF, 0);

    // ---- s1: level 0 off/co/dcn chain (128x128) ----
    {
        const int H = 128, W = 128, HW = H * W;
        XPOSE(S1, O_XT0A, x0, 128, 128L * HW, flow0, 2, 2L * HW, H, W, 80);
        GTAP64(S1, 6, O_XT0A, off_b0, offeat0, 1440, 160, 64, 64, H, W);
        XPOSE(S1, O_XT0B, offeat0, 64, 64L * HW, nullptr, 0, 0, H, W, 32);
        GTAP(S1, 7, O_XT0B, co_b0, om0, 576, 64, 216, 216, H, W, 2);
        DCN(S1, O_SAMP0, x0 + 64L * HW, 128L * HW, om0, 64, H, W);
        GOLD64(S1, 8, O_SAMP0, dcn_b0, fuse0, 576, 64, 128, HW);   // fuse0 ch [0,64)
        cudaEventRecord(g_s.eL0, S1);
    }

    // ---- s2: level 1 off/co/dcn chain (64x64) ----
    {
        const int H = 64, W = 64, HW = H * W;
        XPOSE(S2, O_XT1A, x1, 256, 256L * HW, flow1, 2, 2L * HW, H, W, 144);
        GTAP(S2, 3, O_XT1A, off_b1, offeat1, 2592, 288, 128, 128, H, W, 1);
        XPOSE(S2, O_XT1B, offeat1, 128, 128L * HW, nullptr, 0, 0, H, W, 64);
        GTAP(S2, 4, O_XT1B, co_b1, om1, 1152, 128, 216, 216, H, W, 2);
        DCN(S2, O_SAMP1, x1 + 128L * HW, 256L * HW, om1, 128, H, W);
        GOLD(S2, 5, O_SAMP1, dcn_b1, fuse1, 1152, 128, 256, HW, 1); // fuse1 ch [0,128)
        cudaEventRecord(g_s.eL1, S2);
    }

    // ---- origin: level 2 chain (32x32) + fusion cascade ----
    {
        const int H = 32, W = 32, HW = H * W;
        XPOSE(S0, O_XT2A, x2, 512, 512L * HW, flow2, 2, 2L * HW, H, W, 272);
        GTAP(S0, 0, O_XT2A, off_b2, offeat2, 4896, 544, 256, 256, H, W, 2);
        XPOSE(S0, O_XT2B, offeat2, 256, 256L * HW, nullptr, 0, 0, H, W, 128);
        GTAP(S0, 1, O_XT2B, co_b2, om2, 2304, 256, 216, 216, H, W, 2);
        DCN(S0, O_SAMP2, x2 + 256L * HW, 512L * HW, om2, 256, H, W);
        GOLD(S0, 2, O_SAMP2, dcn_b2, out2, 2304, 256, 256, HW, 2);
        UP2XT(S0, O_XTU1, out2, 256, H, W);
    }
    {   // level 1 fusion (64x64)
        const int H = 64, W = 64, HW = H * W;
        GTAP(S0, 9, O_XTU1, ch_b1, fuse1 + 128L * HW, 2304, 256, 128, 256, H, W, 1);
        cudaStreamWaitEvent(S0, g_s.eL1, 0);
        XPOSE(S0, O_XTF1, fuse1, 256, 256L * HW, nullptr, 0, 0, H, W, 128);
        GTAP(S0, 10, O_XTF1, ft_b1, out1, 2304, 256, 128, 128, H, W, 1);
        UP2XT(S0, O_XTU0, out1, 128, H, W);
    }
    {   // level 0 fusion (128x128)
        const int H = 128, W = 128, HW = H * W;
        GTAP64(S0, 11, O_XTU0, ch_b0, fuse0 + 64L * HW, 1152, 128, 64, 128, H, W);
        cudaStreamWaitEvent(S0, g_s.eL0, 0);
        XPOSE(S0, O_XTF0, fuse0, 128, 128L * HW, nullptr, 0, 0, H, W, 64);
        GTAP64(S0, 12, O_XTF0, ft_b0, out0, 1152, 128, 64, 64, H, W);
    }
}

// round 12
// speedup vs baseline: 1.9427x; 1.0932x over previous
#include <cuda_runtime.h>
#include <cuda_bf16.h>
#include <math.h>
#include <stdint.h>

// ===========================================================================
// MotionCompensationBlock — HMMA bf16x3, implicit-tap GEMM + fused Xt epilogue
// Round 12: GEMMs write bf16 hi/lo Xt[n][c] directly (5 xposes removed)
// ===========================================================================

__device__ __forceinline__ uint32_t smem_u32(const void* p) {
    uint32_t a;
    asm("{ .reg .u64 t; cvta.to.shared.u64 t, %1; cvt.u32.u64 %0, t; }" : "=r"(a) : "l"(p));
    return a;
}

#define CP16(dst, src) \
    asm volatile("cp.async.cg.shared.global [%0], [%1], 16;" :: "r"(dst), "l"(src) : "memory")
#define CP_COMMIT() asm volatile("cp.async.commit_group;" ::: "memory")
#define CP_WAIT(n)  asm volatile("cp.async.wait_group %0;" :: "n"(n) : "memory")
#define ZSTS16(addr) \
    asm volatile("st.shared.v4.b32 [%0], {%1,%1,%1,%1};" :: "r"(addr), "r"(0u) : "memory")

#define LDSM4(r, addr) \
    asm volatile("ldmatrix.sync.aligned.m8n8.x4.shared.b16 {%0,%1,%2,%3}, [%4];" \
                 : "=r"((r)[0]), "=r"((r)[1]), "=r"((r)[2]), "=r"((r)[3]) : "r"(addr))

__device__ __forceinline__ void mma16816(float* c, const uint32_t* a,
                                         uint32_t b0, uint32_t b1) {
    asm volatile(
        "mma.sync.aligned.m16n8k16.row.col.f32.bf16.bf16.f32 "
        "{%0,%1,%2,%3}, {%4,%5,%6,%7}, {%8,%9}, {%0,%1,%2,%3};"
        : "+f"(c[0]), "+f"(c[1]), "+f"(c[2]), "+f"(c[3])
        : "r"(a[0]), "r"(a[1]), "r"(a[2]), "r"(a[3]), "r"(b0), "r"(b1));
}

__device__ __forceinline__ uint32_t hilo_pack_hi(float v0, float v1,
                                                 uint32_t& lo) {
    __nv_bfloat16 h0 = __float2bfloat16(v0), h1 = __float2bfloat16(v1);
    __nv_bfloat16 l0 = __float2bfloat16(v0 - __bfloat162float(h0));
    __nv_bfloat16 l1 = __float2bfloat16(v1 - __bfloat162float(h1));
    __nv_bfloat162 hp = __nv_bfloat162(h0, h1), lp = __nv_bfloat162(l0, l1);
    lo = *(uint32_t*)&lp;
    return *(uint32_t*)&hp;
}

// ------------------------------ pools --------------------------------------
#define POOL_U32 (68u << 20)
__device__ uint32_t g_XH[POOL_U32];
__device__ uint32_t g_XL[POOL_U32];
#define O_XT0A  (0L)
#define O_XT0B  (6L  << 20)
#define O_SAMP0 (9L  << 20)
#define O_XT1A  (28L << 20)
#define O_XT1B  (31L << 20)
#define O_SAMP1 (33L << 20)
#define O_XT2A  (43L << 20)
#define O_XT2B  (45L << 20)
#define O_SAMP2 (46L << 20)
#define O_XTU1  (51L << 20)
#define O_XTF1  (54L << 20)
#define O_XTU0  (57L << 20)
#define O_XTF0  (62L << 20)

#define ASLOT 1253376
__device__ __nv_bfloat16 g_Ah[13L * ASLOT], g_Al[13L * ASLOT];
__device__ float g_om0[14155776], g_om1[3538944], g_om2[884736];

// ------------------------------ streams ------------------------------------
struct MCStreams {
    cudaStream_t s1, s2;
    cudaEvent_t eF, eL0, eL1;
    MCStreams() {
        cudaStreamCreateWithFlags(&s1, cudaStreamNonBlocking);
        cudaStreamCreateWithFlags(&s2, cudaStreamNonBlocking);
        cudaEventCreateWithFlags(&eF,  cudaEventDisableTiming);
        cudaEventCreateWithFlags(&eL0, cudaEventDisableTiming);
        cudaEventCreateWithFlags(&eL1, cudaEventDisableTiming);
    }
};
static MCStreams g_s;

// ---------------------------------------------------------------------------
// xpose: NCHW fp32 (dual-source concat) -> Xt[n][c] bf16 hi/lo pairs
// ---------------------------------------------------------------------------
__global__ void __launch_bounds__(256)
xpose(const float* __restrict__ s1, int c1, long bs1,
      const float* __restrict__ s2, int c2, long bs2,
      int H, int W, int Cph,
      uint32_t* __restrict__ Xh, uint32_t* __restrict__ Xl)
{
    __shared__ uint32_t sh[32][65], sl[32][65];
    __shared__ int sp_b[64], sp_p[64];

    const int tid = threadIdx.x;
    const int cc0 = blockIdx.x * 32;
    const long n0 = (long)blockIdx.y * 64;
    const int HW = H * W;

    if (tid < 64) {
        long n = n0 + tid;
        int b = (int)(n / HW);
        sp_b[tid] = b;
        sp_p[tid] = (int)(n - (long)b * HW);
    }
    __syncthreads();

    const int Cin = c1 + c2;
#pragma unroll
    for (int e = tid; e < 2048; e += 256) {
        const int p = e & 63, cc = e >> 6;
        const int c = (cc0 + cc) * 2;
        float v0 = 0.f, v1 = 0.f;
        const int b = sp_b[p];
        const int sp = sp_p[p];
        if (c < c1)          v0 = s1[(long)b * bs1 + (long)c * HW + sp];
        else if (c < Cin)    v0 = s2[(long)b * bs2 + (long)(c - c1) * HW + sp];
        const int cn = c + 1;
        if (cn < c1)         v1 = s1[(long)b * bs1 + (long)cn * HW + sp];
        else if (cn < Cin)   v1 = s2[(long)b * bs2 + (long)(cn - c1) * HW + sp];
        uint32_t lo;
        uint32_t hi = hilo_pack_hi(v0, v1, lo);
        sh[cc][p] = hi;
        sl[cc][p] = lo;
    }
    __syncthreads();

#pragma unroll
    for (int e = tid; e < 2048; e += 256) {
        const int kk = e & 31, p = e >> 5;
        if (cc0 + kk < Cph) {
            const long o = (n0 + p) * Cph + cc0 + kk;
            Xh[o] = sh[kk][p];
            Xl[o] = sl[kk][p];
        }
    }
}

// ---------------------------------------------------------------------------
// up2_xt: fused bilinear 2x upsample + transpose to Xt[n][c] bf16 hi/lo
// ---------------------------------------------------------------------------
__global__ void __launch_bounds__(256)
up2_xt(const float* __restrict__ src, int C, int Hs, int Ws, int Cph,
       uint32_t* __restrict__ Xh, uint32_t* __restrict__ Xl)
{
    __shared__ uint32_t sh[32][65], sl[32][65];
    __shared__ int sb[64], si0[64], si1[64], si2[64], si3[64];
    __shared__ float swy[64], swx[64];

    const int tid = threadIdx.x;
    const int cc0 = blockIdx.x * 32;
    const long n0 = (long)blockIdx.y * 64;
    const int W2 = 2 * Ws, H2 = 2 * Hs;
    const int HW2 = H2 * W2;
    const int HWs = Hs * Ws;

    if (tid < 64) {
        long n = n0 + tid;
        int b = (int)(n / HW2);
        int p2 = (int)(n - (long)b * HW2);
        int oy = p2 / W2, ox = p2 % W2;
        float sy = fmaxf(oy * 0.5f - 0.25f, 0.f);
        float sx = fmaxf(ox * 0.5f - 0.25f, 0.f);
        int y0 = (int)floorf(sy); float ty = sy - (float)y0;
        int y1 = min(y0 + 1, Hs - 1);
        int x0 = (int)floorf(sx); float tx = sx - (float)x0;
        int x1 = min(x0 + 1, Ws - 1);
        sb[tid] = b;
        si0[tid] = y0 * Ws + x0; si1[tid] = y0 * Ws + x1;
        si2[tid] = y1 * Ws + x0; si3[tid] = y1 * Ws + x1;
        swy[tid] = ty; swx[tid] = tx;
    }
    __syncthreads();

#pragma unroll
    for (int e = tid; e < 2048; e += 256) {
        const int p = e & 63, cc = e >> 6;
        const int c = (cc0 + cc) * 2;
        const float ty = swy[p], tx = swx[p];
        const int i0 = si0[p], i1 = si1[p], i2 = si2[p], i3 = si3[p];
        const float* pc = src + ((long)sb[p] * C + c) * HWs;
        float a0 = pc[i0] * (1.f - ty) + pc[i2] * ty;
        float a1 = pc[i1] * (1.f - ty) + pc[i3] * ty;
        float v0 = a0 * (1.f - tx) + a1 * tx;
        const float* pd = pc + HWs;
        float b0 = pd[i0] * (1.f - ty) + pd[i2] * ty;
        float b1 = pd[i1] * (1.f - ty) + pd[i3] * ty;
        float v1 = b0 * (1.f - tx) + b1 * tx;
        uint32_t lo;
        uint32_t hi = hilo_pack_hi(v0, v1, lo);
        sh[cc][p] = hi;
        sl[cc][p] = lo;
    }
    __syncthreads();

#pragma unroll
    for (int e = tid; e < 2048; e += 256) {
        const int kk = e & 31, p = e >> 5;
        const long o = (n0 + p) * Cph + cc0 + kk;
        Xh[o] = sh[kk][p];
        Xl[o] = sl[kk][p];
    }
}

// ---------------------------------------------------------------------------
// Fused weight convert (unchanged)
// ---------------------------------------------------------------------------
struct WJob {
    const float* w;
    uint32_t* Ah;
    uint32_t* Al;
    int M, Cin, Cp, Kp, total;
};
struct WJobs { WJob j[13]; };

__global__ void __launch_bounds__(256)
wconv_all(WJobs jobs)
{
    const WJob jb = jobs.j[blockIdx.y];
    int idx = blockIdx.x * 256 + threadIdx.x;
    if (idx >= jb.total) return;
    const int Kh = jb.Kp >> 1;
    const int kk = idx % Kh;
    const int m  = idx / Kh;
    const int k0 = kk * 2;
    const int t = k0 / jb.Cp, c = k0 - t * jb.Cp;
    float v0 = 0.f, v1 = 0.f;
    if (m < jb.M && t < 9) {
        if (c < jb.Cin)     v0 = jb.w[((long)m * jb.Cin + c) * 9 + t];
        if (c + 1 < jb.Cin) v1 = jb.w[((long)m * jb.Cin + c + 1) * 9 + t];
    }
    uint32_t lo;
    uint32_t hi = hilo_pack_hi(v0, v1, lo);
    jb.Ah[idx] = hi;
    jb.Al[idx] = lo;
}

// ===========================================================================
// GEMM common geometry
// ===========================================================================
#define LROW 40
#define PLANE (128 * LROW)
#define PLANE_B (PLANE * 2)
#define STAGE_B (4 * PLANE_B)
#define GEMM_SMEM (2 * STAGE_B)            // 80 KB (M128xN128)

#define APL64_B (64 * LROW * 2)
#define BPL64_B (256 * LROW * 2)
#define STAGE64_B (2 * APL64_B + 2 * BPL64_B)
#define GEMM64_SMEM (2 * STAGE64_B)        // 100 KB (M64xN256)

#define MMA_BODY(stgA, plA, stgB, plB)                                         \
    _Pragma("unroll")                                                          \
    for (int s = 0; s < 2; s++) {                                              \
        const uint32_t cofs = (uint32_t)(s * 32);                              \
        uint32_t afh[4][4], afl[4][4], bfh[2][4], bfl[2][4];                   \
        _Pragma("unroll")                                                      \
        for (int mt = 0; mt < 4; mt++) {                                       \
            LDSM4(afh[mt], (stgA) + aoff[mt] + cofs);                          \
            LDSM4(afl[mt], (stgA) + (plA) + aoff[mt] + cofs);                  \
        }                                                                      \
        _Pragma("unroll")                                                      \
        for (int np = 0; np < 2; np++) {                                       \
            LDSM4(bfh[np], (stgB) + boff[np] + cofs);                          \
            LDSM4(bfl[np], (stgB) + (plB) + boff[np] + cofs);                  \
        }                                                                      \
        _Pragma("unroll")                                                      \
        for (int mt = 0; mt < 4; mt++)                                         \
            _Pragma("unroll")                                                  \
            for (int nt = 0; nt < 4; nt++) {                                   \
                const uint32_t* bh = &bfh[nt >> 1][(nt & 1) * 2];              \
                const uint32_t* bl = &bfl[nt >> 1][(nt & 1) * 2];              \
                mma16816(acc[mt][nt], afh[mt], bh[0], bh[1]);                  \
                mma16816(acc[mt][nt], afh[mt], bl[0], bl[1]);                  \
                mma16816(acc[mt][nt], afl[mt], bh[0], bh[1]);                  \
            }                                                                  \
    }

// fp32 NCHW epilogue (M128): writes out[b][oc][p]
#define EPI_FP32_128()                                                         \
    {                                                                          \
        const int bIdx = p0 / HW, prow0 = p0 % HW;                             \
        _Pragma("unroll")                                                      \
        for (int mt = 0; mt < 4; mt++) {                                       \
            const int oca = m0 + wm * 64 + mt * 16 + g;                        \
            const int ocb = oca + 8;                                           \
            const float ba = (oca < Cout) ? bias[oca] : 0.f;                   \
            const float bb = (ocb < Cout) ? bias[ocb] : 0.f;                   \
            _Pragma("unroll")                                                  \
            for (int nt = 0; nt < 4; nt++) {                                   \
                const int pc = prow0 + wn * 32 + nt * 8 + 2 * t;               \
                if (oca < Cout) {                                              \
                    float2 v = make_float2(acc[mt][nt][0] + ba, acc[mt][nt][1] + ba); \
                    *(float2*)&out[((long)bIdx * ocStride + oca) * HW + pc] = v; \
                }                                                              \
                if (ocb < Cout) {                                              \
                    float2 v = make_float2(acc[mt][nt][2] + bb, acc[mt][nt][3] + bb); \
                    *(float2*)&out[((long)bIdx * ocStride + ocb) * HW + pc] = v; \
                }                                                              \
            }                                                                  \
        }                                                                      \
    }

// Xt epilogue (M128 tile = 128 oc x 128 px): smem transpose -> Xt hi/lo
#define EPI_XT_128()                                                           \
    {                                                                          \
        float* sf = (float*)sm;                                                \
        _Pragma("unroll")                                                      \
        for (int mt = 0; mt < 4; mt++) {                                       \
            const int ra = wm * 64 + mt * 16 + g;                              \
            const float ba = bias[m0 + ra];                                    \
            const float bb = bias[m0 + ra + 8];                                \
            _Pragma("unroll")                                                  \
            for (int nt = 0; nt < 4; nt++) {                                   \
                const int pc = wn * 32 + nt * 8 + 2 * t;                       \
                sf[ra * 133 + pc]           = acc[mt][nt][0] + ba;             \
                sf[ra * 133 + pc + 1]       = acc[mt][nt][1] + ba;             \
                sf[(ra + 8) * 133 + pc]     = acc[mt][nt][2] + bb;             \
                sf[(ra + 8) * 133 + pc + 1] = acc[mt][nt][3] + bb;             \
            }                                                                  \
        }                                                                      \
        __syncthreads();                                                       \
        const int cpBase = xtCpOff + (m0 >> 1);                                \
        for (int e = tid; e < 8192; e += 256) {                                \
            const int cp = e & 63, px = e >> 6;                                \
            float v0 = sf[(2 * cp) * 133 + px];                                \
            float v1 = sf[(2 * cp + 1) * 133 + px];                            \
            uint32_t lo;                                                       \
            uint32_t hi = hilo_pack_hi(v0, v1, lo);                            \
            const long o = (long)(p0 + px) * xtCph + cpBase + cp;              \
            xtH[o] = hi; xtL[o] = lo;                                          \
        }                                                                      \
    }

#define EPI_FP32_64()                                                          \
    {                                                                          \
        const int bIdx = p0 / HW, prow0 = p0 % HW;                             \
        _Pragma("unroll")                                                      \
        for (int mt = 0; mt < 4; mt++) {                                       \
            const int oca = mt * 16 + g;                                       \
            const int ocb = oca + 8;                                           \
            const float ba = (oca < Cout) ? bias[oca] : 0.f;                   \
            const float bb = (ocb < Cout) ? bias[ocb] : 0.f;                   \
            _Pragma("unroll")                                                  \
            for (int nt = 0; nt < 4; nt++) {                                   \
                const int pc = prow0 + wn * 32 + nt * 8 + 2 * t;               \
                if (oca < Cout) {                                              \
                    float2 v = make_float2(acc[mt][nt][0] + ba, acc[mt][nt][1] + ba); \
                    *(float2*)&out[((long)bIdx * ocStride + oca) * HW + pc] = v; \
                }                                                              \
                if (ocb < Cout) {                                              \
                    float2 v = make_float2(acc[mt][nt][2] + bb, acc[mt][nt][3] + bb); \
                    *(float2*)&out[((long)bIdx * ocStride + ocb) * HW + pc] = v; \
                }                                                              \
            }                                                                  \
        }                                                                      \
    }

// Xt epilogue (M64 tile = 64 oc x 256 px)
#define EPI_XT_64()                                                            \
    {                                                                          \
        float* sf = (float*)sm;                                                \
        _Pragma("unroll")                                                      \
        for (int mt = 0; mt < 4; mt++) {                                       \
            const int ra = mt * 16 + g;                                        \
            const float ba = bias[ra];                                         \
            const float bb = bias[ra + 8];                                     \
            _Pragma("unroll")                                                  \
            for (int nt = 0; nt < 4; nt++) {                                   \
                const int pc = wn * 32 + nt * 8 + 2 * t;                       \
                sf[ra * 261 + pc]           = acc[mt][nt][0] + ba;             \
                sf[ra * 261 + pc + 1]       = acc[mt][nt][1] + ba;             \
                sf[(ra + 8) * 261 + pc]     = acc[mt][nt][2] + bb;             \
                sf[(ra + 8) * 261 + pc + 1] = acc[mt][nt][3] + bb;             \
            }                                                                  \
        }                                                                      \
        __syncthreads();                                                       \
        for (int e = tid; e < 8192; e += 256) {                                \
            const int cp = e & 31, px = e >> 5;                                \
            float v0 = sf[(2 * cp) * 261 + px];                                \
            float v1 = sf[(2 * cp + 1) * 261 + px];                            \
            uint32_t lo;                                                       \
            uint32_t hi = hilo_pack_hi(v0, v1, lo);                            \
            const long o = (long)(p0 + px) * xtCph + xtCpOff + cp;             \
            xtH[o] = hi; xtL[o] = lo;                                          \
        }                                                                      \
    }

// ---------------------------------------------------------------------------
// gemm_tap: M128 x N128, implicit-tap B staging from compact Xt[n][Cp]
// ---------------------------------------------------------------------------
__global__ void __launch_bounds__(256, 2)
gemm_tap(const __nv_bfloat16* __restrict__ Ahi, const __nv_bfloat16* __restrict__ Alo,
         const uint32_t* __restrict__ Xh, const uint32_t* __restrict__ Xl,
         const float* __restrict__ bias, float* __restrict__ out,
         int Kp, int Cp, int nchunks, int Cout, int ocStride, int H, int W,
         uint32_t* xtH, uint32_t* xtL, int xtCph, int xtCpOff)
{
    extern __shared__ __nv_bfloat16 sm[];

    const int tid = threadIdx.x, wid = tid >> 5, lane = tid & 31;
    const int g = lane >> 2, t = lane & 3;
    const int wm = wid >> 2, wn = wid & 3;
    const int HW = H * W;

    const int p0 = blockIdx.x * 128;
    const int m0 = blockIdx.y * 128;

    float acc[4][4][4];
#pragma unroll
    for (int i = 0; i < 4; i++)
#pragma unroll
        for (int j = 0; j < 4; j++)
#pragma unroll
            for (int k = 0; k < 4; k++) acc[i][j][k] = 0.f;

    const uint32_t smb = smem_u32(sm);
    const int r0 = tid >> 2, s0 = tid & 3;
    const int r1 = r0 + 64, s1 = s0;

    int b0r, y0r, x0r, b1r, y1r, x1r;
    {
        int n = p0 + r0; b0r = n / HW; int p = n - b0r * HW; y0r = p / W; x0r = p - y0r * W;
        n = p0 + r1; b1r = n / HW; p = n - b1r * HW; y1r = p / W; x1r = p - y1r * W;
    }

    uint32_t aoff[4], boff[2];
    {
        const int arow = (lane & 7) + ((lane >> 3) & 1) * 8;
        const int acol = (lane >> 4) * 8;
#pragma unroll
        for (int mt = 0; mt < 4; mt++)
            aoff[mt] = (uint32_t)(((wm * 64 + mt * 16 + arow) * LROW + acol) * 2);
        const int brow = (lane & 7) + (lane >> 4) * 8;
        const int bcol = ((lane >> 3) & 1) * 8;
#pragma unroll
        for (int np = 0; np < 2; np++)
            boff[np] = (uint32_t)(((wn * 32 + np * 16 + brow) * LROW + bcol) * 2);
    }

    const char* XhB = (const char*)Xh;
    const char* XlB = (const char*)Xl;
    const long rowB = (long)Cp * 2;

    auto stage = [&](int tp, int kin, int buf) {
        const long kc = (long)tp * Cp + kin;
        const uint32_t bufb = smb + (uint32_t)buf * STAGE_B;
        CP16(bufb + r0 * 80 + s0 * 16, Ahi + (long)(m0 + r0) * Kp + kc + s0 * 8);
        CP16(bufb + r1 * 80 + s1 * 16, Ahi + (long)(m0 + r1) * Kp + kc + s1 * 8);
        CP16(bufb + PLANE_B + r0 * 80 + s0 * 16, Alo + (long)(m0 + r0) * Kp + kc + s0 * 8);
        CP16(bufb + PLANE_B + r1 * 80 + s1 * 16, Alo + (long)(m0 + r1) * Kp + kc + s1 * 8);
        const int q = tp / 3;
        const int dy = q - 1, dx = tp - 3 * q - 1;
        const long cb = (long)kin * 2;
        {
            const int yy = y0r + dy, xx = x0r + dx;
            const uint32_t dH = bufb + 2 * PLANE_B + r0 * 80 + s0 * 16;
            const uint32_t dL = dH + PLANE_B;
            if ((unsigned)yy < (unsigned)H && (unsigned)xx < (unsigned)W) {
                const long src = ((long)b0r * HW + yy * W + xx) * rowB + cb + s0 * 16;
                CP16(dH, XhB + src);
                CP16(dL, XlB + src);
            } else { ZSTS16(dH); ZSTS16(dL); }
        }
        {
            const int yy = y1r + dy, xx = x1r + dx;
            const uint32_t dH = bufb + 2 * PLANE_B + r1 * 80 + s1 * 16;
            const uint32_t dL = dH + PLANE_B;
            if ((unsigned)yy < (unsigned)H && (unsigned)xx < (unsigned)W) {
                const long src = ((long)b1r * HW + yy * W + xx) * rowB + cb + s1 * 16;
                CP16(dH, XhB + src);
                CP16(dL, XlB + src);
            } else { ZSTS16(dH); ZSTS16(dL); }
        }
    };

    int tP = 0, kinP = 0;
    stage(tP, kinP, 0);
    CP_COMMIT();
    kinP += 32; if (kinP == Cp) { kinP = 0; tP++; }

    for (int ci = 0; ci < nchunks; ci++) {
        if (ci + 1 < nchunks) {
            stage(tP, kinP, (ci + 1) & 1);
            kinP += 32; if (kinP == Cp) { kinP = 0; tP++; }
        }
        CP_COMMIT();
        CP_WAIT(1);
        __syncthreads();

        const uint32_t stg = smb + (uint32_t)(ci & 1) * STAGE_B;
        MMA_BODY(stg, PLANE_B, stg + 2 * PLANE_B, PLANE_B)
        __syncthreads();
    }

    if (xtH) EPI_XT_128()
    else     EPI_FP32_128()
}

// ---------------------------------------------------------------------------
// gemm_tap64: M64 x N256, implicit-tap B staging (for Cout <= 64)
// ---------------------------------------------------------------------------
__global__ void __launch_bounds__(256, 2)
gemm_tap64(const __nv_bfloat16* __restrict__ Ahi, const __nv_bfloat16* __restrict__ Alo,
           const uint32_t* __restrict__ Xh, const uint32_t* __restrict__ Xl,
           const float* __restrict__ bias, float* __restrict__ out,
           int Kp, int Cp, int nchunks, int Cout, int ocStride, int H, int W,
           uint32_t* xtH, uint32_t* xtL, int xtCph, int xtCpOff)
{
    extern __shared__ __nv_bfloat16 sm[];

    const int tid = threadIdx.x, wid = tid >> 5, lane = tid & 31;
    const int g = lane >> 2, t = lane & 3;
    const int wn = wid;
    const int HW = H * W;

    const int p0 = blockIdx.x * 256;

    float acc[4][4][4];
#pragma unroll
    for (int i = 0; i < 4; i++)
#pragma unroll
        for (int j = 0; j < 4; j++)
#pragma unroll
            for (int k = 0; k < 4; k++) acc[i][j][k] = 0.f;

    const uint32_t smb = smem_u32(sm);
    const int rA = tid >> 2, sA = tid & 3;

    int b4[4], y4[4], x4[4];
#pragma unroll
    for (int j = 0; j < 4; j++) {
        int n = p0 + rA + 64 * j;
        b4[j] = n / HW;
        int p = n - b4[j] * HW;
        y4[j] = p / W;
        x4[j] = p - y4[j] * W;
    }

    uint32_t aoff[4], boff[2];
    {
        const int arow = (lane & 7) + ((lane >> 3) & 1) * 8;
        const int acol = (lane >> 4) * 8;
#pragma unroll
        for (int mt = 0; mt < 4; mt++)
            aoff[mt] = (uint32_t)(((mt * 16 + arow) * LROW + acol) * 2);
        const int brow = (lane & 7) + (lane >> 4) * 8;
        const int bcol = ((lane >> 3) & 1) * 8;
#pragma unroll
        for (int np = 0; np < 2; np++)
            boff[np] = (uint32_t)(((wn * 32 + np * 16 + brow) * LROW + bcol) * 2);
    }

    const char* XhB = (const char*)Xh;
    const char* XlB = (const char*)Xl;
    const long rowB = (long)Cp * 2;

    auto stage = [&](int tp, int kin, int buf) {
        const long kc = (long)tp * Cp + kin;
        const uint32_t bufb = smb + (uint32_t)buf * STAGE64_B;
        CP16(bufb + rA * 80 + sA * 16, Ahi + (long)rA * Kp + kc + sA * 8);
        CP16(bufb + APL64_B + rA * 80 + sA * 16, Alo + (long)rA * Kp + kc + sA * 8);
        const int q = tp / 3;
        const int dy = q - 1, dx = tp - 3 * q - 1;
        const long cb = (long)kin * 2;
        const uint32_t bB = bufb + 2 * APL64_B;
#pragma unroll
        for (int j = 0; j < 4; j++) {
            const int r = rA + 64 * j;
            const int yy = y4[j] + dy, xx = x4[j] + dx;
            const uint32_t dH = bB + r * 80 + sA * 16;
            const uint32_t dL = dH + BPL64_B;
            if ((unsigned)yy < (unsigned)H && (unsigned)xx < (unsigned)W) {
                const long src = ((long)b4[j] * HW + yy * W + xx) * rowB + cb + sA * 16;
                CP16(dH, XhB + src);
                CP16(dL, XlB + src);
            } else { ZSTS16(dH); ZSTS16(dL); }
        }
    };

    int tP = 0, kinP = 0;
    stage(tP, kinP, 0);
    CP_COMMIT();
    kinP += 32; if (kinP == Cp) { kinP = 0; tP++; }

    for (int ci = 0; ci < nchunks; ci++) {
        if (ci + 1 < nchunks) {
            stage(tP, kinP, (ci + 1) & 1);
            kinP += 32; if (kinP == Cp) { kinP = 0; tP++; }
        }
        CP_COMMIT();
        CP_WAIT(1);
        __syncthreads();

        const uint32_t stg = smb + (uint32_t)(ci & 1) * STAGE64_B;
        MMA_BODY(stg, APL64_B, stg + 2 * APL64_B, BPL64_B)
        __syncthreads();
    }

    if (xtH) EPI_XT_64()
    else     EPI_FP32_64()
}

// ---------------------------------------------------------------------------
// gemm_mma / gemm_mma64: direct-B variants (DCN GEMMs)
// ---------------------------------------------------------------------------
__global__ void __launch_bounds__(256, 2)
gemm_mma(const __nv_bfloat16* __restrict__ Ahi, const __nv_bfloat16* __restrict__ Alo,
         const __nv_bfloat16* __restrict__ Bhi, const __nv_bfloat16* __restrict__ Blo,
         const float* __restrict__ bias, float* __restrict__ out,
         int Kp, int nchunks, int Cout, int ocStride, int HW,
         uint32_t* xtH, uint32_t* xtL, int xtCph, int xtCpOff)
{
    extern __shared__ __nv_bfloat16 sm[];

    const int tid = threadIdx.x, wid = tid >> 5, lane = tid & 31;
    const int g = lane >> 2, t = lane & 3;
    const int wm = wid >> 2, wn = wid & 3;

    const int p0 = blockIdx.x * 128;
    const int m0 = blockIdx.y * 128;

    float acc[4][4][4];
#pragma unroll
    for (int i = 0; i < 4; i++)
#pragma unroll
        for (int j = 0; j < 4; j++)
#pragma unroll
            for (int k = 0; k < 4; k++) acc[i][j][k] = 0.f;

    const uint32_t smb = smem_u32(sm);
    const int r0 = tid >> 2, s0 = tid & 3;
    const int r1 = r0 + 64, s1 = s0;

    uint32_t aoff[4], boff[2];
    {
        const int arow = (lane & 7) + ((lane >> 3) & 1) * 8;
        const int acol = (lane >> 4) * 8;
#pragma unroll
        for (int mt = 0; mt < 4; mt++)
            aoff[mt] = (uint32_t)(((wm * 64 + mt * 16 + arow) * LROW + acol) * 2);
        const int brow = (lane & 7) + (lane >> 4) * 8;
        const int bcol = ((lane >> 3) & 1) * 8;
#pragma unroll
        for (int np = 0; np < 2; np++)
            boff[np] = (uint32_t)(((wn * 32 + np * 16 + brow) * LROW + bcol) * 2);
    }

    auto stage = [&](int ci, int buf) {
        const long kc = (long)ci * 32;
        const uint32_t bufb = smb + (uint32_t)buf * STAGE_B;
        CP16(bufb + r0 * 80 + s0 * 16, Ahi + (long)(m0 + r0) * Kp + kc + s0 * 8);
        CP16(bufb + r1 * 80 + s1 * 16, Ahi + (long)(m0 + r1) * Kp + kc + s1 * 8);
        CP16(bufb + PLANE_B + r0 * 80 + s0 * 16, Alo + (long)(m0 + r0) * Kp + kc + s0 * 8);
        CP16(bufb + PLANE_B + r1 * 80 + s1 * 16, Alo + (long)(m0 + r1) * Kp + kc + s1 * 8);
        CP16(bufb + 2 * PLANE_B + r0 * 80 + s0 * 16, Bhi + (long)(p0 + r0) * Kp + kc + s0 * 8);
        CP16(bufb + 2 * PLANE_B + r1 * 80 + s1 * 16, Bhi + (long)(p0 + r1) * Kp + kc + s1 * 8);
        CP16(bufb + 3 * PLANE_B + r0 * 80 + s0 * 16, Blo + (long)(p0 + r0) * Kp + kc + s0 * 8);
        CP16(bufb + 3 * PLANE_B + r1 * 80 + s1 * 16, Blo + (long)(p0 + r1) * Kp + kc + s1 * 8);
    };

    stage(0, 0);
    CP_COMMIT();

    for (int ci = 0; ci < nchunks; ci++) {
        if (ci + 1 < nchunks) stage(ci + 1, (ci + 1) & 1);
        CP_COMMIT();
        CP_WAIT(1);
        __syncthreads();

        const uint32_t stg = smb + (uint32_t)(ci & 1) * STAGE_B;
        MMA_BODY(stg, PLANE_B, stg + 2 * PLANE_B, PLANE_B)
        __syncthreads();
    }

    if (xtH) EPI_XT_128()
    else     EPI_FP32_128()
}

__global__ void __launch_bounds__(256, 2)
gemm_mma64(const __nv_bfloat16* __restrict__ Ahi, const __nv_bfloat16* __restrict__ Alo,
           const __nv_bfloat16* __restrict__ Bhi, const __nv_bfloat16* __restrict__ Blo,
           const float* __restrict__ bias, float* __restrict__ out,
           int Kp, int nchunks, int Cout, int ocStride, int HW,
           uint32_t* xtH, uint32_t* xtL, int xtCph, int xtCpOff)
{
    extern __shared__ __nv_bfloat16 sm[];

    const int tid = threadIdx.x, wid = tid >> 5, lane = tid & 31;
    const int g = lane >> 2, t = lane & 3;
    const int wn = wid;

    const int p0 = blockIdx.x * 256;

    float acc[4][4][4];
#pragma unroll
    for (int i = 0; i < 4; i++)
#pragma unroll
        for (int j = 0; j < 4; j++)
#pragma unroll
            for (int k = 0; k < 4; k++) acc[i][j][k] = 0.f;

    const uint32_t smb = smem_u32(sm);
    const int rA = tid >> 2, sA = tid & 3;

    uint32_t aoff[4], boff[2];
    {
        const int arow = (lane & 7) + ((lane >> 3) & 1) * 8;
        const int acol = (lane >> 4) * 8;
#pragma unroll
        for (int mt = 0; mt < 4; mt++)
            aoff[mt] = (uint32_t)(((mt * 16 + arow) * LROW + acol) * 2);
        const int brow = (lane & 7) + (lane >> 4) * 8;
        const int bcol = ((lane >> 3) & 1) * 8;
#pragma unroll
        for (int np = 0; np < 2; np++)
            boff[np] = (uint32_t)(((wn * 32 + np * 16 + brow) * LROW + bcol) * 2);
    }

    auto stage = [&](int ci, int buf) {
        const long kc = (long)ci * 32;
        const uint32_t bufb = smb + (uint32_t)buf * STAGE64_B;
        CP16(bufb + rA * 80 + sA * 16, Ahi + (long)rA * Kp + kc + sA * 8);
        CP16(bufb + APL64_B + rA * 80 + sA * 16, Alo + (long)rA * Kp + kc + sA * 8);
        const uint32_t bB = bufb + 2 * APL64_B;
#pragma unroll
        for (int j = 0; j < 4; j++) {
            const int task = tid + 256 * j;
            const int r = task >> 2, s = task & 3;
            CP16(bB + r * 80 + s * 16, Bhi + (long)(p0 + r) * Kp + kc + s * 8);
            CP16(bB + BPL64_B + r * 80 + s * 16, Blo + (long)(p0 + r) * Kp + kc + s * 8);
        }
    };

    stage(0, 0);
    CP_COMMIT();

    for (int ci = 0; ci < nchunks; ci++) {
        if (ci + 1 < nchunks) stage(ci + 1, (ci + 1) & 1);
        CP_COMMIT();
        CP_WAIT(1);
        __syncthreads();

        const uint32_t stg = smb + (uint32_t)(ci & 1) * STAGE64_B;
        MMA_BODY(stg, APL64_B, stg + 2 * APL64_B, BPL64_B)
        __syncthreads();
    }

    if (xtH) EPI_XT_64()
    else     EPI_FP32_64()
}

// ---------------------------------------------------------------------------
// DCN bilinear sampler (unchanged)
// ---------------------------------------------------------------------------
__global__ void dcn_sample_bf(const float* __restrict__ x, long xbs,
                              const float* __restrict__ om,
                              uint4* __restrict__ Bh4, uint4* __restrict__ Bl4,
                              int C, int H, int W, int total)
{
    int idx = blockIdx.x * blockDim.x + threadIdx.x;
    if (idx >= total) return;
    const int HW = H * W;
    const int p = idx % HW;
    const int k = (idx / HW) % 9;
    const int g = (idx / (HW * 9)) % 8;
    const int b = idx / (HW * 72);
    const int y = p / W, xq = p % W;

    const long omb = (long)b * 216 * HW + (long)(g * 9 + k) * HW + p;
    float dy = om[omb];
    float dx = om[omb + 72L * HW];
    float mk = om[omb + 144L * HW];
    mk = 1.f / (1.f + expf(-mk));

    float pyf = (float)y + (float)(k / 3 - 1) + dy;
    float pxf = (float)xq + (float)(k % 3 - 1) + dx;
    float y0f = floorf(pyf), x0f = floorf(pxf);
    int y0 = (int)y0f, x0i = (int)x0f;
    float ty = pyf - y0f, tx = pxf - x0f;
    int y1 = y0 + 1, x1i = x0i + 1;

    bool vy0 = (y0 >= 0) && (y0 < H), vy1 = (y1 >= 0) && (y1 < H);
    bool vx0 = (x0i >= 0) && (x0i < W), vx1 = (x1i >= 0) && (x1i < W);
    float w00 = (vy0 && vx0) ? (1.f - ty) * (1.f - tx) : 0.f;
    float w01 = (vy0 && vx1) ? (1.f - ty) * tx : 0.f;
    float w10 = (vy1 && vx0) ? ty * (1.f - tx) : 0.f;
    float w11 = (vy1 && vx1) ? ty * tx : 0.f;
    w00 *= mk; w01 *= mk; w10 *= mk; w11 *= mk;

    int cy0 = min(max(y0, 0), H - 1), cy1 = min(max(y1, 0), H - 1);
    int cx0 = min(max(x0i, 0), W - 1), cx1 = min(max(x1i, 0), W - 1);
    int i00 = cy0 * W + cx0, i01 = cy0 * W + cx1;
    int i10 = cy1 * W + cx0, i11 = cy1 * W + cx1;

    const int Cg = C >> 3;
    const int K = C * 9;
    const float* xb = x + (long)b * xbs + (long)g * Cg * HW;
    const long rowbase = ((long)b * HW + p) * K + (long)k * C + (long)g * Cg;
    const long o4 = rowbase >> 3;

    for (int cb = 0; cb < Cg; cb += 8) {
        uint32_t hv[4], lv[4];
#pragma unroll
        for (int j = 0; j < 4; j++) {
            const float* xc0 = xb + (long)(cb + 2 * j) * HW;
            const float* xc1 = xc0 + HW;
            float v0 = w00 * xc0[i00] + w01 * xc0[i01] + w10 * xc0[i10] + w11 * xc0[i11];
            float v1 = w00 * xc1[i00] + w01 * xc1[i01] + w10 * xc1[i10] + w11 * xc1[i11];
            hv[j] = hilo_pack_hi(v0, v1, lv[j]);
        }
        const long o = o4 + (cb >> 3);
        Bh4[o] = make_uint4(hv[0], hv[1], hv[2], hv[3]);
        Bl4[o] = make_uint4(lv[0], lv[1], lv[2], lv[3]);
    }
}

// ---------------------------------------------------------------------------
extern "C" void kernel_launch(void* const* d_in, const int* in_sizes, int n_in,
                              void* d_out, int out_size)
{
    const float *x0 = nullptr, *x1 = nullptr, *x2 = nullptr;
    const float *flow0 = nullptr, *flow1 = nullptr, *flow2 = nullptr;
    for (int i = 0; i < 6; i++) {
        const float* p = (const float*)d_in[i];
        switch (in_sizes[i]) {
            case 4 * 2 * 64 * 128 * 128: x0 = p; break;
            case 4 * 2 * 128 * 64 * 64:  x1 = p; break;
            case 4 * 2 * 256 * 32 * 32:  x2 = p; break;
            case 4 * 2 * 128 * 128:      flow0 = p; break;
            case 4 * 2 * 64 * 64:        flow1 = p; break;
            case 4 * 2 * 32 * 32:        flow2 = p; break;
        }
    }
    const float* off_w0 = (const float*)d_in[6];  const float* off_b0 = (const float*)d_in[7];
    const float* co_w0  = (const float*)d_in[8];  const float* co_b0  = (const float*)d_in[9];
    const float* dcn_w0 = (const float*)d_in[10]; const float* dcn_b0 = (const float*)d_in[11];
    const float* off_w1 = (const float*)d_in[12]; const float* off_b1 = (const float*)d_in[13];
    const float* co_w1  = (const float*)d_in[14]; const float* co_b1  = (const float*)d_in[15];
    const float* dcn_w1 = (const float*)d_in[16]; const float* dcn_b1 = (const float*)d_in[17];
    const float* off_w2 = (const float*)d_in[18]; const float* off_b2 = (const float*)d_in[19];
    const float* co_w2  = (const float*)d_in[20]; const float* co_b2  = (const float*)d_in[21];
    const float* dcn_w2 = (const float*)d_in[22]; const float* dcn_b2 = (const float*)d_in[23];
    const float* ch_w0  = (const float*)d_in[24]; const float* ch_b0  = (const float*)d_in[25];
    const float* ft_w0  = (const float*)d_in[26]; const float* ft_b0  = (const float*)d_in[27];
    const float* ch_w1  = (const float*)d_in[28]; const float* ch_b1  = (const float*)d_in[29];
    const float* ft_w1  = (const float*)d_in[30]; const float* ft_b1  = (const float*)d_in[31];

    uint32_t *XH, *XL;
    __nv_bfloat16 *Ah, *Al;
    float *om0, *om1, *om2;
    cudaGetSymbolAddress((void**)&XH, g_XH);
    cudaGetSymbolAddress((void**)&XL, g_XL);
    cudaGetSymbolAddress((void**)&Ah, g_Ah);
    cudaGetSymbolAddress((void**)&Al, g_Al);
    cudaGetSymbolAddress((void**)&om0, g_om0);
    cudaGetSymbolAddress((void**)&om1, g_om1);
    cudaGetSymbolAddress((void**)&om2, g_om2);

    cudaFuncSetAttribute(gemm_tap,   cudaFuncAttributeMaxDynamicSharedMemorySize, GEMM_SMEM);
    cudaFuncSetAttribute(gemm_tap64, cudaFuncAttributeMaxDynamicSharedMemorySize, GEMM64_SMEM);
    cudaFuncSetAttribute(gemm_mma,   cudaFuncAttributeMaxDynamicSharedMemorySize, GEMM_SMEM);
    cudaFuncSetAttribute(gemm_mma64, cudaFuncAttributeMaxDynamicSharedMemorySize, GEMM64_SMEM);

    float* out0 = (float*)d_out;
    float* out1 = out0 + 4L * 64 * 128 * 128;
    float* out2 = out1 + 4L * 128 * 64 * 64;

    const int B = 4;
    cudaStream_t S0 = 0, S1 = g_s.s1, S2 = g_s.s2;

    auto XPOSE = [&](cudaStream_t st, long off, const float* s1, int c1, long bs1,
                     const float* s2, int c2, long bs2, int H, int W, int Cph) {
        dim3 grid((Cph + 31) / 32, (B * H * W) / 64);
        xpose<<<grid, 256, 0, st>>>(s1, c1, bs1, s2, c2, bs2, H, W, Cph,
                                    XH + off, XL + off);
    };
    auto UP2XT = [&](cudaStream_t st, long off, const float* src, int C,
                     int Hs, int Ws) {
        int Cph = C / 2;
        dim3 grid(Cph / 32, (B * 4 * Hs * Ws) / 64);
        up2_xt<<<grid, 256, 0, st>>>(src, C, Hs, Ws, Cph, XH + off, XL + off);
    };
    auto GTAP = [&](cudaStream_t st, int slot, long off, const float* bias, float* out,
                    int Kp, int Cp, int Cout, int ocStride, int H, int W, int Mtiles,
                    long xtOff = -1, int xtCph = 0, int xtCpOff = 0) {
        dim3 grid((B * H * W) / 128, Mtiles);
        gemm_tap<<<grid, 256, GEMM_SMEM, st>>>(
            Ah + (long)slot * ASLOT, Al + (long)slot * ASLOT, XH + off, XL + off,
            bias, out, Kp, Cp, Kp / 32, Cout, ocStride, H, W,
            xtOff >= 0 ? XH + xtOff : nullptr, xtOff >= 0 ? XL + xtOff : nullptr,
            xtCph, xtCpOff);
    };
    auto GTAP64 = [&](cudaStream_t st, int slot, long off, const float* bias, float* out,
                      int Kp, int Cp, int Cout, int ocStride, int H, int W,
                      long xtOff = -1, int xtCph = 0, int xtCpOff = 0) {
        dim3 grid((B * H * W) / 256);
        gemm_tap64<<<grid, 256, GEMM64_SMEM, st>>>(
            Ah + (long)slot * ASLOT, Al + (long)slot * ASLOT, XH + off, XL + off,
            bias, out, Kp, Cp, Kp / 32, Cout, ocStride, H, W,
            xtOff >= 0 ? XH + xtOff : nullptr, xtOff >= 0 ? XL + xtOff : nullptr,
            xtCph, xtCpOff);
    };
    auto GOLD = [&](cudaStream_t st, int slot, long off, const float* bias, float* out,
                    int Kp, int Cout, int ocStride, int HW, int Mtiles,
                    long xtOff = -1, int xtCph = 0, int xtCpOff = 0) {
        dim3 grid((B * HW) / 128, Mtiles);
        gemm_mma<<<grid, 256, GEMM_SMEM, st>>>(
            Ah + (long)slot * ASLOT, Al + (long)slot * ASLOT,
            (const __nv_bfloat16*)(XH + off), (const __nv_bfloat16*)(XL + off),
            bias, out, Kp, Kp / 32, Cout, ocStride, HW,
            xtOff >= 0 ? XH + xtOff : nullptr, xtOff >= 0 ? XL + xtOff : nullptr,
            xtCph, xtCpOff);
    };
    auto GOLD64 = [&](cudaStream_t st, int slot, long off, const float* bias, float* out,
                      int Kp, int Cout, int ocStride, int HW,
                      long xtOff = -1, int xtCph = 0, int xtCpOff = 0) {
        dim3 grid((B * HW) / 256);
        gemm_mma64<<<grid, 256, GEMM64_SMEM, st>>>(
            Ah + (long)slot * ASLOT, Al + (long)slot * ASLOT,
            (const __nv_bfloat16*)(XH + off), (const __nv_bfloat16*)(XL + off),
            bias, out, Kp, Kp / 32, Cout, ocStride, HW,
            xtOff >= 0 ? XH + xtOff : nullptr, xtOff >= 0 ? XL + xtOff : nullptr,
            xtCph, xtCpOff);
    };
    auto DCN = [&](cudaStream_t st, long off, const float* x, long xbs, const float* om,
                   int C, int H, int W) {
        int total = B * 72 * H * W;
        dcn_sample_bf<<<(total + 255) / 256, 256, 0, st>>>(
            x, xbs, om, (uint4*)(XH + off), (uint4*)(XL + off), C, H, W, total);
    };

    // ---- all weight conversions in ONE launch ----
    {
        WJobs jobs;
        auto J = [&](int i, const float* w, int M, int Cin, int Cp, int Kp, int Mp) {
            jobs.j[i] = WJob{w, (uint32_t*)(Ah + (long)i * ASLOT),
                             (uint32_t*)(Al + (long)i * ASLOT),
                             M, Cin, Cp, Kp, Mp * (Kp >> 1)};
        };
        J(0,  off_w2, 256, 514, 544, 4896, 256);
        J(1,  co_w2,  216, 256, 256, 2304, 256);
        J(2,  dcn_w2, 256, 256, 256, 2304, 256);
        J(3,  off_w1, 128, 258, 288, 2592, 128);
        J(4,  co_w1,  216, 128, 128, 1152, 256);
        J(5,  dcn_w1, 128, 128, 128, 1152, 128);
        J(6,  off_w0, 64,  130, 160, 1440, 64);
        J(7,  co_w0,  216, 64,  64,  576,  256);
        J(8,  dcn_w0, 64,  64,  64,  576,  64);
        J(9,  ch_w1,  128, 256, 256, 2304, 128);
        J(10, ft_w1,  128, 256, 256, 2304, 128);
        J(11, ch_w0,  64,  128, 128, 1152, 64);
        J(12, ft_w0,  64,  128, 128, 1152, 64);
        int maxBlocks = (256 * (4896 >> 1) + 255) / 256;
        wconv_all<<<dim3(maxBlocks, 13), 256, 0, S0>>>(jobs);
    }

    // ---- fork ----
    cudaEventRecord(g_s.eF, S0);
    cudaStreamWaitEvent(S1, g_s.eF, 0);
    cudaStreamWaitEvent(S2, g_s.eF, 0);

    // ---- s1: level 0 off/co/dcn chain (128x128) ----
    {
        const int H = 128, W = 128, HW = H * W;
        XPOSE(S1, O_XT0A, x0, 128, 128L * HW, flow0, 2, 2L * HW, H, W, 80);
        GTAP64(S1, 6, O_XT0A, off_b0, nullptr, 1440, 160, 64, 64, H, W,
               O_XT0B, 32, 0);                                   // offeat0 -> Xt
        GTAP(S1, 7, O_XT0B, co_b0, om0, 576, 64, 216, 216, H, W, 2);
        DCN(S1, O_SAMP0, x0 + 64L * HW, 128L * HW, om0, 64, H, W);
        GOLD64(S1, 8, O_SAMP0, dcn_b0, nullptr, 576, 64, 128, HW,
               O_XTF0, 64, 0);                                   // fuse0 cp [0,32)
        cudaEventRecord(g_s.eL0, S1);
    }

    // ---- s2: level 1 off/co/dcn chain (64x64) ----
    {
        const int H = 64, W = 64, HW = H * W;
        XPOSE(S2, O_XT1A, x1, 256, 256L * HW, flow1, 2, 2L * HW, H, W, 144);
        GTAP(S2, 3, O_XT1A, off_b1, nullptr, 2592, 288, 128, 128, H, W, 1,
             O_XT1B, 64, 0);                                     // offeat1 -> Xt
        GTAP(S2, 4, O_XT1B, co_b1, om1, 1152, 128, 216, 216, H, W, 2);
        DCN(S2, O_SAMP1, x1 + 128L * HW, 256L * HW, om1, 128, H, W);
        GOLD(S2, 5, O_SAMP1, dcn_b1, nullptr, 1152, 128, 256, HW, 1,
             O_XTF1, 128, 0);                                    // fuse1 cp [0,64)
        cudaEventRecord(g_s.eL1, S2);
    }

    // ---- origin: level 2 chain (32x32) + fusion cascade ----
    {
        const int H = 32, W = 32, HW = H * W;
        XPOSE(S0, O_XT2A, x2, 512, 512L * HW, flow2, 2, 2L * HW, H, W, 272);
        GTAP(S0, 0, O_XT2A, off_b2, nullptr, 4896, 544, 256, 256, H, W, 2,
             O_XT2B, 128, 0);                                    // offeat2 -> Xt
        GTAP(S0, 1, O_XT2B, co_b2, om2, 2304, 256, 216, 216, H, W, 2);
        DCN(S0, O_SAMP2, x2 + 256L * HW, 512L * HW, om2, 256, H, W);
        GOLD(S0, 2, O_SAMP2, dcn_b2, out2, 2304, 256, 256, HW, 2);
        UP2XT(S0, O_XTU1, out2, 256, H, W);
    }
    {   // level 1 fusion (64x64)
        const int H = 64, W = 64, HW = H * W;
        GTAP(S0, 9, O_XTU1, ch_b1, nullptr, 2304, 256, 128, 256, H, W, 1,
             O_XTF1, 128, 64);                                   // fuse1 cp [64,128)
        cudaStreamWaitEvent(S0, g_s.eL1, 0);
        GTAP(S0, 10, O_XTF1, ft_b1, out1, 2304, 256, 128, 128, H, W, 1);
        UP2XT(S0, O_XTU0, out1, 128, H, W);
    }
    {   // level 0 fusion (128x128)
        const int H = 128, W = 128, HW = H * W;
        GTAP64(S0, 11, O_XTU0, ch_b0, nullptr, 1152, 128, 64, 128, H, W,
               O_XTF0, 64, 32);                                  // fuse0 cp [32,64)
        cudaStreamWaitEvent(S0, g_s.eL0, 0);
        GTAP64(S0, 12, O_XTF0, ft_b0, out0, 1152, 128, 64, 64, H, W);
    }
}

// round 14
// speedup vs baseline: 2.7558x; 1.4186x over previous
#include <cuda_runtime.h>
#include <cuda_fp16.h>
#include <math.h>
#include <stdint.h>

// ===========================================================================
// MotionCompensationBlock — HMMA fp16x2 (A hi/lo · B hi), implicit-tap GEMM
// Round 14: R13 structure with fp16 numerics (B residual 2^-11 vs bf16 2^-9)
// ===========================================================================

__device__ __forceinline__ uint32_t smem_u32(const void* p) {
    uint32_t a;
    asm("{ .reg .u64 t; cvta.to.shared.u64 t, %1; cvt.u32.u64 %0, t; }" : "=r"(a) : "l"(p));
    return a;
}

#define CP16(dst, src) \
    asm volatile("cp.async.cg.shared.global [%0], [%1], 16;" :: "r"(dst), "l"(src) : "memory")
#define CP_COMMIT() asm volatile("cp.async.commit_group;" ::: "memory")
#define CP_WAIT(n)  asm volatile("cp.async.wait_group %0;" :: "n"(n) : "memory")
#define ZSTS16(addr) \
    asm volatile("st.shared.v4.b32 [%0], {%1,%1,%1,%1};" :: "r"(addr), "r"(0u) : "memory")

#define LDSM4(r, addr) \
    asm volatile("ldmatrix.sync.aligned.m8n8.x4.shared.b16 {%0,%1,%2,%3}, [%4];" \
                 : "=r"((r)[0]), "=r"((r)[1]), "=r"((r)[2]), "=r"((r)[3]) : "r"(addr))

__device__ __forceinline__ void mma16816(float* c, const uint32_t* a,
                                         uint32_t b0, uint32_t b1) {
    asm volatile(
        "mma.sync.aligned.m16n8k16.row.col.f32.f16.f16.f32 "
        "{%0,%1,%2,%3}, {%4,%5,%6,%7}, {%8,%9}, {%0,%1,%2,%3};"
        : "+f"(c[0]), "+f"(c[1]), "+f"(c[2]), "+f"(c[3])
        : "r"(a[0]), "r"(a[1]), "r"(a[2]), "r"(a[3]), "r"(b0), "r"(b1));
}

__device__ __forceinline__ uint32_t hilo_pack_hi(float v0, float v1,
                                                 uint32_t& lo) {
    __half h0 = __float2half(v0), h1 = __float2half(v1);
    __half l0 = __float2half(v0 - __half2float(h0));
    __half l1 = __float2half(v1 - __half2float(h1));
    __half2 hp = __halves2half2(h0, h1), lp = __halves2half2(l0, l1);
    lo = *(uint32_t*)&lp;
    return *(uint32_t*)&hp;
}
__device__ __forceinline__ uint32_t pack_h2(float v0, float v1) {
    __half2 hp = __halves2half2(__float2half(v0), __float2half(v1));
    return *(uint32_t*)&hp;
}

// ------------------------------ pools --------------------------------------
#define POOL_U32 (68u << 20)
__device__ uint32_t g_XH[POOL_U32];
#define O_XT0A  (0L)
#define O_XT0B  (6L  << 20)
#define O_SAMP0 (9L  << 20)
#define O_XT1A  (28L << 20)
#define O_XT1B  (31L << 20)
#define O_SAMP1 (33L << 20)
#define O_XT2A  (43L << 20)
#define O_XT2B  (45L << 20)
#define O_SAMP2 (46L << 20)
#define O_XTU1  (51L << 20)
#define O_XTF1  (54L << 20)
#define O_XTU0  (57L << 20)
#define O_XTF0  (62L << 20)

#define ASLOT 1253376
__device__ __half g_Ah[13L * ASLOT], g_Al[13L * ASLOT];
__device__ float g_om0[14155776], g_om1[3538944], g_om2[884736];

// ------------------------------ streams ------------------------------------
struct MCStreams {
    cudaStream_t s1, s2;
    cudaEvent_t eF, eL0, eL1;
    MCStreams() {
        cudaStreamCreateWithFlags(&s1, cudaStreamNonBlocking);
        cudaStreamCreateWithFlags(&s2, cudaStreamNonBlocking);
        cudaEventCreateWithFlags(&eF,  cudaEventDisableTiming);
        cudaEventCreateWithFlags(&eL0, cudaEventDisableTiming);
        cudaEventCreateWithFlags(&eL1, cudaEventDisableTiming);
    }
};
static MCStreams g_s;

// ---------------------------------------------------------------------------
// xpose: NCHW fp32 (dual-source concat) -> Xt[n][c] fp16 pairs (hi only)
// ---------------------------------------------------------------------------
__global__ void __launch_bounds__(256)
xpose(const float* __restrict__ s1, int c1, long bs1,
      const float* __restrict__ s2, int c2, long bs2,
      int H, int W, int Cph, uint32_t* __restrict__ Xh)
{
    __shared__ uint32_t sh[32][65];
    __shared__ int sp_b[64], sp_p[64];

    const int tid = threadIdx.x;
    const int cc0 = blockIdx.x * 32;
    const long n0 = (long)blockIdx.y * 64;
    const int HW = H * W;

    if (tid < 64) {
        long n = n0 + tid;
        int b = (int)(n / HW);
        sp_b[tid] = b;
        sp_p[tid] = (int)(n - (long)b * HW);
    }
    __syncthreads();

    const int Cin = c1 + c2;
#pragma unroll
    for (int e = tid; e < 2048; e += 256) {
        const int p = e & 63, cc = e >> 6;
        const int c = (cc0 + cc) * 2;
        float v0 = 0.f, v1 = 0.f;
        const int b = sp_b[p];
        const int sp = sp_p[p];
        if (c < c1)          v0 = s1[(long)b * bs1 + (long)c * HW + sp];
        else if (c < Cin)    v0 = s2[(long)b * bs2 + (long)(c - c1) * HW + sp];
        const int cn = c + 1;
        if (cn < c1)         v1 = s1[(long)b * bs1 + (long)cn * HW + sp];
        else if (cn < Cin)   v1 = s2[(long)b * bs2 + (long)(cn - c1) * HW + sp];
        sh[cc][p] = pack_h2(v0, v1);
    }
    __syncthreads();

#pragma unroll
    for (int e = tid; e < 2048; e += 256) {
        const int kk = e & 31, p = e >> 5;
        if (cc0 + kk < Cph)
            Xh[(n0 + p) * Cph + cc0 + kk] = sh[kk][p];
    }
}

// ---------------------------------------------------------------------------
// up2_xt: fused bilinear 2x upsample + transpose to Xt[n][c] fp16 (hi only)
// ---------------------------------------------------------------------------
__global__ void __launch_bounds__(256)
up2_xt(const float* __restrict__ src, int C, int Hs, int Ws, int Cph,
       uint32_t* __restrict__ Xh)
{
    __shared__ uint32_t sh[32][65];
    __shared__ int sb[64], si0[64], si1[64], si2[64], si3[64];
    __shared__ float swy[64], swx[64];

    const int tid = threadIdx.x;
    const int cc0 = blockIdx.x * 32;
    const long n0 = (long)blockIdx.y * 64;
    const int W2 = 2 * Ws, H2 = 2 * Hs;
    const int HW2 = H2 * W2;
    const int HWs = Hs * Ws;

    if (tid < 64) {
        long n = n0 + tid;
        int b = (int)(n / HW2);
        int p2 = (int)(n - (long)b * HW2);
        int oy = p2 / W2, ox = p2 % W2;
        float sy = fmaxf(oy * 0.5f - 0.25f, 0.f);
        float sx = fmaxf(ox * 0.5f - 0.25f, 0.f);
        int y0 = (int)floorf(sy); float ty = sy - (float)y0;
        int y1 = min(y0 + 1, Hs - 1);
        int x0 = (int)floorf(sx); float tx = sx - (float)x0;
        int x1 = min(x0 + 1, Ws - 1);
        sb[tid] = b;
        si0[tid] = y0 * Ws + x0; si1[tid] = y0 * Ws + x1;
        si2[tid] = y1 * Ws + x0; si3[tid] = y1 * Ws + x1;
        swy[tid] = ty; swx[tid] = tx;
    }
    __syncthreads();

#pragma unroll
    for (int e = tid; e < 2048; e += 256) {
        const int p = e & 63, cc = e >> 6;
        const int c = (cc0 + cc) * 2;
        const float ty = swy[p], tx = swx[p];
        const int i0 = si0[p], i1 = si1[p], i2 = si2[p], i3 = si3[p];
        const float* pc = src + ((long)sb[p] * C + c) * HWs;
        float a0 = pc[i0] * (1.f - ty) + pc[i2] * ty;
        float a1 = pc[i1] * (1.f - ty) + pc[i3] * ty;
        float v0 = a0 * (1.f - tx) + a1 * tx;
        const float* pd = pc + HWs;
        float b0 = pd[i0] * (1.f - ty) + pd[i2] * ty;
        float b1 = pd[i1] * (1.f - ty) + pd[i3] * ty;
        float v1 = b0 * (1.f - tx) + b1 * tx;
        sh[cc][p] = pack_h2(v0, v1);
    }
    __syncthreads();

#pragma unroll
    for (int e = tid; e < 2048; e += 256) {
        const int kk = e & 31, p = e >> 5;
        Xh[(n0 + p) * Cph + cc0 + kk] = sh[kk][p];
    }
}

// ---------------------------------------------------------------------------
// Fused weight convert (A keeps hi/lo, fp16)
// ---------------------------------------------------------------------------
struct WJob {
    const float* w;
    uint32_t* Ah;
    uint32_t* Al;
    int M, Cin, Cp, Kp, total;
};
struct WJobs { WJob j[13]; };

__global__ void __launch_bounds__(256)
wconv_all(WJobs jobs)
{
    const WJob jb = jobs.j[blockIdx.y];
    int idx = blockIdx.x * 256 + threadIdx.x;
    if (idx >= jb.total) return;
    const int Kh = jb.Kp >> 1;
    const int kk = idx % Kh;
    const int m  = idx / Kh;
    const int k0 = kk * 2;
    const int t = k0 / jb.Cp, c = k0 - t * jb.Cp;
    float v0 = 0.f, v1 = 0.f;
    if (m < jb.M && t < 9) {
        if (c < jb.Cin)     v0 = jb.w[((long)m * jb.Cin + c) * 9 + t];
        if (c + 1 < jb.Cin) v1 = jb.w[((long)m * jb.Cin + c + 1) * 9 + t];
    }
    uint32_t lo;
    uint32_t hi = hilo_pack_hi(v0, v1, lo);
    jb.Ah[idx] = hi;
    jb.Al[idx] = lo;
}

// ===========================================================================
// GEMM common geometry (3 planes/stage: Ah, Al, Bh — 3-stage pipeline)
// ===========================================================================
#define LROW 40
#define PLANE_B (128 * LROW * 2)           // 10240 B
#define STG3_B (3 * PLANE_B)               // 30720 B
#define GEMM_SMEM (3 * STG3_B)             // 92160 B (M128xN128)

#define APL64_B (64 * LROW * 2)            // 5120 B
#define BPL64_B (256 * LROW * 2)           // 20480 B
#define STG64_B (2 * APL64_B + BPL64_B)    // 30720 B
#define GEMM64_SMEM (3 * STG64_B)          // 92160 B (M64xN256)

#define MMA_BODY2(stgA, plA, stgB)                                             \
    _Pragma("unroll")                                                          \
    for (int s = 0; s < 2; s++) {                                              \
        const uint32_t cofs = (uint32_t)(s * 32);                              \
        uint32_t afh[4][4], afl[4][4], bfh[2][4];                              \
        _Pragma("unroll")                                                      \
        for (int mt = 0; mt < 4; mt++) {                                       \
            LDSM4(afh[mt], (stgA) + aoff[mt] + cofs);                          \
            LDSM4(afl[mt], (stgA) + (plA) + aoff[mt] + cofs);                  \
        }                                                                      \
        _Pragma("unroll")                                                      \
        for (int np = 0; np < 2; np++)                                         \
            LDSM4(bfh[np], (stgB) + boff[np] + cofs);                          \
        _Pragma("unroll")                                                      \
        for (int mt = 0; mt < 4; mt++)                                         \
            _Pragma("unroll")                                                  \
            for (int nt = 0; nt < 4; nt++) {                                   \
                const uint32_t* bh = &bfh[nt >> 1][(nt & 1) * 2];              \
                mma16816(acc[mt][nt], afh[mt], bh[0], bh[1]);                  \
                mma16816(acc[mt][nt], afl[mt], bh[0], bh[1]);                  \
            }                                                                  \
    }

#define EPI_FP32_128()                                                         \
    {                                                                          \
        const int bIdx = p0 / HW, prow0 = p0 % HW;                             \
        _Pragma("unroll")                                                      \
        for (int mt = 0; mt < 4; mt++) {                                       \
            const int oca = m0 + wm * 64 + mt * 16 + g;                        \
            const int ocb = oca + 8;                                           \
            const float ba = (oca < Cout) ? bias[oca] : 0.f;                   \
            const float bb = (ocb < Cout) ? bias[ocb] : 0.f;                   \
            _Pragma("unroll")                                                  \
            for (int nt = 0; nt < 4; nt++) {                                   \
                const int pc = prow0 + wn * 32 + nt * 8 + 2 * t;               \
                if (oca < Cout) {                                              \
                    float2 v = make_float2(acc[mt][nt][0] + ba, acc[mt][nt][1] + ba); \
                    *(float2*)&out[((long)bIdx * ocStride + oca) * HW + pc] = v; \
                }                                                              \
                if (ocb < Cout) {                                              \
                    float2 v = make_float2(acc[mt][nt][2] + bb, acc[mt][nt][3] + bb); \
                    *(float2*)&out[((long)bIdx * ocStride + ocb) * HW + pc] = v; \
                }                                                              \
            }                                                                  \
        }                                                                      \
    }

#define EPI_XT_128()                                                           \
    {                                                                          \
        float* sf = (float*)sm;                                                \
        _Pragma("unroll")                                                      \
        for (int mt = 0; mt < 4; mt++) {                                       \
            const int ra = wm * 64 + mt * 16 + g;                              \
            const float ba = bias[m0 + ra];                                    \
            const float bb = bias[m0 + ra + 8];                                \
            _Pragma("unroll")                                                  \
            for (int nt = 0; nt < 4; nt++) {                                   \
                const int pc = wn * 32 + nt * 8 + 2 * t;                       \
                sf[ra * 133 + pc]           = acc[mt][nt][0] + ba;             \
                sf[ra * 133 + pc + 1]       = acc[mt][nt][1] + ba;             \
                sf[(ra + 8) * 133 + pc]     = acc[mt][nt][2] + bb;             \
                sf[(ra + 8) * 133 + pc + 1] = acc[mt][nt][3] + bb;             \
            }                                                                  \
        }                                                                      \
        __syncthreads();                                                       \
        const int cpBase = xtCpOff + (m0 >> 1);                                \
        for (int e = tid; e < 8192; e += 256) {                                \
            const int cp = e & 63, px = e >> 6;                                \
            xtH[(long)(p0 + px) * xtCph + cpBase + cp] =                       \
                pack_h2(sf[(2 * cp) * 133 + px], sf[(2 * cp + 1) * 133 + px]); \
        }                                                                      \
    }

#define EPI_FP32_64()                                                          \
    {                                                                          \
        const int bIdx = p0 / HW, prow0 = p0 % HW;                             \
        _Pragma("unroll")                                                      \
        for (int mt = 0; mt < 4; mt++) {                                       \
            const int oca = mt * 16 + g;                                       \
            const int ocb = oca + 8;                                           \
            const float ba = (oca < Cout) ? bias[oca] : 0.f;                   \
            const float bb = (ocb < Cout) ? bias[ocb] : 0.f;                   \
            _Pragma("unroll")                                                  \
            for (int nt = 0; nt < 4; nt++) {                                   \
                const int pc = prow0 + wn * 32 + nt * 8 + 2 * t;               \
                if (oca < Cout) {                                              \
                    float2 v = make_float2(acc[mt][nt][0] + ba, acc[mt][nt][1] + ba); \
                    *(float2*)&out[((long)bIdx * ocStride + oca) * HW + pc] = v; \
                }                                                              \
                if (ocb < Cout) {                                              \
                    float2 v = make_float2(acc[mt][nt][2] + bb, acc[mt][nt][3] + bb); \
                    *(float2*)&out[((long)bIdx * ocStride + ocb) * HW + pc] = v; \
                }                                                              \
            }                                                                  \
        }                                                                      \
    }

#define EPI_XT_64()                                                            \
    {                                                                          \
        float* sf = (float*)sm;                                                \
        _Pragma("unroll")                                                      \
        for (int mt = 0; mt < 4; mt++) {                                       \
            const int ra = mt * 16 + g;                                        \
            const float ba = bias[ra];                                         \
            const float bb = bias[ra + 8];                                     \
            _Pragma("unroll")                                                  \
            for (int nt = 0; nt < 4; nt++) {                                   \
                const int pc = wn * 32 + nt * 8 + 2 * t;                       \
                sf[ra * 261 + pc]           = acc[mt][nt][0] + ba;             \
                sf[ra * 261 + pc + 1]       = acc[mt][nt][1] + ba;             \
                sf[(ra + 8) * 261 + pc]     = acc[mt][nt][2] + bb;             \
                sf[(ra + 8) * 261 + pc + 1] = acc[mt][nt][3] + bb;             \
            }                                                                  \
        }                                                                      \
        __syncthreads();                                                       \
        for (int e = tid; e < 8192; e += 256) {                                \
            const int cp = e & 31, px = e >> 5;                                \
            xtH[(long)(p0 + px) * xtCph + xtCpOff + cp] =                      \
                pack_h2(sf[(2 * cp) * 261 + px], sf[(2 * cp + 1) * 261 + px]); \
        }                                                                      \
    }

// 3-stage loop skeleton
#define PIPE3_LOOP(STAGEFN, ADVANCE, MMAEXP)                                   \
    STAGEFN(0);                                                                \
    CP_COMMIT();                                                               \
    ADVANCE;                                                                   \
    if (nchunks > 1) { STAGEFN(1); }                                           \
    CP_COMMIT();                                                               \
    ADVANCE;                                                                   \
    for (int ci = 0; ci < nchunks; ci++) {                                     \
        CP_WAIT(1);                                                            \
        __syncthreads();                                                       \
        if (ci + 2 < nchunks) { STAGEFN((ci + 2) % 3); ADVANCE; }              \
        CP_COMMIT();                                                           \
        const uint32_t stg = smb + (uint32_t)(ci % 3) * stageBytes;            \
        MMAEXP                                                                 \
    }                                                                          \
    __syncthreads();

// ---------------------------------------------------------------------------
// gemm_tap: M128 x N128, implicit-tap B staging from compact Xt[n][Cp]
// ---------------------------------------------------------------------------
__global__ void __launch_bounds__(256, 2)
gemm_tap(const __half* __restrict__ Ahi, const __half* __restrict__ Alo,
         const uint32_t* __restrict__ Xh,
         const float* __restrict__ bias, float* __restrict__ out,
         int Kp, int Cp, int nchunks, int Cout, int ocStride, int H, int W,
         uint32_t* xtH, int xtCph, int xtCpOff)
{
    extern __shared__ __half sm[];
    const uint32_t stageBytes = STG3_B;

    const int tid = threadIdx.x, wid = tid >> 5, lane = tid & 31;
    const int g = lane >> 2, t = lane & 3;
    const int wm = wid >> 2, wn = wid & 3;
    const int HW = H * W;

    const int p0 = blockIdx.x * 128;
    const int m0 = blockIdx.y * 128;

    float acc[4][4][4];
#pragma unroll
    for (int i = 0; i < 4; i++)
#pragma unroll
        for (int j = 0; j < 4; j++)
#pragma unroll
            for (int k = 0; k < 4; k++) acc[i][j][k] = 0.f;

    const uint32_t smb = smem_u32(sm);
    const int r0 = tid >> 2, s0 = tid & 3;
    const int r1 = r0 + 64;

    int b0r, y0r, x0r, b1r, y1r, x1r;
    {
        int n = p0 + r0; b0r = n / HW; int p = n - b0r * HW; y0r = p / W; x0r = p - y0r * W;
        n = p0 + r1; b1r = n / HW; p = n - b1r * HW; y1r = p / W; x1r = p - y1r * W;
    }

    uint32_t aoff[4], boff[2];
    {
        const int arow = (lane & 7) + ((lane >> 3) & 1) * 8;
        const int acol = (lane >> 4) * 8;
#pragma unroll
        for (int mt = 0; mt < 4; mt++)
            aoff[mt] = (uint32_t)(((wm * 64 + mt * 16 + arow) * LROW + acol) * 2);
        const int brow = (lane & 7) + (lane >> 4) * 8;
        const int bcol = ((lane >> 3) & 1) * 8;
#pragma unroll
        for (int np = 0; np < 2; np++)
            boff[np] = (uint32_t)(((wn * 32 + np * 16 + brow) * LROW + bcol) * 2);
    }

    const char* XhB = (const char*)Xh;
    const long rowB = (long)Cp * 2;

    int tP = 0, kinP = 0;
    auto stage = [&](int buf) {
        const long kc = (long)tP * Cp + kinP;
        const uint32_t bufb = smb + (uint32_t)buf * STG3_B;
        CP16(bufb + r0 * 80 + s0 * 16, Ahi + (long)(m0 + r0) * Kp + kc + s0 * 8);
        CP16(bufb + r1 * 80 + s0 * 16, Ahi + (long)(m0 + r1) * Kp + kc + s0 * 8);
        CP16(bufb + PLANE_B + r0 * 80 + s0 * 16, Alo + (long)(m0 + r0) * Kp + kc + s0 * 8);
        CP16(bufb + PLANE_B + r1 * 80 + s0 * 16, Alo + (long)(m0 + r1) * Kp + kc + s0 * 8);
        const int q = tP / 3;
        const int dy = q - 1, dx = tP - 3 * q - 1;
        const long cb = (long)kinP * 2;
        {
            const int yy = y0r + dy, xx = x0r + dx;
            const uint32_t dH = bufb + 2 * PLANE_B + r0 * 80 + s0 * 16;
            if ((unsigned)yy < (unsigned)H && (unsigned)xx < (unsigned)W)
                CP16(dH, XhB + ((long)b0r * HW + yy * W + xx) * rowB + cb + s0 * 16);
            else ZSTS16(dH);
        }
        {
            const int yy = y1r + dy, xx = x1r + dx;
            const uint32_t dH = bufb + 2 * PLANE_B + r1 * 80 + s0 * 16;
            if ((unsigned)yy < (unsigned)H && (unsigned)xx < (unsigned)W)
                CP16(dH, XhB + ((long)b1r * HW + yy * W + xx) * rowB + cb + s0 * 16);
            else ZSTS16(dH);
        }
    };

#define ADV { kinP += 32; if (kinP == Cp) { kinP = 0; tP++; } }
    PIPE3_LOOP(stage, ADV, MMA_BODY2(stg, PLANE_B, stg + 2 * PLANE_B))
#undef ADV

    if (xtH) EPI_XT_128()
    else     EPI_FP32_128()
}

// ---------------------------------------------------------------------------
// gemm_tap64: M64 x N256, implicit-tap B staging (Cout <= 64)
// ---------------------------------------------------------------------------
__global__ void __launch_bounds__(256, 2)
gemm_tap64(const __half* __restrict__ Ahi, const __half* __restrict__ Alo,
           const uint32_t* __restrict__ Xh,
           const float* __restrict__ bias, float* __restrict__ out,
           int Kp, int Cp, int nchunks, int Cout, int ocStride, int H, int W,
           uint32_t* xtH, int xtCph, int xtCpOff)
{
    extern __shared__ __half sm[];
    const uint32_t stageBytes = STG64_B;

    const int tid = threadIdx.x, wid = tid >> 5, lane = tid & 31;
    const int g = lane >> 2, t = lane & 3;
    const int wn = wid;
    const int HW = H * W;

    const int p0 = blockIdx.x * 256;

    float acc[4][4][4];
#pragma unroll
    for (int i = 0; i < 4; i++)
#pragma unroll
        for (int j = 0; j < 4; j++)
#pragma unroll
            for (int k = 0; k < 4; k++) acc[i][j][k] = 0.f;

    const uint32_t smb = smem_u32(sm);
    const int rA = tid >> 2, sA = tid & 3;

    int b4[4], y4[4], x4[4];
#pragma unroll
    for (int j = 0; j < 4; j++) {
        int n = p0 + rA + 64 * j;
        b4[j] = n / HW;
        int p = n - b4[j] * HW;
        y4[j] = p / W;
        x4[j] = p - y4[j] * W;
    }

    uint32_t aoff[4], boff[2];
    {
        const int arow = (lane & 7) + ((lane >> 3) & 1) * 8;
        const int acol = (lane >> 4) * 8;
#pragma unroll
        for (int mt = 0; mt < 4; mt++)
            aoff[mt] = (uint32_t)(((mt * 16 + arow) * LROW + acol) * 2);
        const int brow = (lane & 7) + (lane >> 4) * 8;
        const int bcol = ((lane >> 3) & 1) * 8;
#pragma unroll
        for (int np = 0; np < 2; np++)
            boff[np] = (uint32_t)(((wn * 32 + np * 16 + brow) * LROW + bcol) * 2);
    }

    const char* XhB = (const char*)Xh;
    const long rowB = (long)Cp * 2;

    int tP = 0, kinP = 0;
    auto stage = [&](int buf) {
        const long kc = (long)tP * Cp + kinP;
        const uint32_t bufb = smb + (uint32_t)buf * STG64_B;
        CP16(bufb + rA * 80 + sA * 16, Ahi + (long)rA * Kp + kc + sA * 8);
        CP16(bufb + APL64_B + rA * 80 + sA * 16, Alo + (long)rA * Kp + kc + sA * 8);
        const int q = tP / 3;
        const int dy = q - 1, dx = tP - 3 * q - 1;
        const long cb = (long)kinP * 2;
        const uint32_t bB = bufb + 2 * APL64_B;
#pragma unroll
        for (int j = 0; j < 4; j++) {
            const int r = rA + 64 * j;
            const int yy = y4[j] + dy, xx = x4[j] + dx;
            const uint32_t dH = bB + r * 80 + sA * 16;
            if ((unsigned)yy < (unsigned)H && (unsigned)xx < (unsigned)W)
                CP16(dH, XhB + ((long)b4[j] * HW + yy * W + xx) * rowB + cb + sA * 16);
            else ZSTS16(dH);
        }
    };

#define ADV { kinP += 32; if (kinP == Cp) { kinP = 0; tP++; } }
    PIPE3_LOOP(stage, ADV, MMA_BODY2(stg, APL64_B, stg + 2 * APL64_B))
#undef ADV

    if (xtH) EPI_XT_64()
    else     EPI_FP32_64()
}

// ---------------------------------------------------------------------------
// gemm_mma / gemm_mma64: direct-B (DCN GEMMs), B hi only
// ---------------------------------------------------------------------------
__global__ void __launch_bounds__(256, 2)
gemm_mma(const __half* __restrict__ Ahi, const __half* __restrict__ Alo,
         const __half* __restrict__ Bhi,
         const float* __restrict__ bias, float* __restrict__ out,
         int Kp, int nchunks, int Cout, int ocStride, int HW,
         uint32_t* xtH, int xtCph, int xtCpOff)
{
    extern __shared__ __half sm[];
    const uint32_t stageBytes = STG3_B;

    const int tid = threadIdx.x, wid = tid >> 5, lane = tid & 31;
    const int g = lane >> 2, t = lane & 3;
    const int wm = wid >> 2, wn = wid & 3;

    const int p0 = blockIdx.x * 128;
    const int m0 = blockIdx.y * 128;

    float acc[4][4][4];
#pragma unroll
    for (int i = 0; i < 4; i++)
#pragma unroll
        for (int j = 0; j < 4; j++)
#pragma unroll
            for (int k = 0; k < 4; k++) acc[i][j][k] = 0.f;

    const uint32_t smb = smem_u32(sm);
    const int r0 = tid >> 2, s0 = tid & 3;
    const int r1 = r0 + 64;

    uint32_t aoff[4], boff[2];
    {
        const int arow = (lane & 7) + ((lane >> 3) & 1) * 8;
        const int acol = (lane >> 4) * 8;
#pragma unroll
        for (int mt = 0; mt < 4; mt++)
            aoff[mt] = (uint32_t)(((wm * 64 + mt * 16 + arow) * LROW + acol) * 2);
        const int brow = (lane & 7) + (lane >> 4) * 8;
        const int bcol = ((lane >> 3) & 1) * 8;
#pragma unroll
        for (int np = 0; np < 2; np++)
            boff[np] = (uint32_t)(((wn * 32 + np * 16 + brow) * LROW + bcol) * 2);
    }

    int ciP = 0;
    auto stage = [&](int buf) {
        const long kc = (long)ciP * 32;
        const uint32_t bufb = smb + (uint32_t)buf * STG3_B;
        CP16(bufb + r0 * 80 + s0 * 16, Ahi + (long)(m0 + r0) * Kp + kc + s0 * 8);
        CP16(bufb + r1 * 80 + s0 * 16, Ahi + (long)(m0 + r1) * Kp + kc + s0 * 8);
        CP16(bufb + PLANE_B + r0 * 80 + s0 * 16, Alo + (long)(m0 + r0) * Kp + kc + s0 * 8);
        CP16(bufb + PLANE_B + r1 * 80 + s0 * 16, Alo + (long)(m0 + r1) * Kp + kc + s0 * 8);
        CP16(bufb + 2 * PLANE_B + r0 * 80 + s0 * 16, Bhi + (long)(p0 + r0) * Kp + kc + s0 * 8);
        CP16(bufb + 2 * PLANE_B + r1 * 80 + s0 * 16, Bhi + (long)(p0 + r1) * Kp + kc + s0 * 8);
    };

#define ADV { ciP++; }
    PIPE3_LOOP(stage, ADV, MMA_BODY2(stg, PLANE_B, stg + 2 * PLANE_B))
#undef ADV

    if (xtH) EPI_XT_128()
    else     EPI_FP32_128()
}

__global__ void __launch_bounds__(256, 2)
gemm_mma64(const __half* __restrict__ Ahi, const __half* __restrict__ Alo,
           const __half* __restrict__ Bhi,
           const float* __restrict__ bias, float* __restrict__ out,
           int Kp, int nchunks, int Cout, int ocStride, int HW,
           uint32_t* xtH, int xtCph, int xtCpOff)
{
    extern __shared__ __half sm[];
    const uint32_t stageBytes = STG64_B;

    const int tid = threadIdx.x, wid = tid >> 5, lane = tid & 31;
    const int g = lane >> 2, t = lane & 3;
    const int wn = wid;

    const int p0 = blockIdx.x * 256;

    float acc[4][4][4];
#pragma unroll
    for (int i = 0; i < 4; i++)
#pragma unroll
        for (int j = 0; j < 4; j++)
#pragma unroll
            for (int k = 0; k < 4; k++) acc[i][j][k] = 0.f;

    const uint32_t smb = smem_u32(sm);
    const int rA = tid >> 2, sA = tid & 3;

    uint32_t aoff[4], boff[2];
    {
        const int arow = (lane & 7) + ((lane >> 3) & 1) * 8;
        const int acol = (lane >> 4) * 8;
#pragma unroll
        for (int mt = 0; mt < 4; mt++)
            aoff[mt] = (uint32_t)(((mt * 16 + arow) * LROW + acol) * 2);
        const int brow = (lane & 7) + (lane >> 4) * 8;
        const int bcol = ((lane >> 3) & 1) * 8;
#pragma unroll
        for (int np = 0; np < 2; np++)
            boff[np] = (uint32_t)(((wn * 32 + np * 16 + brow) * LROW + bcol) * 2);
    }

    int ciP = 0;
    auto stage = [&](int buf) {
        const long kc = (long)ciP * 32;
        const uint32_t bufb = smb + (uint32_t)buf * STG64_B;
        CP16(bufb + rA * 80 + sA * 16, Ahi + (long)rA * Kp + kc + sA * 8);
        CP16(bufb + APL64_B + rA * 80 + sA * 16, Alo + (long)rA * Kp + kc + sA * 8);
        const uint32_t bB = bufb + 2 * APL64_B;
#pragma unroll
        for (int j = 0; j < 4; j++) {
            const int task = tid + 256 * j;
            const int r = task >> 2, s = task & 3;
            CP16(bB + r * 80 + s * 16, Bhi + (long)(p0 + r) * Kp + kc + s * 8);
        }
    };

#define ADV { ciP++; }
    PIPE3_LOOP(stage, ADV, MMA_BODY2(stg, APL64_B, stg + 2 * APL64_B))
#undef ADV

    if (xtH) EPI_XT_64()
    else     EPI_FP32_64()
}

// ---------------------------------------------------------------------------
// DCN bilinear sampler (fp16 hi only)
// ---------------------------------------------------------------------------
__global__ void dcn_sample_bf(const float* __restrict__ x, long xbs,
                              const float* __restrict__ om,
                              uint4* __restrict__ Bh4,
                              int C, int H, int W, int total)
{
    int idx = blockIdx.x * blockDim.x + threadIdx.x;
    if (idx >= total) return;
    const int HW = H * W;
    const int p = idx % HW;
    const int k = (idx / HW) % 9;
    const int g = (idx / (HW * 9)) % 8;
    const int b = idx / (HW * 72);
    const int y = p / W, xq = p % W;

    const long omb = (long)b * 216 * HW + (long)(g * 9 + k) * HW + p;
    float dy = om[omb];
    float dx = om[omb + 72L * HW];
    float mk = om[omb + 144L * HW];
    mk = 1.f / (1.f + expf(-mk));

    float pyf = (float)y + (float)(k / 3 - 1) + dy;
    float pxf = (float)xq + (float)(k % 3 - 1) + dx;
    float y0f = floorf(pyf), x0f = floorf(pxf);
    int y0 = (int)y0f, x0i = (int)x0f;
    float ty = pyf - y0f, tx = pxf - x0f;
    int y1 = y0 + 1, x1i = x0i + 1;

    bool vy0 = (y0 >= 0) && (y0 < H), vy1 = (y1 >= 0) && (y1 < H);
    bool vx0 = (x0i >= 0) && (x0i < W), vx1 = (x1i >= 0) && (x1i < W);
    float w00 = (vy0 && vx0) ? (1.f - ty) * (1.f - tx) : 0.f;
    float w01 = (vy0 && vx1) ? (1.f - ty) * tx : 0.f;
    float w10 = (vy1 && vx0) ? ty * (1.f - tx) : 0.f;
    float w11 = (vy1 && vx1) ? ty * tx : 0.f;
    w00 *= mk; w01 *= mk; w10 *= mk; w11 *= mk;

    int cy0 = min(max(y0, 0), H - 1), cy1 = min(max(y1, 0), H - 1);
    int cx0 = min(max(x0i, 0), W - 1), cx1 = min(max(x1i, 0), W - 1);
    int i00 = cy0 * W + cx0, i01 = cy0 * W + cx1;
    int i10 = cy1 * W + cx0, i11 = cy1 * W + cx1;

    const int Cg = C >> 3;
    const int K = C * 9;
    const float* xb = x + (long)b * xbs + (long)g * Cg * HW;
    const long rowbase = ((long)b * HW + p) * K + (long)k * C + (long)g * Cg;
    const long o4 = rowbase >> 3;

    for (int cb = 0; cb < Cg; cb += 8) {
        uint32_t hv[4];
#pragma unroll
        for (int j = 0; j < 4; j++) {
            const float* xc0 = xb + (long)(cb + 2 * j) * HW;
            const float* xc1 = xc0 + HW;
            float v0 = w00 * xc0[i00] + w01 * xc0[i01] + w10 * xc0[i10] + w11 * xc0[i11];
            float v1 = w00 * xc1[i00] + w01 * xc1[i01] + w10 * xc1[i10] + w11 * xc1[i11];
            hv[j] = pack_h2(v0, v1);
        }
        Bh4[o4 + (cb >> 3)] = make_uint4(hv[0], hv[1], hv[2], hv[3]);
    }
}

// ---------------------------------------------------------------------------
extern "C" void kernel_launch(void* const* d_in, const int* in_sizes, int n_in,
                              void* d_out, int out_size)
{
    const float *x0 = nullptr, *x1 = nullptr, *x2 = nullptr;
    const float *flow0 = nullptr, *flow1 = nullptr, *flow2 = nullptr;
    for (int i = 0; i < 6; i++) {
        const float* p = (const float*)d_in[i];
        switch (in_sizes[i]) {
            case 4 * 2 * 64 * 128 * 128: x0 = p; break;
            case 4 * 2 * 128 * 64 * 64:  x1 = p; break;
            case 4 * 2 * 256 * 32 * 32:  x2 = p; break;
            case 4 * 2 * 128 * 128:      flow0 = p; break;
            case 4 * 2 * 64 * 64:        flow1 = p; break;
            case 4 * 2 * 32 * 32:        flow2 = p; break;
        }
    }
    const float* off_w0 = (const float*)d_in[6];  const float* off_b0 = (const float*)d_in[7];
    const float* co_w0  = (const float*)d_in[8];  const float* co_b0  = (const float*)d_in[9];
    const float* dcn_w0 = (const float*)d_in[10]; const float* dcn_b0 = (const float*)d_in[11];
    const float* off_w1 = (const float*)d_in[12]; const float* off_b1 = (const float*)d_in[13];
    const float* co_w1  = (const float*)d_in[14]; const float* co_b1  = (const float*)d_in[15];
    const float* dcn_w1 = (const float*)d_in[16]; const float* dcn_b1 = (const float*)d_in[17];
    const float* off_w2 = (const float*)d_in[18]; const float* off_b2 = (const float*)d_in[19];
    const float* co_w2  = (const float*)d_in[20]; const float* co_b2  = (const float*)d_in[21];
    const float* dcn_w2 = (const float*)d_in[22]; const float* dcn_b2 = (const float*)d_in[23];
    const float* ch_w0  = (const float*)d_in[24]; const float* ch_b0  = (const float*)d_in[25];
    const float* ft_w0  = (const float*)d_in[26]; const float* ft_b0  = (const float*)d_in[27];
    const float* ch_w1  = (const float*)d_in[28]; const float* ch_b1  = (const float*)d_in[29];
    const float* ft_w1  = (const float*)d_in[30]; const float* ft_b1  = (const float*)d_in[31];

    uint32_t* XH;
    __half *Ah, *Al;
    float *om0, *om1, *om2;
    cudaGetSymbolAddress((void**)&XH, g_XH);
    cudaGetSymbolAddress((void**)&Ah, g_Ah);
    cudaGetSymbolAddress((void**)&Al, g_Al);
    cudaGetSymbolAddress((void**)&om0, g_om0);
    cudaGetSymbolAddress((void**)&om1, g_om1);
    cudaGetSymbolAddress((void**)&om2, g_om2);

    cudaFuncSetAttribute(gemm_tap,   cudaFuncAttributeMaxDynamicSharedMemorySize, GEMM_SMEM);
    cudaFuncSetAttribute(gemm_tap64, cudaFuncAttributeMaxDynamicSharedMemorySize, GEMM64_SMEM);
    cudaFuncSetAttribute(gemm_mma,   cudaFuncAttributeMaxDynamicSharedMemorySize, GEMM_SMEM);
    cudaFuncSetAttribute(gemm_mma64, cudaFuncAttributeMaxDynamicSharedMemorySize, GEMM64_SMEM);

    float* out0 = (float*)d_out;
    float* out1 = out0 + 4L * 64 * 128 * 128;
    float* out2 = out1 + 4L * 128 * 64 * 64;

    const int B = 4;
    cudaStream_t S0 = 0, S1 = g_s.s1, S2 = g_s.s2;

    auto XPOSE = [&](cudaStream_t st, long off, const float* s1, int c1, long bs1,
                     const float* s2, int c2, long bs2, int H, int W, int Cph) {
        dim3 grid((Cph + 31) / 32, (B * H * W) / 64);
        xpose<<<grid, 256, 0, st>>>(s1, c1, bs1, s2, c2, bs2, H, W, Cph, XH + off);
    };
    auto UP2XT = [&](cudaStream_t st, long off, const float* src, int C,
                     int Hs, int Ws) {
        int Cph = C / 2;
        dim3 grid(Cph / 32, (B * 4 * Hs * Ws) / 64);
        up2_xt<<<grid, 256, 0, st>>>(src, C, Hs, Ws, Cph, XH + off);
    };
    auto GTAP = [&](cudaStream_t st, int slot, long off, const float* bias, float* out,
                    int Kp, int Cp, int Cout, int ocStride, int H, int W, int Mtiles,
                    long xtOff = -1, int xtCph = 0, int xtCpOff = 0) {
        dim3 grid((B * H * W) / 128, Mtiles);
        gemm_tap<<<grid, 256, GEMM_SMEM, st>>>(
            Ah + (long)slot * ASLOT, Al + (long)slot * ASLOT, XH + off,
            bias, out, Kp, Cp, Kp / 32, Cout, ocStride, H, W,
            xtOff >= 0 ? XH + xtOff : nullptr, xtCph, xtCpOff);
    };
    auto GTAP64 = [&](cudaStream_t st, int slot, long off, const float* bias, float* out,
                      int Kp, int Cp, int Cout, int ocStride, int H, int W,
                      long xtOff = -1, int xtCph = 0, int xtCpOff = 0) {
        dim3 grid((B * H * W) / 256);
        gemm_tap64<<<grid, 256, GEMM64_SMEM, st>>>(
            Ah + (long)slot * ASLOT, Al + (long)slot * ASLOT, XH + off,
            bias, out, Kp, Cp, Kp / 32, Cout, ocStride, H, W,
            xtOff >= 0 ? XH + xtOff : nullptr, xtCph, xtCpOff);
    };
    auto GOLD = [&](cudaStream_t st, int slot, long off, const float* bias, float* out,
                    int Kp, int Cout, int ocStride, int HW, int Mtiles,
                    long xtOff = -1, int xtCph = 0, int xtCpOff = 0) {
        dim3 grid((B * HW) / 128, Mtiles);
        gemm_mma<<<grid, 256, GEMM_SMEM, st>>>(
            Ah + (long)slot * ASLOT, Al + (long)slot * ASLOT,
            (const __half*)(XH + off),
            bias, out, Kp, Kp / 32, Cout, ocStride, HW,
            xtOff >= 0 ? XH + xtOff : nullptr, xtCph, xtCpOff);
    };
    auto GOLD64 = [&](cudaStream_t st, int slot, long off, const float* bias, float* out,
                      int Kp, int Cout, int ocStride, int HW,
                      long xtOff = -1, int xtCph = 0, int xtCpOff = 0) {
        dim3 grid((B * HW) / 256);
        gemm_mma64<<<grid, 256, GEMM64_SMEM, st>>>(
            Ah + (long)slot * ASLOT, Al + (long)slot * ASLOT,
            (const __half*)(XH + off),
            bias, out, Kp, Kp / 32, Cout, ocStride, HW,
            xtOff >= 0 ? XH + xtOff : nullptr, xtCph, xtCpOff);
    };
    auto DCN = [&](cudaStream_t st, long off, const float* x, long xbs, const float* om,
                   int C, int H, int W) {
        int total = B * 72 * H * W;
        dcn_sample_bf<<<(total + 255) / 256, 256, 0, st>>>(
            x, xbs, om, (uint4*)(XH + off), C, H, W, total);
    };

    // ---- all weight conversions in ONE launch ----
    {
        WJobs jobs;
        auto J = [&](int i, const float* w, int M, int Cin, int Cp, int Kp, int Mp) {
            jobs.j[i] = WJob{w, (uint32_t*)(Ah + (long)i * ASLOT),
                             (uint32_t*)(Al + (long)i * ASLOT),
                             M, Cin, Cp, Kp, Mp * (Kp >> 1)};
        };
        J(0,  off_w2, 256, 514, 544, 4896, 256);
        J(1,  co_w2,  216, 256, 256, 2304, 256);
        J(2,  dcn_w2, 256, 256, 256, 2304, 256);
        J(3,  off_w1, 128, 258, 288, 2592, 128);
        J(4,  co_w1,  216, 128, 128, 1152, 256);
        J(5,  dcn_w1, 128, 128, 128, 1152, 128);
        J(6,  off_w0, 64,  130, 160, 1440, 64);
        J(7,  co_w0,  216, 64,  64,  576,  256);
        J(8,  dcn_w0, 64,  64,  64,  576,  64);
        J(9,  ch_w1,  128, 256, 256, 2304, 128);
        J(10, ft_w1,  128, 256, 256, 2304, 128);
        J(11, ch_w0,  64,  128, 128, 1152, 64);
        J(12, ft_w0,  64,  128, 128, 1152, 64);
        int maxBlocks = (256 * (4896 >> 1) + 255) / 256;
        wconv_all<<<dim3(maxBlocks, 13), 256, 0, S0>>>(jobs);
    }

    // ---- fork ----
    cudaEventRecord(g_s.eF, S0);
    cudaStreamWaitEvent(S1, g_s.eF, 0);
    cudaStreamWaitEvent(S2, g_s.eF, 0);

    // ---- s1: level 0 off/co/dcn chain (128x128) ----
    {
        const int H = 128, W = 128, HW = H * W;
        XPOSE(S1, O_XT0A, x0, 128, 128L * HW, flow0, 2, 2L * HW, H, W, 80);
        GTAP64(S1, 6, O_XT0A, off_b0, nullptr, 1440, 160, 64, 64, H, W,
               O_XT0B, 32, 0);
        GTAP(S1, 7, O_XT0B, co_b0, om0, 576, 64, 216, 216, H, W, 2);
        DCN(S1, O_SAMP0, x0 + 64L * HW, 128L * HW, om0, 64, H, W);
        GOLD64(S1, 8, O_SAMP0, dcn_b0, nullptr, 576, 64, 128, HW,
               O_XTF0, 64, 0);
        cudaEventRecord(g_s.eL0, S1);
    }

    // ---- s2: level 1 off/co/dcn chain (64x64) ----
    {
        const int H = 64, W = 64, HW = H * W;
        XPOSE(S2, O_XT1A, x1, 256, 256L * HW, flow1, 2, 2L * HW, H, W, 144);
        GTAP(S2, 3, O_XT1A, off_b1, nullptr, 2592, 288, 128, 128, H, W, 1,
             O_XT1B, 64, 0);
        GTAP(S2, 4, O_XT1B, co_b1, om1, 1152, 128, 216, 216, H, W, 2);
        DCN(S2, O_SAMP1, x1 + 128L * HW, 256L * HW, om1, 128, H, W);
        GOLD(S2, 5, O_SAMP1, dcn_b1, nullptr, 1152, 128, 256, HW, 1,
             O_XTF1, 128, 0);
        cudaEventRecord(g_s.eL1, S2);
    }

    // ---- origin: level 2 chain (32x32) + fusion cascade ----
    {
        const int H = 32, W = 32, HW = H * W;
        XPOSE(S0, O_XT2A, x2, 512, 512L * HW, flow2, 2, 2L * HW, H, W, 272);
        GTAP(S0, 0, O_XT2A, off_b2, nullptr, 4896, 544, 256, 256, H, W, 2,
             O_XT2B, 128, 0);
        GTAP(S0, 1, O_XT2B, co_b2, om2, 2304, 256, 216, 216, H, W, 2);
        DCN(S0, O_SAMP2, x2 + 256L * HW, 512L * HW, om2, 256, H, W);
        GOLD(S0, 2, O_SAMP2, dcn_b2, out2, 2304, 256, 256, HW, 2);
        UP2XT(S0, O_XTU1, out2, 256, H, W);
    }
    {   // level 1 fusion (64x64)
        const int H = 64, W = 64, HW = H * W;
        GTAP(S0, 9, O_XTU1, ch_b1, nullptr, 2304, 256, 128, 256, H, W, 1,
             O_XTF1, 128, 64);
        cudaStreamWaitEvent(S0, g_s.eL1, 0);
        GTAP(S0, 10, O_XTF1, ft_b1, out1, 2304, 256, 128, 128, H, W, 1);
        UP2XT(S0, O_XTU0, out1, 128, H, W);
    }
    {   // level 0 fusion (128x128)
        const int H = 128, W = 128, HW = H * W;
        GTAP64(S0, 11, O_XTU0, ch_b0, nullptr, 1152, 128, 64, 128, H, W,
               O_XTF0, 64, 32);
        cudaStreamWaitEvent(S0, g_s.eL0, 0);
        GTAP64(S0, 12, O_XTF0, ft_b0, out0, 1152, 128, 64, 64, H, W);
    }
}

// round 15
// speedup vs baseline: 3.6762x; 1.3340x over previous
#include <cuda_runtime.h>
#include <cuda_fp16.h>
#include <math.h>
#include <stdint.h>

// ===========================================================================
// MotionCompensationBlock — HMMA fp16 (A hi · B hi), implicit-tap GEMM
// Round 15: drop A-lo plane too (1 MMA/frag), 3-stage 2-plane pipeline
// ===========================================================================

__device__ __forceinline__ uint32_t smem_u32(const void* p) {
    uint32_t a;
    asm("{ .reg .u64 t; cvta.to.shared.u64 t, %1; cvt.u32.u64 %0, t; }" : "=r"(a) : "l"(p));
    return a;
}

#define CP16(dst, src) \
    asm volatile("cp.async.cg.shared.global [%0], [%1], 16;" :: "r"(dst), "l"(src) : "memory")
#define CP_COMMIT() asm volatile("cp.async.commit_group;" ::: "memory")
#define CP_WAIT(n)  asm volatile("cp.async.wait_group %0;" :: "n"(n) : "memory")
#define ZSTS16(addr) \
    asm volatile("st.shared.v4.b32 [%0], {%1,%1,%1,%1};" :: "r"(addr), "r"(0u) : "memory")

#define LDSM4(r, addr) \
    asm volatile("ldmatrix.sync.aligned.m8n8.x4.shared.b16 {%0,%1,%2,%3}, [%4];" \
                 : "=r"((r)[0]), "=r"((r)[1]), "=r"((r)[2]), "=r"((r)[3]) : "r"(addr))

__device__ __forceinline__ void mma16816(float* c, const uint32_t* a,
                                         uint32_t b0, uint32_t b1) {
    asm volatile(
        "mma.sync.aligned.m16n8k16.row.col.f32.f16.f16.f32 "
        "{%0,%1,%2,%3}, {%4,%5,%6,%7}, {%8,%9}, {%0,%1,%2,%3};"
        : "+f"(c[0]), "+f"(c[1]), "+f"(c[2]), "+f"(c[3])
        : "r"(a[0]), "r"(a[1]), "r"(a[2]), "r"(a[3]), "r"(b0), "r"(b1));
}

__device__ __forceinline__ uint32_t pack_h2(float v0, float v1) {
    __half2 hp = __halves2half2(__float2half(v0), __float2half(v1));
    return *(uint32_t*)&hp;
}

// ------------------------------ pools --------------------------------------
#define POOL_U32 (68u << 20)
__device__ uint32_t g_XH[POOL_U32];
#define O_XT0A  (0L)
#define O_XT0B  (6L  << 20)
#define O_SAMP0 (9L  << 20)
#define O_XT1A  (28L << 20)
#define O_XT1B  (31L << 20)
#define O_SAMP1 (33L << 20)
#define O_XT2A  (43L << 20)
#define O_XT2B  (45L << 20)
#define O_SAMP2 (46L << 20)
#define O_XTU1  (51L << 20)
#define O_XTF1  (54L << 20)
#define O_XTU0  (57L << 20)
#define O_XTF0  (62L << 20)

#define ASLOT 1253376
__device__ __half g_Ah[13L * ASLOT];
__device__ float g_om0[14155776], g_om1[3538944], g_om2[884736];

// ------------------------------ streams ------------------------------------
struct MCStreams {
    cudaStream_t s1, s2;
    cudaEvent_t eF, eL0, eL1;
    MCStreams() {
        cudaStreamCreateWithFlags(&s1, cudaStreamNonBlocking);
        cudaStreamCreateWithFlags(&s2, cudaStreamNonBlocking);
        cudaEventCreateWithFlags(&eF,  cudaEventDisableTiming);
        cudaEventCreateWithFlags(&eL0, cudaEventDisableTiming);
        cudaEventCreateWithFlags(&eL1, cudaEventDisableTiming);
    }
};
static MCStreams g_s;

// ---------------------------------------------------------------------------
// xpose: NCHW fp32 (dual-source concat) -> Xt[n][c] fp16 pairs
// ---------------------------------------------------------------------------
__global__ void __launch_bounds__(256)
xpose(const float* __restrict__ s1, int c1, long bs1,
      const float* __restrict__ s2, int c2, long bs2,
      int H, int W, int Cph, uint32_t* __restrict__ Xh)
{
    __shared__ uint32_t sh[32][65];
    __shared__ int sp_b[64], sp_p[64];

    const int tid = threadIdx.x;
    const int cc0 = blockIdx.x * 32;
    const long n0 = (long)blockIdx.y * 64;
    const int HW = H * W;

    if (tid < 64) {
        long n = n0 + tid;
        int b = (int)(n / HW);
        sp_b[tid] = b;
        sp_p[tid] = (int)(n - (long)b * HW);
    }
    __syncthreads();

    const int Cin = c1 + c2;
#pragma unroll
    for (int e = tid; e < 2048; e += 256) {
        const int p = e & 63, cc = e >> 6;
        const int c = (cc0 + cc) * 2;
        float v0 = 0.f, v1 = 0.f;
        const int b = sp_b[p];
        const int sp = sp_p[p];
        if (c < c1)          v0 = s1[(long)b * bs1 + (long)c * HW + sp];
        else if (c < Cin)    v0 = s2[(long)b * bs2 + (long)(c - c1) * HW + sp];
        const int cn = c + 1;
        if (cn < c1)         v1 = s1[(long)b * bs1 + (long)cn * HW + sp];
        else if (cn < Cin)   v1 = s2[(long)b * bs2 + (long)(cn - c1) * HW + sp];
        sh[cc][p] = pack_h2(v0, v1);
    }
    __syncthreads();

#pragma unroll
    for (int e = tid; e < 2048; e += 256) {
        const int kk = e & 31, p = e >> 5;
        if (cc0 + kk < Cph)
            Xh[(n0 + p) * Cph + cc0 + kk] = sh[kk][p];
    }
}

// ---------------------------------------------------------------------------
// up2_xt: fused bilinear 2x upsample + transpose to Xt[n][c] fp16
// ---------------------------------------------------------------------------
__global__ void __launch_bounds__(256)
up2_xt(const float* __restrict__ src, int C, int Hs, int Ws, int Cph,
       uint32_t* __restrict__ Xh)
{
    __shared__ uint32_t sh[32][65];
    __shared__ int sb[64], si0[64], si1[64], si2[64], si3[64];
    __shared__ float swy[64], swx[64];

    const int tid = threadIdx.x;
    const int cc0 = blockIdx.x * 32;
    const long n0 = (long)blockIdx.y * 64;
    const int W2 = 2 * Ws, H2 = 2 * Hs;
    const int HW2 = H2 * W2;
    const int HWs = Hs * Ws;

    if (tid < 64) {
        long n = n0 + tid;
        int b = (int)(n / HW2);
        int p2 = (int)(n - (long)b * HW2);
        int oy = p2 / W2, ox = p2 % W2;
        float sy = fmaxf(oy * 0.5f - 0.25f, 0.f);
        float sx = fmaxf(ox * 0.5f - 0.25f, 0.f);
        int y0 = (int)floorf(sy); float ty = sy - (float)y0;
        int y1 = min(y0 + 1, Hs - 1);
        int x0 = (int)floorf(sx); float tx = sx - (float)x0;
        int x1 = min(x0 + 1, Ws - 1);
        sb[tid] = b;
        si0[tid] = y0 * Ws + x0; si1[tid] = y0 * Ws + x1;
        si2[tid] = y1 * Ws + x0; si3[tid] = y1 * Ws + x1;
        swy[tid] = ty; swx[tid] = tx;
    }
    __syncthreads();

#pragma unroll
    for (int e = tid; e < 2048; e += 256) {
        const int p = e & 63, cc = e >> 6;
        const int c = (cc0 + cc) * 2;
        const float ty = swy[p], tx = swx[p];
        const int i0 = si0[p], i1 = si1[p], i2 = si2[p], i3 = si3[p];
        const float* pc = src + ((long)sb[p] * C + c) * HWs;
        float a0 = pc[i0] * (1.f - ty) + pc[i2] * ty;
        float a1 = pc[i1] * (1.f - ty) + pc[i3] * ty;
        float v0 = a0 * (1.f - tx) + a1 * tx;
        const float* pd = pc + HWs;
        float b0 = pd[i0] * (1.f - ty) + pd[i2] * ty;
        float b1 = pd[i1] * (1.f - ty) + pd[i3] * ty;
        float v1 = b0 * (1.f - tx) + b1 * tx;
        sh[cc][p] = pack_h2(v0, v1);
    }
    __syncthreads();

#pragma unroll
    for (int e = tid; e < 2048; e += 256) {
        const int kk = e & 31, p = e >> 5;
        Xh[(n0 + p) * Cph + cc0 + kk] = sh[kk][p];
    }
}

// ---------------------------------------------------------------------------
// Fused weight convert (fp16 hi only)
// ---------------------------------------------------------------------------
struct WJob {
    const float* w;
    uint32_t* Ah;
    int M, Cin, Cp, Kp, total;
};
struct WJobs { WJob j[13]; };

__global__ void __launch_bounds__(256)
wconv_all(WJobs jobs)
{
    const WJob jb = jobs.j[blockIdx.y];
    int idx = blockIdx.x * 256 + threadIdx.x;
    if (idx >= jb.total) return;
    const int Kh = jb.Kp >> 1;
    const int kk = idx % Kh;
    const int m  = idx / Kh;
    const int k0 = kk * 2;
    const int t = k0 / jb.Cp, c = k0 - t * jb.Cp;
    float v0 = 0.f, v1 = 0.f;
    if (m < jb.M && t < 9) {
        if (c < jb.Cin)     v0 = jb.w[((long)m * jb.Cin + c) * 9 + t];
        if (c + 1 < jb.Cin) v1 = jb.w[((long)m * jb.Cin + c + 1) * 9 + t];
    }
    jb.Ah[idx] = pack_h2(v0, v1);
}

// ===========================================================================
// GEMM common geometry (2 planes/stage: Ah, Bh — 3-stage pipeline)
// ===========================================================================
#define LROW 40
#define PLANE_B (128 * LROW * 2)           // 10240 B
#define STG2_B (2 * PLANE_B)               // 20480 B
#define GEMM_SMEM 70656                    // >= max(3*STG2_B, 128*133*4 epi)

#define APL64_B (64 * LROW * 2)            // 5120 B
#define BPL64_B (256 * LROW * 2)           // 20480 B
#define STG64_B (APL64_B + BPL64_B)        // 25600 B
#define GEMM64_SMEM 76800                  // 3*STG64_B (>= 64*261*4 epi)

#define MMA_BODY1(stgA, stgB)                                                  \
    _Pragma("unroll")                                                          \
    for (int s = 0; s < 2; s++) {                                              \
        const uint32_t cofs = (uint32_t)(s * 32);                              \
        uint32_t afh[4][4], bfh[2][4];                                         \
        _Pragma("unroll")                                                      \
        for (int mt = 0; mt < 4; mt++)                                         \
            LDSM4(afh[mt], (stgA) + aoff[mt] + cofs);                          \
        _Pragma("unroll")                                                      \
        for (int np = 0; np < 2; np++)                                         \
            LDSM4(bfh[np], (stgB) + boff[np] + cofs);                          \
        _Pragma("unroll")                                                      \
        for (int mt = 0; mt < 4; mt++)                                         \
            _Pragma("unroll")                                                  \
            for (int nt = 0; nt < 4; nt++) {                                   \
                const uint32_t* bh = &bfh[nt >> 1][(nt & 1) * 2];              \
                mma16816(acc[mt][nt], afh[mt], bh[0], bh[1]);                  \
            }                                                                  \
    }

#define EPI_FP32_128()                                                         \
    {                                                                          \
        const int bIdx = p0 / HW, prow0 = p0 % HW;                             \
        _Pragma("unroll")                                                      \
        for (int mt = 0; mt < 4; mt++) {                                       \
            const int oca = m0 + wm * 64 + mt * 16 + g;                        \
            const int ocb = oca + 8;                                           \
            const float ba = (oca < Cout) ? bias[oca] : 0.f;                   \
            const float bb = (ocb < Cout) ? bias[ocb] : 0.f;                   \
            _Pragma("unroll")                                                  \
            for (int nt = 0; nt < 4; nt++) {                                   \
                const int pc = prow0 + wn * 32 + nt * 8 + 2 * t;               \
                if (oca < Cout) {                                              \
                    float2 v = make_float2(acc[mt][nt][0] + ba, acc[mt][nt][1] + ba); \
                    *(float2*)&out[((long)bIdx * ocStride + oca) * HW + pc] = v; \
                }                                                              \
                if (ocb < Cout) {                                              \
                    float2 v = make_float2(acc[mt][nt][2] + bb, acc[mt][nt][3] + bb); \
                    *(float2*)&out[((long)bIdx * ocStride + ocb) * HW + pc] = v; \
                }                                                              \
            }                                                                  \
        }                                                                      \
    }

#define EPI_XT_128()                                                           \
    {                                                                          \
        float* sf = (float*)sm;                                                \
        _Pragma("unroll")                                                      \
        for (int mt = 0; mt < 4; mt++) {                                       \
            const int ra = wm * 64 + mt * 16 + g;                              \
            const float ba = bias[m0 + ra];                                    \
            const float bb = bias[m0 + ra + 8];                                \
            _Pragma("unroll")                                                  \
            for (int nt = 0; nt < 4; nt++) {                                   \
                const int pc = wn * 32 + nt * 8 + 2 * t;                       \
                sf[ra * 133 + pc]           = acc[mt][nt][0] + ba;             \
                sf[ra * 133 + pc + 1]       = acc[mt][nt][1] + ba;             \
                sf[(ra + 8) * 133 + pc]     = acc[mt][nt][2] + bb;             \
                sf[(ra + 8) * 133 + pc + 1] = acc[mt][nt][3] + bb;             \
            }                                                                  \
        }                                                                      \
        __syncthreads();                                                       \
        const int cpBase = xtCpOff + (m0 >> 1);                                \
        for (int e = tid; e < 8192; e += 256) {                                \
            const int cp = e & 63, px = e >> 6;                                \
            xtH[(long)(p0 + px) * xtCph + cpBase + cp] =                       \
                pack_h2(sf[(2 * cp) * 133 + px], sf[(2 * cp + 1) * 133 + px]); \
        }                                                                      \
    }

#define EPI_FP32_64()                                                          \
    {                                                                          \
        const int bIdx = p0 / HW, prow0 = p0 % HW;                             \
        _Pragma("unroll")                                                      \
        for (int mt = 0; mt < 4; mt++) {                                       \
            const int oca = mt * 16 + g;                                       \
            const int ocb = oca + 8;                                           \
            const float ba = (oca < Cout) ? bias[oca] : 0.f;                   \
            const float bb = (ocb < Cout) ? bias[ocb] : 0.f;                   \
            _Pragma("unroll")                                                  \
            for (int nt = 0; nt < 4; nt++) {                                   \
                const int pc = prow0 + wn * 32 + nt * 8 + 2 * t;               \
                if (oca < Cout) {                                              \
                    float2 v = make_float2(acc[mt][nt][0] + ba, acc[mt][nt][1] + ba); \
                    *(float2*)&out[((long)bIdx * ocStride + oca) * HW + pc] = v; \
                }                                                              \
                if (ocb < Cout) {                                              \
                    float2 v = make_float2(acc[mt][nt][2] + bb, acc[mt][nt][3] + bb); \
                    *(float2*)&out[((long)bIdx * ocStride + ocb) * HW + pc] = v; \
                }                                                              \
            }                                                                  \
        }                                                                      \
    }

#define EPI_XT_64()                                                            \
    {                                                                          \
        float* sf = (float*)sm;                                                \
        _Pragma("unroll")                                                      \
        for (int mt = 0; mt < 4; mt++) {                                       \
            const int ra = mt * 16 + g;                                        \
            const float ba = bias[ra];                                         \
            const float bb = bias[ra + 8];                                     \
            _Pragma("unroll")                                                  \
            for (int nt = 0; nt < 4; nt++) {                                   \
                const int pc = wn * 32 + nt * 8 + 2 * t;                       \
                sf[ra * 261 + pc]           = acc[mt][nt][0] + ba;             \
                sf[ra * 261 + pc + 1]       = acc[mt][nt][1] + ba;             \
                sf[(ra + 8) * 261 + pc]     = acc[mt][nt][2] + bb;             \
                sf[(ra + 8) * 261 + pc + 1] = acc[mt][nt][3] + bb;             \
            }                                                                  \
        }                                                                      \
        __syncthreads();                                                       \
        for (int e = tid; e < 8192; e += 256) {                                \
            const int cp = e & 31, px = e >> 5;                                \
            xtH[(long)(p0 + px) * xtCph + xtCpOff + cp] =                      \
                pack_h2(sf[(2 * cp) * 261 + px], sf[(2 * cp + 1) * 261 + px]); \
        }                                                                      \
    }

// 3-stage loop skeleton
#define PIPE3_LOOP(STAGEFN, ADVANCE, MMAEXP)                                   \
    STAGEFN(0);                                                                \
    CP_COMMIT();                                                               \
    ADVANCE;                                                                   \
    if (nchunks > 1) { STAGEFN(1); }                                           \
    CP_COMMIT();                                                               \
    ADVANCE;                                                                   \
    for (int ci = 0; ci < nchunks; ci++) {                                     \
        CP_WAIT(1);                                                            \
        __syncthreads();                                                       \
        if (ci + 2 < nchunks) { STAGEFN((ci + 2) % 3); ADVANCE; }              \
        CP_COMMIT();                                                           \
        const uint32_t stg = smb + (uint32_t)(ci % 3) * stageBytes;            \
        MMAEXP                                                                 \
    }                                                                          \
    __syncthreads();

// ---------------------------------------------------------------------------
// gemm_tap: M128 x N128, implicit-tap B staging from compact Xt[n][Cp]
// ---------------------------------------------------------------------------
__global__ void __launch_bounds__(256, 2)
gemm_tap(const __half* __restrict__ Ahi,
         const uint32_t* __restrict__ Xh,
         const float* __restrict__ bias, float* __restrict__ out,
         int Kp, int Cp, int nchunks, int Cout, int ocStride, int H, int W,
         uint32_t* xtH, int xtCph, int xtCpOff)
{
    extern __shared__ __half sm[];
    const uint32_t stageBytes = STG2_B;

    const int tid = threadIdx.x, wid = tid >> 5, lane = tid & 31;
    const int g = lane >> 2, t = lane & 3;
    const int wm = wid >> 2, wn = wid & 3;
    const int HW = H * W;

    const int p0 = blockIdx.x * 128;
    const int m0 = blockIdx.y * 128;

    float acc[4][4][4];
#pragma unroll
    for (int i = 0; i < 4; i++)
#pragma unroll
        for (int j = 0; j < 4; j++)
#pragma unroll
            for (int k = 0; k < 4; k++) acc[i][j][k] = 0.f;

    const uint32_t smb = smem_u32(sm);
    const int r0 = tid >> 2, s0 = tid & 3;
    const int r1 = r0 + 64;

    int b0r, y0r, x0r, b1r, y1r, x1r;
    {
        int n = p0 + r0; b0r = n / HW; int p = n - b0r * HW; y0r = p / W; x0r = p - y0r * W;
        n = p0 + r1; b1r = n / HW; p = n - b1r * HW; y1r = p / W; x1r = p - y1r * W;
    }

    uint32_t aoff[4], boff[2];
    {
        const int arow = (lane & 7) + ((lane >> 3) & 1) * 8;
        const int acol = (lane >> 4) * 8;
#pragma unroll
        for (int mt = 0; mt < 4; mt++)
            aoff[mt] = (uint32_t)(((wm * 64 + mt * 16 + arow) * LROW + acol) * 2);
        const int brow = (lane & 7) + (lane >> 4) * 8;
        const int bcol = ((lane >> 3) & 1) * 8;
#pragma unroll
        for (int np = 0; np < 2; np++)
            boff[np] = (uint32_t)(((wn * 32 + np * 16 + brow) * LROW + bcol) * 2);
    }

    const char* XhB = (const char*)Xh;
    const long rowB = (long)Cp * 2;

    int tP = 0, kinP = 0;
    auto stage = [&](int buf) {
        const long kc = (long)tP * Cp + kinP;
        const uint32_t bufb = smb + (uint32_t)buf * STG2_B;
        CP16(bufb + r0 * 80 + s0 * 16, Ahi + (long)(m0 + r0) * Kp + kc + s0 * 8);
        CP16(bufb + r1 * 80 + s0 * 16, Ahi + (long)(m0 + r1) * Kp + kc + s0 * 8);
        const int q = tP / 3;
        const int dy = q - 1, dx = tP - 3 * q - 1;
        const long cb = (long)kinP * 2;
        {
            const int yy = y0r + dy, xx = x0r + dx;
            const uint32_t dH = bufb + PLANE_B + r0 * 80 + s0 * 16;
            if ((unsigned)yy < (unsigned)H && (unsigned)xx < (unsigned)W)
                CP16(dH, XhB + ((long)b0r * HW + yy * W + xx) * rowB + cb + s0 * 16);
            else ZSTS16(dH);
        }
        {
            const int yy = y1r + dy, xx = x1r + dx;
            const uint32_t dH = bufb + PLANE_B + r1 * 80 + s0 * 16;
            if ((unsigned)yy < (unsigned)H && (unsigned)xx < (unsigned)W)
                CP16(dH, XhB + ((long)b1r * HW + yy * W + xx) * rowB + cb + s0 * 16);
            else ZSTS16(dH);
        }
    };

#define ADV { kinP += 32; if (kinP == Cp) { kinP = 0; tP++; } }
    PIPE3_LOOP(stage, ADV, MMA_BODY1(stg, stg + PLANE_B))
#undef ADV

    if (xtH) EPI_XT_128()
    else     EPI_FP32_128()
}

// ---------------------------------------------------------------------------
// gemm_tap64: M64 x N256, implicit-tap B staging (Cout <= 64)
// ---------------------------------------------------------------------------
__global__ void __launch_bounds__(256, 2)
gemm_tap64(const __half* __restrict__ Ahi,
           const uint32_t* __restrict__ Xh,
           const float* __restrict__ bias, float* __restrict__ out,
           int Kp, int Cp, int nchunks, int Cout, int ocStride, int H, int W,
           uint32_t* xtH, int xtCph, int xtCpOff)
{
    extern __shared__ __half sm[];
    const uint32_t stageBytes = STG64_B;

    const int tid = threadIdx.x, wid = tid >> 5, lane = tid & 31;
    const int g = lane >> 2, t = lane & 3;
    const int wn = wid;
    const int HW = H * W;

    const int p0 = blockIdx.x * 256;

    float acc[4][4][4];
#pragma unroll
    for (int i = 0; i < 4; i++)
#pragma unroll
        for (int j = 0; j < 4; j++)
#pragma unroll
            for (int k = 0; k < 4; k++) acc[i][j][k] = 0.f;

    const uint32_t smb = smem_u32(sm);
    const int rA = tid >> 2, sA = tid & 3;

    int b4[4], y4[4], x4[4];
#pragma unroll
    for (int j = 0; j < 4; j++) {
        int n = p0 + rA + 64 * j;
        b4[j] = n / HW;
        int p = n - b4[j] * HW;
        y4[j] = p / W;
        x4[j] = p - y4[j] * W;
    }

    uint32_t aoff[4], boff[2];
    {
        const int arow = (lane & 7) + ((lane >> 3) & 1) * 8;
        const int acol = (lane >> 4) * 8;
#pragma unroll
        for (int mt = 0; mt < 4; mt++)
            aoff[mt] = (uint32_t)(((mt * 16 + arow) * LROW + acol) * 2);
        const int brow = (lane & 7) + (lane >> 4) * 8;
        const int bcol = ((lane >> 3) & 1) * 8;
#pragma unroll
        for (int np = 0; np < 2; np++)
            boff[np] = (uint32_t)(((wn * 32 + np * 16 + brow) * LROW + bcol) * 2);
    }

    const char* XhB = (const char*)Xh;
    const long rowB = (long)Cp * 2;

    int tP = 0, kinP = 0;
    auto stage = [&](int buf) {
        const long kc = (long)tP * Cp + kinP;
        const uint32_t bufb = smb + (uint32_t)buf * STG64_B;
        CP16(bufb + rA * 80 + sA * 16, Ahi + (long)rA * Kp + kc + sA * 8);
        const int q = tP / 3;
        const int dy = q - 1, dx = tP - 3 * q - 1;
        const long cb = (long)kinP * 2;
        const uint32_t bB = bufb + APL64_B;
#pragma unroll
        for (int j = 0; j < 4; j++) {
            const int r = rA + 64 * j;
            const int yy = y4[j] + dy, xx = x4[j] + dx;
            const uint32_t dH = bB + r * 80 + sA * 16;
            if ((unsigned)yy < (unsigned)H && (unsigned)xx < (unsigned)W)
                CP16(dH, XhB + ((long)b4[j] * HW + yy * W + xx) * rowB + cb + sA * 16);
            else ZSTS16(dH);
        }
    };

#define ADV { kinP += 32; if (kinP == Cp) { kinP = 0; tP++; } }
    PIPE3_LOOP(stage, ADV, MMA_BODY1(stg, stg + APL64_B))
#undef ADV

    if (xtH) EPI_XT_64()
    else     EPI_FP32_64()
}

// ---------------------------------------------------------------------------
// gemm_mma / gemm_mma64: direct-B (DCN GEMMs)
// ---------------------------------------------------------------------------
__global__ void __launch_bounds__(256, 2)
gemm_mma(const __half* __restrict__ Ahi,
         const __half* __restrict__ Bhi,
         const float* __restrict__ bias, float* __restrict__ out,
         int Kp, int nchunks, int Cout, int ocStride, int HW,
         uint32_t* xtH, int xtCph, int xtCpOff)
{
    extern __shared__ __half sm[];
    const uint32_t stageBytes = STG2_B;

    const int tid = threadIdx.x, wid = tid >> 5, lane = tid & 31;
    const int g = lane >> 2, t = lane & 3;
    const int wm = wid >> 2, wn = wid & 3;

    const int p0 = blockIdx.x * 128;
    const int m0 = blockIdx.y * 128;

    float acc[4][4][4];
#pragma unroll
    for (int i = 0; i < 4; i++)
#pragma unroll
        for (int j = 0; j < 4; j++)
#pragma unroll
            for (int k = 0; k < 4; k++) acc[i][j][k] = 0.f;

    const uint32_t smb = smem_u32(sm);
    const int r0 = tid >> 2, s0 = tid & 3;
    const int r1 = r0 + 64;

    uint32_t aoff[4], boff[2];
    {
        const int arow = (lane & 7) + ((lane >> 3) & 1) * 8;
        const int acol = (lane >> 4) * 8;
#pragma unroll
        for (int mt = 0; mt < 4; mt++)
            aoff[mt] = (uint32_t)(((wm * 64 + mt * 16 + arow) * LROW + acol) * 2);
        const int brow = (lane & 7) + (lane >> 4) * 8;
        const int bcol = ((lane >> 3) & 1) * 8;
#pragma unroll
        for (int np = 0; np < 2; np++)
            boff[np] = (uint32_t)(((wn * 32 + np * 16 + brow) * LROW + bcol) * 2);
    }

    int ciP = 0;
    auto stage = [&](int buf) {
        const long kc = (long)ciP * 32;
        const uint32_t bufb = smb + (uint32_t)buf * STG2_B;
        CP16(bufb + r0 * 80 + s0 * 16, Ahi + (long)(m0 + r0) * Kp + kc + s0 * 8);
        CP16(bufb + r1 * 80 + s0 * 16, Ahi + (long)(m0 + r1) * Kp + kc + s0 * 8);
        CP16(bufb + PLANE_B + r0 * 80 + s0 * 16, Bhi + (long)(p0 + r0) * Kp + kc + s0 * 8);
        CP16(bufb + PLANE_B + r1 * 80 + s0 * 16, Bhi + (long)(p0 + r1) * Kp + kc + s0 * 8);
    };

#define ADV { ciP++; }
    PIPE3_LOOP(stage, ADV, MMA_BODY1(stg, stg + PLANE_B))
#undef ADV

    if (xtH) EPI_XT_128()
    else     EPI_FP32_128()
}

__global__ void __launch_bounds__(256, 2)
gemm_mma64(const __half* __restrict__ Ahi,
           const __half* __restrict__ Bhi,
           const float* __restrict__ bias, float* __restrict__ out,
           int Kp, int nchunks, int Cout, int ocStride, int HW,
           uint32_t* xtH, int xtCph, int xtCpOff)
{
    extern __shared__ __half sm[];
    const uint32_t stageBytes = STG64_B;

    const int tid = threadIdx.x, wid = tid >> 5, lane = tid & 31;
    const int g = lane >> 2, t = lane & 3;
    const int wn = wid;

    const int p0 = blockIdx.x * 256;

    float acc[4][4][4];
#pragma unroll
    for (int i = 0; i < 4; i++)
#pragma unroll
        for (int j = 0; j < 4; j++)
#pragma unroll
            for (int k = 0; k < 4; k++) acc[i][j][k] = 0.f;

    const uint32_t smb = smem_u32(sm);
    const int rA = tid >> 2, sA = tid & 3;

    uint32_t aoff[4], boff[2];
    {
        const int arow = (lane & 7) + ((lane >> 3) & 1) * 8;
        const int acol = (lane >> 4) * 8;
#pragma unroll
        for (int mt = 0; mt < 4; mt++)
            aoff[mt] = (uint32_t)(((mt * 16 + arow) * LROW + acol) * 2);
        const int brow = (lane & 7) + (lane >> 4) * 8;
        const int bcol = ((lane >> 3) & 1) * 8;
#pragma unroll
        for (int np = 0; np < 2; np++)
            boff[np] = (uint32_t)(((wn * 32 + np * 16 + brow) * LROW + bcol) * 2);
    }

    int ciP = 0;
    auto stage = [&](int buf) {
        const long kc = (long)ciP * 32;
        const uint32_t bufb = smb + (uint32_t)buf * STG64_B;
        CP16(bufb + rA * 80 + sA * 16, Ahi + (long)rA * Kp + kc + sA * 8);
        const uint32_t bB = bufb + APL64_B;
#pragma unroll
        for (int j = 0; j < 4; j++) {
            const int task = tid + 256 * j;
            const int r = task >> 2, s = task & 3;
            CP16(bB + r * 80 + s * 16, Bhi + (long)(p0 + r) * Kp + kc + s * 8);
        }
    };

#define ADV { ciP++; }
    PIPE3_LOOP(stage, ADV, MMA_BODY1(stg, stg + APL64_B))
#undef ADV

    if (xtH) EPI_XT_64()
    else     EPI_FP32_64()
}

// ---------------------------------------------------------------------------
// DCN bilinear sampler (fp16)
// ---------------------------------------------------------------------------
__global__ void dcn_sample_bf(const float* __restrict__ x, long xbs,
                              const float* __restrict__ om,
                              uint4* __restrict__ Bh4,
                              int C, int H, int W, int total)
{
    int idx = blockIdx.x * blockDim.x + threadIdx.x;
    if (idx >= total) return;
    const int HW = H * W;
    const int p = idx % HW;
    const int k = (idx / HW) % 9;
    const int g = (idx / (HW * 9)) % 8;
    const int b = idx / (HW * 72);
    const int y = p / W, xq = p % W;

    const long omb = (long)b * 216 * HW + (long)(g * 9 + k) * HW + p;
    float dy = om[omb];
    float dx = om[omb + 72L * HW];
    float mk = om[omb + 144L * HW];
    mk = 1.f / (1.f + expf(-mk));

    float pyf = (float)y + (float)(k / 3 - 1) + dy;
    float pxf = (float)xq + (float)(k % 3 - 1) + dx;
    float y0f = floorf(pyf), x0f = floorf(pxf);
    int y0 = (int)y0f, x0i = (int)x0f;
    float ty = pyf - y0f, tx = pxf - x0f;
    int y1 = y0 + 1, x1i = x0i + 1;

    bool vy0 = (y0 >= 0) && (y0 < H), vy1 = (y1 >= 0) && (y1 < H);
    bool vx0 = (x0i >= 0) && (x0i < W), vx1 = (x1i >= 0) && (x1i < W);
    float w00 = (vy0 && vx0) ? (1.f - ty) * (1.f - tx) : 0.f;
    float w01 = (vy0 && vx1) ? (1.f - ty) * tx : 0.f;
    float w10 = (vy1 && vx0) ? ty * (1.f - tx) : 0.f;
    float w11 = (vy1 && vx1) ? ty * tx : 0.f;
    w00 *= mk; w01 *= mk; w10 *= mk; w11 *= mk;

    int cy0 = min(max(y0, 0), H - 1), cy1 = min(max(y1, 0), H - 1);
    int cx0 = min(max(x0i, 0), W - 1), cx1 = min(max(x1i, 0), W - 1);
    int i00 = cy0 * W + cx0, i01 = cy0 * W + cx1;
    int i10 = cy1 * W + cx0, i11 = cy1 * W + cx1;

    const int Cg = C >> 3;
    const int K = C * 9;
    const float* xb = x + (long)b * xbs + (long)g * Cg * HW;
    const long rowbase = ((long)b * HW + p) * K + (long)k * C + (long)g * Cg;
    const long o4 = rowbase >> 3;

    for (int cb = 0; cb < Cg; cb += 8) {
        uint32_t hv[4];
#pragma unroll
        for (int j = 0; j < 4; j++) {
            const float* xc0 = xb + (long)(cb + 2 * j) * HW;
            const float* xc1 = xc0 + HW;
            float v0 = w00 * xc0[i00] + w01 * xc0[i01] + w10 * xc0[i10] + w11 * xc0[i11];
            float v1 = w00 * xc1[i00] + w01 * xc1[i01] + w10 * xc1[i10] + w11 * xc1[i11];
            hv[j] = pack_h2(v0, v1);
        }
        Bh4[o4 + (cb >> 3)] = make_uint4(hv[0], hv[1], hv[2], hv[3]);
    }
}

// ---------------------------------------------------------------------------
extern "C" void kernel_launch(void* const* d_in, const int* in_sizes, int n_in,
                              void* d_out, int out_size)
{
    const float *x0 = nullptr, *x1 = nullptr, *x2 = nullptr;
    const float *flow0 = nullptr, *flow1 = nullptr, *flow2 = nullptr;
    for (int i = 0; i < 6; i++) {
        const float* p = (const float*)d_in[i];
        switch (in_sizes[i]) {
            case 4 * 2 * 64 * 128 * 128: x0 = p; break;
            case 4 * 2 * 128 * 64 * 64:  x1 = p; break;
            case 4 * 2 * 256 * 32 * 32:  x2 = p; break;
            case 4 * 2 * 128 * 128:      flow0 = p; break;
            case 4 * 2 * 64 * 64:        flow1 = p; break;
            case 4 * 2 * 32 * 32:        flow2 = p; break;
        }
    }
    const float* off_w0 = (const float*)d_in[6];  const float* off_b0 = (const float*)d_in[7];
    const float* co_w0  = (const float*)d_in[8];  const float* co_b0  = (const float*)d_in[9];
    const float* dcn_w0 = (const float*)d_in[10]; const float* dcn_b0 = (const float*)d_in[11];
    const float* off_w1 = (const float*)d_in[12]; const float* off_b1 = (const float*)d_in[13];
    const float* co_w1  = (const float*)d_in[14]; const float* co_b1  = (const float*)d_in[15];
    const float* dcn_w1 = (const float*)d_in[16]; const float* dcn_b1 = (const float*)d_in[17];
    const float* off_w2 = (const float*)d_in[18]; const float* off_b2 = (const float*)d_in[19];
    const float* co_w2  = (const float*)d_in[20]; const float* co_b2  = (const float*)d_in[21];
    const float* dcn_w2 = (const float*)d_in[22]; const float* dcn_b2 = (const float*)d_in[23];
    const float* ch_w0  = (const float*)d_in[24]; const float* ch_b0  = (const float*)d_in[25];
    const float* ft_w0  = (const float*)d_in[26]; const float* ft_b0  = (const float*)d_in[27];
    const float* ch_w1  = (const float*)d_in[28]; const float* ch_b1  = (const float*)d_in[29];
    const float* ft_w1  = (const float*)d_in[30]; const float* ft_b1  = (const float*)d_in[31];

    uint32_t* XH;
    __half* Ah;
    float *om0, *om1, *om2;
    cudaGetSymbolAddress((void**)&XH, g_XH);
    cudaGetSymbolAddress((void**)&Ah, g_Ah);
    cudaGetSymbolAddress((void**)&om0, g_om0);
    cudaGetSymbolAddress((void**)&om1, g_om1);
    cudaGetSymbolAddress((void**)&om2, g_om2);

    cudaFuncSetAttribute(gemm_tap,   cudaFuncAttributeMaxDynamicSharedMemorySize, GEMM_SMEM);
    cudaFuncSetAttribute(gemm_tap64, cudaFuncAttributeMaxDynamicSharedMemorySize, GEMM64_SMEM);
    cudaFuncSetAttribute(gemm_mma,   cudaFuncAttributeMaxDynamicSharedMemorySize, GEMM_SMEM);
    cudaFuncSetAttribute(gemm_mma64, cudaFuncAttributeMaxDynamicSharedMemorySize, GEMM64_SMEM);

    float* out0 = (float*)d_out;
    float* out1 = out0 + 4L * 64 * 128 * 128;
    float* out2 = out1 + 4L * 128 * 64 * 64;

    const int B = 4;
    cudaStream_t S0 = 0, S1 = g_s.s1, S2 = g_s.s2;

    auto XPOSE = [&](cudaStream_t st, long off, const float* s1, int c1, long bs1,
                     const float* s2, int c2, long bs2, int H, int W, int Cph) {
        dim3 grid((Cph + 31) / 32, (B * H * W) / 64);
        xpose<<<grid, 256, 0, st>>>(s1, c1, bs1, s2, c2, bs2, H, W, Cph, XH + off);
    };
    auto UP2XT = [&](cudaStream_t st, long off, const float* src, int C,
                     int Hs, int Ws) {
        int Cph = C / 2;
        dim3 grid(Cph / 32, (B * 4 * Hs * Ws) / 64);
        up2_xt<<<grid, 256, 0, st>>>(src, C, Hs, Ws, Cph, XH + off);
    };
    auto GTAP = [&](cudaStream_t st, int slot, long off, const float* bias, float* out,
                    int Kp, int Cp, int Cout, int ocStride, int H, int W, int Mtiles,
                    long xtOff = -1, int xtCph = 0, int xtCpOff = 0) {
        dim3 grid((B * H * W) / 128, Mtiles);
        gemm_tap<<<grid, 256, GEMM_SMEM, st>>>(
            Ah + (long)slot * ASLOT, XH + off,
            bias, out, Kp, Cp, Kp / 32, Cout, ocStride, H, W,
            xtOff >= 0 ? XH + xtOff : nullptr, xtCph, xtCpOff);
    };
    auto GTAP64 = [&](cudaStream_t st, int slot, long off, const float* bias, float* out,
                      int Kp, int Cp, int Cout, int ocStride, int H, int W,
                      long xtOff = -1, int xtCph = 0, int xtCpOff = 0) {
        dim3 grid((B * H * W) / 256);
        gemm_tap64<<<grid, 256, GEMM64_SMEM, st>>>(
            Ah + (long)slot * ASLOT, XH + off,
            bias, out, Kp, Cp, Kp / 32, Cout, ocStride, H, W,
            xtOff >= 0 ? XH + xtOff : nullptr, xtCph, xtCpOff);
    };
    auto GOLD = [&](cudaStream_t st, int slot, long off, const float* bias, float* out,
                    int Kp, int Cout, int ocStride, int HW, int Mtiles,
                    long xtOff = -1, int xtCph = 0, int xtCpOff = 0) {
        dim3 grid((B * HW) / 128, Mtiles);
        gemm_mma<<<grid, 256, GEMM_SMEM, st>>>(
            Ah + (long)slot * ASLOT, (const __half*)(XH + off),
            bias, out, Kp, Kp / 32, Cout, ocStride, HW,
            xtOff >= 0 ? XH + xtOff : nullptr, xtCph, xtCpOff);
    };
    auto GOLD64 = [&](cudaStream_t st, int slot, long off, const float* bias, float* out,
                      int Kp, int Cout, int ocStride, int HW,
                      long xtOff = -1, int xtCph = 0, int xtCpOff = 0) {
        dim3 grid((B * HW) / 256);
        gemm_mma64<<<grid, 256, GEMM64_SMEM, st>>>(
            Ah + (long)slot * ASLOT, (const __half*)(XH + off),
            bias, out, Kp, Kp / 32, Cout, ocStride, HW,
            xtOff >= 0 ? XH + xtOff : nullptr, xtCph, xtCpOff);
    };
    auto DCN = [&](cudaStream_t st, long off, const float* x, long xbs, const float* om,
                   int C, int H, int W) {
        int total = B * 72 * H * W;
        dcn_sample_bf<<<(total + 255) / 256, 256, 0, st>>>(
            x, xbs, om, (uint4*)(XH + off), C, H, W, total);
    };

    // ---- all weight conversions in ONE launch ----
    {
        WJobs jobs;
        auto J = [&](int i, const float* w, int M, int Cin, int Cp, int Kp, int Mp) {
            jobs.j[i] = WJob{w, (uint32_t*)(Ah + (long)i * ASLOT),
                             M, Cin, Cp, Kp, Mp * (Kp >> 1)};
        };
        J(0,  off_w2, 256, 514, 544, 4896, 256);
        J(1,  co_w2,  216, 256, 256, 2304, 256);
        J(2,  dcn_w2, 256, 256, 256, 2304, 256);
        J(3,  off_w1, 128, 258, 288, 2592, 128);
        J(4,  co_w1,  216, 128, 128, 1152, 256);
        J(5,  dcn_w1, 128, 128, 128, 1152, 128);
        J(6,  off_w0, 64,  130, 160, 1440, 64);
        J(7,  co_w0,  216, 64,  64,  576,  256);
        J(8,  dcn_w0, 64,  64,  64,  576,  64);
        J(9,  ch_w1,  128, 256, 256, 2304, 128);
        J(10, ft_w1,  128, 256, 256, 2304, 128);
        J(11, ch_w0,  64,  128, 128, 1152, 64);
        J(12, ft_w0,  64,  128, 128, 1152, 64);
        int maxBlocks = (256 * (4896 >> 1) + 255) / 256;
        wconv_all<<<dim3(maxBlocks, 13), 256, 0, S0>>>(jobs);
    }

    // ---- fork ----
    cudaEventRecord(g_s.eF, S0);
    cudaStreamWaitEvent(S1, g_s.eF, 0);
    cudaStreamWaitEvent(S2, g_s.eF, 0);

    // ---- s1: level 0 off/co/dcn chain (128x128) ----
    {
        const int H = 128, W = 128, HW = H * W;
        XPOSE(S1, O_XT0A, x0, 128, 128L * HW, flow0, 2, 2L * HW, H, W, 80);
        GTAP64(S1, 6, O_XT0A, off_b0, nullptr, 1440, 160, 64, 64, H, W,
               O_XT0B, 32, 0);
        GTAP(S1, 7, O_XT0B, co_b0, om0, 576, 64, 216, 216, H, W, 2);
        DCN(S1, O_SAMP0, x0 + 64L * HW, 128L * HW, om0, 64, H, W);
        GOLD64(S1, 8, O_SAMP0, dcn_b0, nullptr, 576, 64, 128, HW,
               O_XTF0, 64, 0);
        cudaEventRecord(g_s.eL0, S1);
    }

    // ---- s2: level 1 off/co/dcn chain (64x64) ----
    {
        const int H = 64, W = 64, HW = H * W;
        XPOSE(S2, O_XT1A, x1, 256, 256L * HW, flow1, 2, 2L * HW, H, W, 144);
        GTAP(S2, 3, O_XT1A, off_b1, nullptr, 2592, 288, 128, 128, H, W, 1,
             O_XT1B, 64, 0);
        GTAP(S2, 4, O_XT1B, co_b1, om1, 1152, 128, 216, 216, H, W, 2);
        DCN(S2, O_SAMP1, x1 + 128L * HW, 256L * HW, om1, 128, H, W);
        GOLD(S2, 5, O_SAMP1, dcn_b1, nullptr, 1152, 128, 256, HW, 1,
             O_XTF1, 128, 0);
        cudaEventRecord(g_s.eL1, S2);
    }

    // ---- origin: level 2 chain (32x32) + fusion cascade ----
    {
        const int H = 32, W = 32, HW = H * W;
        XPOSE(S0, O_XT2A, x2, 512, 512L * HW, flow2, 2, 2L * HW, H, W, 272);
        GTAP(S0, 0, O_XT2A, off_b2, nullptr, 4896, 544, 256, 256, H, W, 2,
             O_XT2B, 128, 0);
        GTAP(S0, 1, O_XT2B, co_b2, om2, 2304, 256, 216, 216, H, W, 2);
        DCN(S0, O_SAMP2, x2 + 256L * HW, 512L * HW, om2, 256, H, W);
        GOLD(S0, 2, O_SAMP2, dcn_b2, out2, 2304, 256, 256, HW, 2);
        UP2XT(S0, O_XTU1, out2, 256, H, W);
    }
    {   // level 1 fusion (64x64)
        const int H = 64, W = 64, HW = H * W;
        GTAP(S0, 9, O_XTU1, ch_b1, nullptr, 2304, 256, 128, 256, H, W, 1,
             O_XTF1, 128, 64);
        cudaStreamWaitEvent(S0, g_s.eL1, 0);
        GTAP(S0, 10, O_XTF1, ft_b1, out1, 2304, 256, 128, 128, H, W, 1);
        UP2XT(S0, O_XTU0, out1, 128, H, W);
    }
    {   // level 0 fusion (128x128)
        const int H = 128, W = 128, HW = H * W;
        GTAP64(S0, 11, O_XTU0, ch_b0, nullptr, 1152, 128, 64, 128, H, W,
               O_XTF0, 64, 32);
        cudaStreamWaitEvent(S0, g_s.eL0, 0);
        GTAP64(S0, 12, O_XTF0, ft_b0, out0, 1152, 128, 64, 64, H, W);
    }
}